// round 4
// baseline (speedup 1.0000x reference)
#include <cuda_runtime.h>
#include <cuda_fp16.h>
#include <mma.h>
#include <math.h>

using namespace nvcuda;

// ---------------- problem constants ----------------
#define NEXP 8
#define NB   1024
#define NA   32
#define DTOK 128
#define FF   1024
#define HH   512
#define NRW  4

// ---------------- scratch (__device__ globals; no allocs) ----------------
// pre-split (hi/lo) transposed weights, half precision
__device__ __half g_win_h [NEXP*DTOK*384];   // [e][k][c]
__device__ __half g_win_l [NEXP*DTOK*384];
__device__ __half g_wout_h[NEXP*DTOK*DTOK];
__device__ __half g_wout_l[NEXP*DTOK*DTOK];
__device__ __half g_w1_h  [NEXP*DTOK*FF];
__device__ __half g_w1_l  [NEXP*DTOK*FF];
__device__ __half g_w2_h  [NEXP*FF*DTOK];
__device__ __half g_w2_l  [NEXP*FF*DTOK];
__device__ __half g_h1_h  [4096*HH];
__device__ __half g_h1_l  [4096*HH];

__device__ float g_ys   [2u*NB*4096];
__device__ float4 g_assign[NB];
__device__ float g_lse  [NB];
__device__ float g_hid  [NB*HH];

// smem layout of expert kernel (float indices)
#define QKV_LD   388
#define XS_OFF   0
#define QKV_OFF  4096                       // 32 x 388
#define SC_OFF   (4096 + 32*QKV_LD)        // 16512 : scores 128x33 / bias C / act
#define AHL_OFF  (SC_OFF + 4224)           // 20736 : A-half hi(4096h) + lo(4096h) = 4096 floats
#define SM_FLOATS (AHL_OFF + 4096)         // 24832 floats = 99328 B  (2 blocks/SM)
#define SMEM_BYTES (SM_FLOATS*4)

// ---------------- wmma fp16 types ----------------
typedef wmma::fragment<wmma::matrix_a, 16,16,16, __half, wmma::row_major> HA;
typedef wmma::fragment<wmma::matrix_b, 16,16,16, __half, wmma::row_major> HB;
typedef wmma::fragment<wmma::accumulator, 16,16,16, float> HC;

__device__ __forceinline__ void split_h(float v, __half& h, __half& l) {
    h = __float2half_rn(v);
    l = __float2half_rn(v - __half2float(h));
}

// convert 32x128 fp32 (row stride ld) -> half hi/lo (dense ld 128)
__device__ __forceinline__ void conv_ahl(const float* src, int ld, __half* ah, __half* al) {
    for (int i = threadIdx.x; i < 4096; i += 256) {
        float v = src[(i >> 7)*ld + (i & 127)];
        __half h, l; split_h(v, h, l);
        ah[i] = h; al[i] = l;
    }
}

// C(smem fp32, preloaded with bias) += Ah@Bh + Al@Bh + Ah@Bl   (M=32,N=128,K=128)
// 8 warps: warp w -> m0=(w>>2)*16, n0=(w&3)*32
template<bool RELU>
__device__ __forceinline__ void wgemm_h(const __half* Ah, const __half* Al,
                                        const __half* __restrict__ Bh,
                                        const __half* __restrict__ Bl, int ldB,
                                        float* Cs, int ldC) {
    int w = threadIdx.x >> 5;
    int m0 = (w >> 2) << 4;
    int n0 = (w & 3) << 5;
    HC c0, c1;
    wmma::load_matrix_sync(c0, Cs + m0*ldC + n0,      ldC, wmma::mem_row_major);
    wmma::load_matrix_sync(c1, Cs + m0*ldC + n0 + 16, ldC, wmma::mem_row_major);
    #pragma unroll 2
    for (int k = 0; k < 128; k += 16) {
        HA ah, al;
        wmma::load_matrix_sync(ah, Ah + m0*128 + k, 128);
        wmma::load_matrix_sync(al, Al + m0*128 + k, 128);
        HB bh0, bh1, bl0, bl1;
        wmma::load_matrix_sync(bh0, Bh + (size_t)k*ldB + n0,      ldB);
        wmma::load_matrix_sync(bh1, Bh + (size_t)k*ldB + n0 + 16, ldB);
        wmma::load_matrix_sync(bl0, Bl + (size_t)k*ldB + n0,      ldB);
        wmma::load_matrix_sync(bl1, Bl + (size_t)k*ldB + n0 + 16, ldB);
        wmma::mma_sync(c0, ah, bh0, c0);
        wmma::mma_sync(c1, ah, bh1, c1);
        wmma::mma_sync(c0, al, bh0, c0);
        wmma::mma_sync(c1, al, bh1, c1);
        wmma::mma_sync(c0, ah, bl0, c0);
        wmma::mma_sync(c1, ah, bl1, c1);
    }
    if (RELU) {
        #pragma unroll
        for (int i = 0; i < c0.num_elements; i++) {
            c0.x[i] = fmaxf(c0.x[i], 0.f);
            c1.x[i] = fmaxf(c1.x[i], 0.f);
        }
    }
    wmma::store_matrix_sync(Cs + m0*ldC + n0,      c0, ldC, wmma::mem_row_major);
    wmma::store_matrix_sync(Cs + m0*ldC + n0 + 16, c1, ldC, wmma::mem_row_major);
}

// accumulate variant: C frags stay in registers (FFN second GEMM)
__device__ __forceinline__ void wgemm_acc(const __half* Ah, const __half* Al,
                                          const __half* __restrict__ Bh,
                                          const __half* __restrict__ Bl, int ldB,
                                          HC& c0, HC& c1, int m0, int n0) {
    #pragma unroll 2
    for (int k = 0; k < 128; k += 16) {
        HA ah, al;
        wmma::load_matrix_sync(ah, Ah + m0*128 + k, 128);
        wmma::load_matrix_sync(al, Al + m0*128 + k, 128);
        HB bh0, bh1, bl0, bl1;
        wmma::load_matrix_sync(bh0, Bh + (size_t)k*ldB + n0,      ldB);
        wmma::load_matrix_sync(bh1, Bh + (size_t)k*ldB + n0 + 16, ldB);
        wmma::load_matrix_sync(bl0, Bl + (size_t)k*ldB + n0,      ldB);
        wmma::load_matrix_sync(bl1, Bl + (size_t)k*ldB + n0 + 16, ldB);
        wmma::mma_sync(c0, ah, bh0, c0);
        wmma::mma_sync(c1, ah, bh1, c1);
        wmma::mma_sync(c0, al, bh0, c0);
        wmma::mma_sync(c1, al, bh1, c1);
        wmma::mma_sync(c0, ah, bl0, c0);
        wmma::mma_sync(c1, ah, bl1, c1);
    }
}

// ---------------- weight repack: transpose + half hi/lo split ----------------
__global__ void repack_kernel(const float* __restrict__ w_in,
                              const float* __restrict__ w_out,
                              const float* __restrict__ w1,
                              const float* __restrict__ w2,
                              const float* __restrict__ hw1) {
    const int N_in  = NEXP*384*DTOK;
    const int N_out = NEXP*DTOK*DTOK;
    const int N_w1  = NEXP*FF*DTOK;
    const int N_w2  = NEXP*DTOK*FF;
    const int N_h1  = HH*4096;
    const int total = N_in + N_out + N_w1 + N_w2 + N_h1;
    for (int i = blockIdx.x*blockDim.x + threadIdx.x; i < total; i += gridDim.x*blockDim.x) {
        float v; int dst;
        __half h, l;
        if (i < N_in) {
            int e = i / (384*DTOK); int r = i % (384*DTOK);
            int c = r / DTOK, k = r % DTOK;
            v = w_in[i]; split_h(v, h, l);
            dst = e*(384*DTOK) + k*384 + c;
            g_win_h[dst] = h; g_win_l[dst] = l;
        } else if (i < N_in + N_out) {
            int j = i - N_in;
            int e = j / (DTOK*DTOK); int r = j % (DTOK*DTOK);
            int c = r / DTOK, k = r % DTOK;
            v = w_out[j]; split_h(v, h, l);
            dst = e*(DTOK*DTOK) + k*DTOK + c;
            g_wout_h[dst] = h; g_wout_l[dst] = l;
        } else if (i < N_in + N_out + N_w1) {
            int j = i - N_in - N_out;
            int e = j / (FF*DTOK); int r = j % (FF*DTOK);
            int f = r / DTOK, k = r % DTOK;
            v = w1[j]; split_h(v, h, l);
            dst = e*(FF*DTOK) + k*FF + f;
            g_w1_h[dst] = h; g_w1_l[dst] = l;
        } else if (i < N_in + N_out + N_w1 + N_w2) {
            int j = i - N_in - N_out - N_w1;
            int e = j / (DTOK*FF); int r = j % (DTOK*FF);
            int d = r / FF, k = r % FF;
            v = w2[j]; split_h(v, h, l);
            dst = e*(DTOK*FF) + k*DTOK + d;
            g_w2_h[dst] = h; g_w2_l[dst] = l;
        } else {
            int j = i - N_in - N_out - N_w1 - N_w2;
            int c = j / 4096, k = j % 4096;
            v = hw1[j]; split_h(v, h, l);
            dst = k*HH + c;
            g_h1_h[dst] = h; g_h1_l[dst] = l;
        }
    }
}

// ---------------- gating ----------------
__global__ void gating_kernel(const float* __restrict__ z, const float* __restrict__ a,
                              const float* __restrict__ wg, float* __restrict__ gates_out) {
    int b = blockIdx.x;
    int tid = threadIdx.x, w = tid >> 5, lane = tid & 31;
    __shared__ float lg[NEXP];
    float s = 0.f;
    for (int i = lane; i < 4096; i += 32) {
        int n = i >> 7, d = i & 127;
        float xv = (d < 96) ? z[(b*NA + n)*96 + d] : a[(b*NA + n)*32 + d - 96];
        s += xv * wg[i*NEXP + w];
    }
    #pragma unroll
    for (int o = 16; o; o >>= 1) s += __shfl_xor_sync(0xffffffffu, s, o);
    if (lane == 0) lg[w] = s;
    __syncthreads();
    if (tid == 0) {
        int i0 = 0; float v0 = lg[0];
        for (int e = 1; e < NEXP; e++) if (lg[e] > v0) { v0 = lg[e]; i0 = e; }
        int i1 = -1; float v1 = -1e30f;
        for (int e = 0; e < NEXP; e++) if (e != i0 && lg[e] > v1) { v1 = lg[e]; i1 = e; }
        float g0 = 1.f/(1.f + __expf(v1 - v0));
        float g1 = 1.f - g0;
        for (int e = 0; e < NEXP; e++)
            gates_out[b*NEXP + e] = (e == i0) ? g0 : ((e == i1) ? g1 : 0.f);
        g_assign[b] = make_float4((float)i0, g0, (float)i1, g1);
        float se = 0.f;
        for (int e = 0; e < NEXP; e++) se += __expf(lg[e] - v0);
        g_lse[b] = v0 + logf(se);
    }
}

// ---------------- balance loss ----------------
__device__ __forceinline__ float cv2_of8(const float* v) {
    float m = 0.f;
    for (int i = 0; i < 8; i++) m += v[i];
    m *= 0.125f;
    float q = 0.f;
    for (int i = 0; i < 8; i++) { float d = v[i]-m; q += d*d; }
    float var = q / 7.f;
    return var / (m*m + 1e-10f);
}

__global__ void loss_kernel(const float* __restrict__ gates, float* __restrict__ out) {
    __shared__ float imp[NEXP], ldv[NEXP], red[256];
    int tid = threadIdx.x, w = tid >> 5, lane = tid & 31;
    float s = 0.f, c = 0.f;
    for (int b = lane; b < NB; b += 32) {
        float gv = gates[b*NEXP + w];
        s += gv; if (gv > 0.f) c += 1.f;
    }
    #pragma unroll
    for (int o = 16; o; o >>= 1) {
        s += __shfl_xor_sync(0xffffffffu, s, o);
        c += __shfl_xor_sync(0xffffffffu, c, o);
    }
    if (lane == 0) { imp[w] = s; ldv[w] = c; }
    float ls = 0.f;
    for (int b = tid; b < NB; b += 256) ls += g_lse[b];
    red[tid] = ls; __syncthreads();
    for (int o = 128; o; o >>= 1) { if (tid < o) red[tid] += red[tid+o]; __syncthreads(); }
    if (tid == 0)
        out[12288] = cv2_of8(imp) + cv2_of8(ldv) + red[0]*(1.f/1024.f);
}

// ---------------- LayerNorm (warp per 4 rows) ----------------
__device__ __forceinline__ void ln_rows(const float* xs, const float* add,
                                        const float* __restrict__ g, const float* __restrict__ bt,
                                        float* dst, float scale) {
    int tid = threadIdx.x, w = tid >> 5, lane = tid & 31;
    float4 gv = *(const float4*)(g + lane*4);
    float4 bv = *(const float4*)(bt + lane*4);
    #pragma unroll
    for (int r = 0; r < 4; r++) {
        int row = w*4 + r;
        float4 xv = *(const float4*)(xs + row*128 + lane*4);
        float4 ov = *(const float4*)(add + row*128 + lane*4);
        float vx = xv.x+ov.x, vy = xv.y+ov.y, vz = xv.z+ov.z, vw = xv.w+ov.w;
        float s = vx+vy+vz+vw;
        #pragma unroll
        for (int o = 16; o; o >>= 1) s += __shfl_xor_sync(0xffffffffu, s, o);
        float mu = s*(1.f/128.f);
        float dx = vx-mu, dy = vy-mu, dz = vz-mu, dw = vw-mu;
        float q = dx*dx+dy*dy+dz*dz+dw*dw;
        #pragma unroll
        for (int o = 16; o; o >>= 1) q += __shfl_xor_sync(0xffffffffu, q, o);
        float rs = rsqrtf(q*(1.f/128.f) + 1e-5f);
        float4 res;
        res.x = (dx*rs*gv.x + bv.x)*scale;
        res.y = (dy*rs*gv.y + bv.y)*scale;
        res.z = (dz*rs*gv.z + bv.z)*scale;
        res.w = (dw*rs*gv.w + bv.w)*scale;
        *(float4*)(dst + row*128 + lane*4) = res;
    }
}

// ---------------- expert kernel: one block per (batch, slot) ----------------
__global__ void __launch_bounds__(256, 2)
expert_kernel(const float* __restrict__ z, const float* __restrict__ a,
              const float* __restrict__ b_in, const float* __restrict__ b_out,
              const float* __restrict__ ln1g, const float* __restrict__ ln1b,
              const float* __restrict__ b1, const float* __restrict__ b2,
              const float* __restrict__ ln2g, const float* __restrict__ ln2b) {
    extern __shared__ float sm[];
    float* xs  = sm + XS_OFF;     // 32x128 (x, later h)
    float* qkv = sm + QKV_OFF;    // 32x388 (q slot reused for attn-out)
    float* sc  = sm + SC_OFF;     // scores 128x33 / C-bias tile / act fp32
    __half* ah = (__half*)(sm + AHL_OFF);   // 32x128 A-hi
    __half* al = ah + 4096;                 // 32x128 A-lo
    int tid = threadIdx.x;
    int bs = blockIdx.x, b = bs >> 1, slot = bs & 1;
    float4 as = g_assign[b];
    int e; float gate;
    if (slot == 0) { e = (int)as.x; gate = as.y; } else { e = (int)as.z; gate = as.w; }

    // load x = concat(z, a)
    for (int i = tid; i < 4096; i += 256) {
        int n = i >> 7, d = i & 127;
        xs[i] = (d < 96) ? z[(b*NA + n)*96 + d] : a[(b*NA + n)*32 + d - 96];
    }
    // preload qkv with bias rows
    for (int i = tid; i < 32*384; i += 256) {
        int r = i / 384, c = i % 384;
        qkv[r*QKV_LD + c] = b_in[e*384 + c];
    }
    __syncthreads();
    // split x -> ah/al
    conv_ahl(xs, 128, ah, al);
    __syncthreads();

    // qkv = x @ w_in.T + b_in
    {
        const __half* wh = g_win_h + e*(128*384);
        const __half* wl = g_win_l + e*(128*384);
        #pragma unroll 1
        for (int p = 0; p < 3; p++)
            wgemm_h<false>(ah, al, wh + p*128, wl + p*128, 384, qkv + p*128, QKV_LD);
    }
    __syncthreads();

    // attention scores -> sc[(h*32+i)*33 + j], lane-rotated d to kill bank conflicts
    for (int t = tid; t < 4096; t += 256) {
        int j = t & 31, hi = t >> 5;
        int h = hi >> 5, i = hi & 31;
        const float* qq = qkv + i*QKV_LD + h*32;
        const float* kk = qkv + j*QKV_LD + 128 + h*32;
        float s = 0.f;
        int lane = tid & 31;
        #pragma unroll
        for (int d = 0; d < 32; d++) {
            int dd = (d + lane) & 31;
            s += qq[dd]*kk[dd];
        }
        sc[hi*33 + j] = s * 0.17677669529663687f;
    }
    __syncthreads();
    // softmax rows
    if (tid < 128) {
        float* row = sc + tid*33;
        float m = row[0];
        #pragma unroll
        for (int j = 1; j < 32; j++) m = fmaxf(m, row[j]);
        float ssum = 0.f;
        #pragma unroll
        for (int j = 0; j < 32; j++) { float ev = __expf(row[j]-m); row[j] = ev; ssum += ev; }
        float inv = 1.f/ssum;
        #pragma unroll
        for (int j = 0; j < 32; j++) row[j] *= inv;
    }
    __syncthreads();
    // attn out -> q slot of qkv (q is dead)
    for (int t = tid; t < 4096; t += 256) {
        int i = t >> 7, c = t & 127, h = c >> 5;
        const float* pr = sc + (h*32 + i)*33;
        const float* vv = qkv + 256 + c;
        float s = 0.f;
        #pragma unroll
        for (int j = 0; j < 32; j++) s += pr[j]*vv[j*QKV_LD];
        qkv[i*QKV_LD + c] = s;
    }
    __syncthreads();
    // o-proj: split attn-out -> ah/al; sc <- b_out rows
    conv_ahl(qkv, QKV_LD, ah, al);
    for (int i = tid; i < 4096; i += 256) sc[i] = b_out[e*128 + (i & 127)];
    __syncthreads();
    wgemm_h<false>(ah, al, g_wout_h + e*(128*128), g_wout_l + e*(128*128), 128, sc, 128);
    __syncthreads();
    // h = LN(x + o) -> xs
    ln_rows(xs, sc, ln1g + e*128, ln1b + e*128, xs, 1.f);
    __syncthreads();

    // FFN: h halves in ah/al (fixed), f accumulator in registers
    conv_ahl(xs, 128, ah, al);
    for (int i = tid; i < 4096; i += 256) sc[i] = b2[e*128 + (i & 127)];
    __syncthreads();
    int w = tid >> 5, m0 = (w >> 2) << 4, n0 = (w & 3) << 5;
    HC f0, f1;
    wmma::load_matrix_sync(f0, sc + m0*128 + n0,      128, wmma::mem_row_major);
    wmma::load_matrix_sync(f1, sc + m0*128 + n0 + 16, 128, wmma::mem_row_major);
    __syncthreads();

    const __half* w1h = g_w1_h + e*(128*1024);
    const __half* w1l = g_w1_l + e*(128*1024);
    const __half* w2h = g_w2_h + e*(1024*128);
    const __half* w2l = g_w2_l + e*(1024*128);
    __half* sch = (__half*)sc;

    #pragma unroll 1
    for (int ch = 0; ch < 8; ch++) {
        // act = relu(h @ W1chunk + b1chunk) -> sc (fp32)
        for (int i = tid; i < 4096; i += 256) sc[i] = b1[e*1024 + ch*128 + (i & 127)];
        __syncthreads();
        wgemm_h<true>(ah, al, w1h + ch*128, w1l + ch*128, 1024, sc, 128);
        __syncthreads();
        // in-place convert sc -> half hi/lo
        float tmp[16];
        #pragma unroll
        for (int r = 0; r < 16; r++) tmp[r] = sc[tid + r*256];
        __syncthreads();
        #pragma unroll
        for (int r = 0; r < 16; r++) {
            int i = tid + r*256;
            __half h, l; split_h(tmp[r], h, l);
            sch[i] = h; sch[4096 + i] = l;
        }
        __syncthreads();
        // f += act @ W2chunk
        wgemm_acc(sch, sch + 4096, w2h + ch*128*128, w2l + ch*128*128, 128, f0, f1, m0, n0);
        __syncthreads();
    }
    // store f frags -> sc, then LN2
    wmma::store_matrix_sync(sc + m0*128 + n0,      f0, 128, wmma::mem_row_major);
    wmma::store_matrix_sync(sc + m0*128 + n0 + 16, f1, 128, wmma::mem_row_major);
    __syncthreads();
    ln_rows(xs, sc, ln2g + e*128, ln2b + e*128,
            g_ys + ((size_t)slot*NB + b)*4096, gate);
}

// ---------------- head1: hid = relu((ys0+ys1) @ head_w1.T + b1) ----------------
__global__ void __launch_bounds__(256)
head1_kernel(const float* __restrict__ hb1) {
    __shared__ float cb[16*128];
    __shared__ __half xh[16*128], xl[16*128];
    int tid = threadIdx.x, w = tid >> 5;
    int rowbase = blockIdx.x * 16;
    int colbase = blockIdx.y * 128;
    int n0 = w * 16;

    for (int i = tid; i < 2048; i += 256) cb[i] = hb1[colbase + (i & 127)];
    __syncthreads();
    HC c;
    wmma::load_matrix_sync(c, cb + n0, 128, wmma::mem_row_major);
    __syncthreads();

    for (int kc = 0; kc < 4096; kc += 128) {
        for (int i = tid; i < 2048; i += 256) {
            int rr = i >> 7, cc = i & 127;
            size_t gi = (size_t)(rowbase + rr)*4096 + kc + cc;
            float v = g_ys[gi] + g_ys[(size_t)NB*4096 + gi];
            __half h, l; split_h(v, h, l);
            xh[i] = h; xl[i] = l;
        }
        __syncthreads();
        #pragma unroll 2
        for (int k = 0; k < 128; k += 16) {
            HA ah, al;
            wmma::load_matrix_sync(ah, xh + k, 128);
            wmma::load_matrix_sync(al, xl + k, 128);
            HB bh, bl;
            const __half* bph = g_h1_h + (size_t)(kc + k)*HH + colbase + n0;
            const __half* bpl = g_h1_l + (size_t)(kc + k)*HH + colbase + n0;
            wmma::load_matrix_sync(bh, bph, HH);
            wmma::load_matrix_sync(bl, bpl, HH);
            wmma::mma_sync(c, ah, bh, c);
            wmma::mma_sync(c, al, bh, c);
            wmma::mma_sync(c, ah, bl, c);
        }
        __syncthreads();
    }
    #pragma unroll
    for (int i = 0; i < c.num_elements; i++) c.x[i] = fmaxf(c.x[i], 0.f);
    wmma::store_matrix_sync(g_hid + (size_t)rowbase*HH + colbase + n0, c, HH, wmma::mem_row_major);
}

// ---------------- head2 ----------------
__global__ void head2_kernel(const float* __restrict__ w2h, const float* __restrict__ b2h,
                             float* __restrict__ out) {
    int b = blockIdx.x;
    int w = threadIdx.x >> 5, lane = threadIdx.x & 31;
    const float* hp = g_hid + (size_t)b*HH;
    const float* wp = w2h + w*HH;
    float s = 0.f;
    for (int i = lane; i < HH; i += 32) s += hp[i]*wp[i];
    #pragma unroll
    for (int o = 16; o; o >>= 1) s += __shfl_xor_sync(0xffffffffu, s, o);
    if (lane == 0) out[b*NRW + w] = s + b2h[w];
}

// ---------------- launch ----------------
extern "C" void kernel_launch(void* const* d_in, const int* in_sizes, int n_in,
                              void* d_out, int out_size) {
    const float* z     = (const float*)d_in[0];
    const float* a     = (const float*)d_in[1];
    const float* w_gate= (const float*)d_in[2];
    const float* w_in  = (const float*)d_in[3];
    const float* b_in  = (const float*)d_in[4];
    const float* w_out = (const float*)d_in[5];
    const float* b_out = (const float*)d_in[6];
    const float* ln1g  = (const float*)d_in[7];
    const float* ln1b  = (const float*)d_in[8];
    const float* w1    = (const float*)d_in[9];
    const float* b1    = (const float*)d_in[10];
    const float* w2    = (const float*)d_in[11];
    const float* b2    = (const float*)d_in[12];
    const float* ln2g  = (const float*)d_in[13];
    const float* ln2b  = (const float*)d_in[14];
    const float* hw1   = (const float*)d_in[15];
    const float* hb1   = (const float*)d_in[16];
    const float* hw2   = (const float*)d_in[17];
    const float* hb2   = (const float*)d_in[18];
    float* out = (float*)d_out;

    cudaFuncSetAttribute((const void*)expert_kernel,
                         cudaFuncAttributeMaxDynamicSharedMemorySize, SMEM_BYTES);

    repack_kernel<<<4096, 256>>>(w_in, w_out, w1, w2, hw1);
    gating_kernel<<<NB, 256>>>(z, a, w_gate, out + 4096);
    loss_kernel<<<1, 256>>>(out + 4096, out);
    expert_kernel<<<2*NB, 256, SMEM_BYTES>>>(z, a, b_in, b_out, ln1g, ln1b,
                                             b1, b2, ln2g, ln2b);
    head1_kernel<<<dim3(64, 4), 256>>>(hb1);
    head2_kernel<<<NB, 128>>>(hw2, hb2, out);
}

// round 6
// speedup vs baseline: 1.6597x; 1.6597x over previous
#include <cuda_runtime.h>
#include <cuda_fp16.h>
#include <mma.h>
#include <math.h>

using namespace nvcuda;

// ---------------- problem constants ----------------
#define NEXP 8
#define NB   1024
#define NA   32
#define DTOK 128
#define FF   1024
#define HH   512
#define NRW  4
#define MAXG 520

// ---------------- scratch (__device__ globals; no allocs) ----------------
__device__ __half g_win_h [NEXP*DTOK*384];
__device__ __half g_win_l [NEXP*DTOK*384];
__device__ __half g_wout_h[NEXP*DTOK*DTOK];
__device__ __half g_wout_l[NEXP*DTOK*DTOK];
__device__ __half g_w1_h  [NEXP*DTOK*FF];
__device__ __half g_w1_l  [NEXP*DTOK*FF];
__device__ __half g_w2_h  [NEXP*FF*DTOK];
__device__ __half g_w2_l  [NEXP*FF*DTOK];
__device__ __half g_h1_h  [4096*HH];
__device__ __half g_h1_l  [4096*HH];

__device__ float  g_scr   [(size_t)MAXG*128*384];   // per-block qkv / o / h / f scratch
__device__ float  g_ys    [2u*NB*4096];
__device__ float4 g_assign[NB];
__device__ float  g_lse   [NB];
__device__ float  g_hid   [NB*HH];

__device__ int    g_el_bs [NEXP*2048];   // b | slot<<16
__device__ float  g_el_g  [NEXP*2048];
__device__ int4   g_grp   [MAXG];        // x=e, y=base, z=count

// ---------------- smem layout of expert kernel (bytes) ----------------
#define OFF_AH   0
#define OFF_AL   34816
#define OFF_A2H  69632
#define OFF_A2L  88064
#define OFF_BH   106496
#define OFF_BL   124928
#define OFF_CB   143360
#define SMEM_BYTES 178176

// ---------------- smem layout of head1 kernel (bytes) ----------------
#define H1_XH    0
#define H1_XL    9216
#define H1_WHL   18432
#define H1_SMEM  (18432 + 34816)   // 53248

typedef wmma::fragment<wmma::matrix_a, 16,16,16, __half, wmma::row_major> HA;
typedef wmma::fragment<wmma::matrix_b, 16,16,16, __half, wmma::row_major> HB;
typedef wmma::fragment<wmma::accumulator, 16,16,16, float> HC;

__device__ __forceinline__ void split_h(float v, __half& h, __half& l) {
    h = __float2half_rn(v);
    l = __float2half_rn(v - __half2float(h));
}

// ---------------- weight repack: transpose + half hi/lo split ----------------
__global__ void repack_kernel(const float* __restrict__ w_in,
                              const float* __restrict__ w_out,
                              const float* __restrict__ w1,
                              const float* __restrict__ w2,
                              const float* __restrict__ hw1) {
    const int N_in  = NEXP*384*DTOK;
    const int N_out = NEXP*DTOK*DTOK;
    const int N_w1  = NEXP*FF*DTOK;
    const int N_w2  = NEXP*DTOK*FF;
    const int N_h1  = HH*4096;
    const int total = N_in + N_out + N_w1 + N_w2 + N_h1;
    for (int i = blockIdx.x*blockDim.x + threadIdx.x; i < total; i += gridDim.x*blockDim.x) {
        float v; int dst; __half h, l;
        if (i < N_in) {
            int e = i / (384*DTOK); int r = i % (384*DTOK);
            int c = r / DTOK, k = r % DTOK;
            v = w_in[i]; split_h(v, h, l);
            dst = e*(384*DTOK) + k*384 + c;
            g_win_h[dst] = h; g_win_l[dst] = l;
        } else if (i < N_in + N_out) {
            int j = i - N_in;
            int e = j / (DTOK*DTOK); int r = j % (DTOK*DTOK);
            int c = r / DTOK, k = r % DTOK;
            v = w_out[j]; split_h(v, h, l);
            dst = e*(DTOK*DTOK) + k*DTOK + c;
            g_wout_h[dst] = h; g_wout_l[dst] = l;
        } else if (i < N_in + N_out + N_w1) {
            int j = i - N_in - N_out;
            int e = j / (FF*DTOK); int r = j % (FF*DTOK);
            int f = r / DTOK, k = r % DTOK;
            v = w1[j]; split_h(v, h, l);
            dst = e*(FF*DTOK) + k*FF + f;
            g_w1_h[dst] = h; g_w1_l[dst] = l;
        } else if (i < N_in + N_out + N_w1 + N_w2) {
            int j = i - N_in - N_out - N_w1;
            int e = j / (DTOK*FF); int r = j % (DTOK*FF);
            int d = r / FF, k = r % FF;
            v = w2[j]; split_h(v, h, l);
            dst = e*(DTOK*FF) + k*DTOK + d;
            g_w2_h[dst] = h; g_w2_l[dst] = l;
        } else {
            int j = i - N_in - N_out - N_w1 - N_w2;
            int c = j / 4096, k = j % 4096;
            v = hw1[j]; split_h(v, h, l);
            dst = k*HH + c;
            g_h1_h[dst] = h; g_h1_l[dst] = l;
        }
    }
}

// ---------------- gating ----------------
__global__ void gating_kernel(const float* __restrict__ z, const float* __restrict__ a,
                              const float* __restrict__ wg, float* __restrict__ gates_out) {
    int b = blockIdx.x;
    int tid = threadIdx.x, w = tid >> 5, lane = tid & 31;
    __shared__ float lg[NEXP];
    float s = 0.f;
    for (int i = lane; i < 4096; i += 32) {
        int n = i >> 7, d = i & 127;
        float xv = (d < 96) ? z[(b*NA + n)*96 + d] : a[(b*NA + n)*32 + d - 96];
        s += xv * wg[i*NEXP + w];
    }
    #pragma unroll
    for (int o = 16; o; o >>= 1) s += __shfl_xor_sync(0xffffffffu, s, o);
    if (lane == 0) lg[w] = s;
    __syncthreads();
    if (tid == 0) {
        int i0 = 0; float v0 = lg[0];
        for (int e = 1; e < NEXP; e++) if (lg[e] > v0) { v0 = lg[e]; i0 = e; }
        int i1 = -1; float v1 = -1e30f;
        for (int e = 0; e < NEXP; e++) if (e != i0 && lg[e] > v1) { v1 = lg[e]; i1 = e; }
        float g0 = 1.f/(1.f + __expf(v1 - v0));
        float g1 = 1.f - g0;
        for (int e = 0; e < NEXP; e++)
            gates_out[b*NEXP + e] = (e == i0) ? g0 : ((e == i1) ? g1 : 0.f);
        g_assign[b] = make_float4((float)i0, g0, (float)i1, g1);
        float se = 0.f;
        for (int e = 0; e < NEXP; e++) se += __expf(lg[e] - v0);
        g_lse[b] = v0 + logf(se);
    }
}

// ---------------- scheduling: per-expert groups of 4 (b,slot) ----------------
__global__ void sched_kernel() {
    __shared__ int cnt[NEXP];
    int tid = threadIdx.x;
    if (tid < NEXP) cnt[tid] = 0;
    __syncthreads();
    for (int idx = tid; idx < 2*NB; idx += blockDim.x) {
        int b = idx >> 1, slot = idx & 1;
        float4 as = g_assign[b];
        int e = slot ? (int)as.z : (int)as.x;
        float g = slot ? as.w : as.y;
        int pos = atomicAdd(&cnt[e], 1);
        g_el_bs[e*2048 + pos] = b | (slot << 16);
        g_el_g [e*2048 + pos] = g;
    }
    __syncthreads();
    if (tid == 0) {
        int gi = 0;
        for (int e = 0; e < NEXP; e++) {
            for (int s = 0; s < cnt[e]; s += 4) {
                int n = cnt[e] - s; if (n > 4) n = 4;
                g_grp[gi++] = make_int4(e, e*2048 + s, n, 0);
            }
        }
        while (gi < MAXG) g_grp[gi++] = make_int4(-1, 0, 0, 0);
    }
}

// ---------------- balance loss ----------------
__device__ __forceinline__ float cv2_of8(const float* v) {
    float m = 0.f;
    for (int i = 0; i < 8; i++) m += v[i];
    m *= 0.125f;
    float q = 0.f;
    for (int i = 0; i < 8; i++) { float d = v[i]-m; q += d*d; }
    return (q / 7.f) / (m*m + 1e-10f);
}

__global__ void loss_kernel(const float* __restrict__ gates, float* __restrict__ out) {
    __shared__ float imp[NEXP], ldv[NEXP], red[256];
    int tid = threadIdx.x, w = tid >> 5, lane = tid & 31;
    float s = 0.f, c = 0.f;
    for (int b = lane; b < NB; b += 32) {
        float gv = gates[b*NEXP + w];
        s += gv; if (gv > 0.f) c += 1.f;
    }
    #pragma unroll
    for (int o = 16; o; o >>= 1) {
        s += __shfl_xor_sync(0xffffffffu, s, o);
        c += __shfl_xor_sync(0xffffffffu, c, o);
    }
    if (lane == 0) { imp[w] = s; ldv[w] = c; }
    float ls = 0.f;
    for (int b = tid; b < NB; b += 256) ls += g_lse[b];
    red[tid] = ls; __syncthreads();
    for (int o = 128; o; o >>= 1) { if (tid < o) red[tid] += red[tid+o]; __syncthreads(); }
    if (tid == 0)
        out[12288] = cv2_of8(imp) + cv2_of8(ldv) + red[0]*(1.f/1024.f);
}

// ---------------- GEMM helpers (smem-staged, 3-pass hi/lo) ----------------
// stage [128 rows x 64 cols] half slice into BH/BL (ld 72)
__device__ __forceinline__ void stageB64(const __half* __restrict__ sh,
                                         const __half* __restrict__ sl,
                                         int ldsrc, int c0, __half* BH, __half* BL) {
    for (int i = threadIdx.x; i < 1024; i += 256) {
        int r = i >> 3, v = i & 7;
        *(int4*)(BH + r*72 + v*8) = *(const int4*)(sh + (size_t)r*ldsrc + c0 + v*8);
        *(int4*)(BL + r*72 + v*8) = *(const int4*)(sl + (size_t)r*ldsrc + c0 + v*8);
    }
}

// C[128x64] = A[128x128] @ B[128x64]  (A ld136, B ld72, C ld68, 3-pass)
__device__ __forceinline__ void gemm64(const __half* AHs, const __half* ALs,
                                       const __half* BHs, const __half* BLs, float* CB) {
    int w = threadIdx.x >> 5;
    int m0 = (w >> 1) << 5;
    int n0 = (w & 1) << 5;
    HC c00, c01, c10, c11;
    wmma::fill_fragment(c00, 0.f); wmma::fill_fragment(c01, 0.f);
    wmma::fill_fragment(c10, 0.f); wmma::fill_fragment(c11, 0.f);
    #pragma unroll 2
    for (int k = 0; k < 128; k += 16) {
        HA a0h, a1h, a0l, a1l;
        wmma::load_matrix_sync(a0h, AHs + m0*136 + k, 136);
        wmma::load_matrix_sync(a1h, AHs + (m0+16)*136 + k, 136);
        wmma::load_matrix_sync(a0l, ALs + m0*136 + k, 136);
        wmma::load_matrix_sync(a1l, ALs + (m0+16)*136 + k, 136);
        HB b0h, b1h, b0l, b1l;
        wmma::load_matrix_sync(b0h, BHs + k*72 + n0, 72);
        wmma::load_matrix_sync(b1h, BHs + k*72 + n0 + 16, 72);
        wmma::load_matrix_sync(b0l, BLs + k*72 + n0, 72);
        wmma::load_matrix_sync(b1l, BLs + k*72 + n0 + 16, 72);
        wmma::mma_sync(c00, a0h, b0h, c00); wmma::mma_sync(c01, a0h, b1h, c01);
        wmma::mma_sync(c10, a1h, b0h, c10); wmma::mma_sync(c11, a1h, b1h, c11);
        wmma::mma_sync(c00, a0l, b0h, c00); wmma::mma_sync(c01, a0l, b1h, c01);
        wmma::mma_sync(c10, a1l, b0h, c10); wmma::mma_sync(c11, a1l, b1h, c11);
        wmma::mma_sync(c00, a0h, b0l, c00); wmma::mma_sync(c01, a0h, b1l, c01);
        wmma::mma_sync(c10, a1h, b0l, c10); wmma::mma_sync(c11, a1h, b1l, c11);
    }
    wmma::store_matrix_sync(CB + m0*68 + n0,           c00, 68, wmma::mem_row_major);
    wmma::store_matrix_sync(CB + m0*68 + n0 + 16,      c01, 68, wmma::mem_row_major);
    wmma::store_matrix_sync(CB + (m0+16)*68 + n0,      c10, 68, wmma::mem_row_major);
    wmma::store_matrix_sync(CB + (m0+16)*68 + n0 + 16, c11, 68, wmma::mem_row_major);
}

// ff[2][4] += act[128x64] @ W2chunk[64x128]   (A2 ld72, B ld136)
__device__ __forceinline__ void ffn2_acc(const __half* A2H, const __half* A2L,
                                         const __half* BHs, const __half* BLs,
                                         HC ff[2][4], int m0, int n0) {
    #pragma unroll
    for (int k = 0; k < 64; k += 16) {
        HA a0h, a1h, a0l, a1l;
        wmma::load_matrix_sync(a0h, A2H + m0*72 + k, 72);
        wmma::load_matrix_sync(a1h, A2H + (m0+16)*72 + k, 72);
        wmma::load_matrix_sync(a0l, A2L + m0*72 + k, 72);
        wmma::load_matrix_sync(a1l, A2L + (m0+16)*72 + k, 72);
        #pragma unroll
        for (int j = 0; j < 4; j++) {
            HB bh, bl;
            wmma::load_matrix_sync(bh, BHs + k*136 + n0 + 16*j, 136);
            wmma::load_matrix_sync(bl, BLs + k*136 + n0 + 16*j, 136);
            wmma::mma_sync(ff[0][j], a0h, bh, ff[0][j]);
            wmma::mma_sync(ff[1][j], a1h, bh, ff[1][j]);
            wmma::mma_sync(ff[0][j], a0l, bh, ff[0][j]);
            wmma::mma_sync(ff[1][j], a1l, bh, ff[1][j]);
            wmma::mma_sync(ff[0][j], a0h, bl, ff[0][j]);
            wmma::mma_sync(ff[1][j], a1h, bl, ff[1][j]);
        }
    }
}

// ---------------- expert kernel: one block = one expert x 4 batches ----------------
__global__ void __launch_bounds__(256)
expert_kernel(const float* __restrict__ z, const float* __restrict__ a,
              const float* __restrict__ b_in, const float* __restrict__ b_out,
              const float* __restrict__ ln1g, const float* __restrict__ ln1b,
              const float* __restrict__ b1, const float* __restrict__ b2,
              const float* __restrict__ ln2g, const float* __restrict__ ln2b) {
    extern __shared__ char sm8[];
    __half* AH  = (__half*)(sm8 + OFF_AH);
    __half* AL  = (__half*)(sm8 + OFF_AL);
    __half* A2H = (__half*)(sm8 + OFF_A2H);
    __half* A2L = (__half*)(sm8 + OFF_A2L);
    __half* BH  = (__half*)(sm8 + OFF_BH);
    __half* BL  = (__half*)(sm8 + OFF_BL);
    float*  CB  = (float*)(sm8 + OFF_CB);
    float*  SC  = (float*)(sm8 + OFF_BH);   // scores alias (4x4x32x33 fp32)

    int tid = threadIdx.x, w = tid >> 5, lane = tid & 31;
    int4 grp = g_grp[blockIdx.x];
    int e = grp.x;
    if (e < 0) return;

    __shared__ int s_b[4], s_slot[4];
    __shared__ float s_g[4];
    if (tid < 4) {
        if (tid < grp.z) {
            int v = g_el_bs[grp.y + tid];
            s_b[tid] = v & 0xffff; s_slot[tid] = v >> 16;
            s_g[tid] = g_el_g[grp.y + tid];
        } else { s_b[tid] = -1; s_slot[tid] = 0; s_g[tid] = 0.f; }
    }
    __syncthreads();
    float* scr = g_scr + (size_t)blockIdx.x * 49152;

    // ---- P1: load x = concat(z,a), split to AH/AL ----
    for (int i = tid; i < 16384; i += 256) {
        int r = i >> 7, c = i & 127;
        int b = s_b[r >> 5], tok = r & 31;
        float v = 0.f;
        if (b >= 0) v = (c < 96) ? z[(b*NA + tok)*96 + c] : a[(b*NA + tok)*32 + c - 96];
        __half h, l; split_h(v, h, l);
        AH[r*136 + c] = h; AL[r*136 + c] = l;
    }
    __syncthreads();

    // ---- P2: qkv = x @ w_in.T (+bias at store) -> scratch cols 0..383 ----
    for (int p = 0; p < 6; p++) {
        stageB64(g_win_h + e*49152, g_win_l + e*49152, 384, p*64, BH, BL);
        __syncthreads();
        gemm64(AH, AL, BH, BL, CB);
        __syncthreads();
        for (int i = tid; i < 8192; i += 256) {
            int r = i >> 6, c = i & 63;
            scr[r*384 + p*64 + c] = CB[r*68 + c] + b_in[e*384 + p*64 + c];
        }
        __syncthreads();
    }

    // ---- P3: attention (scalar fp32 on scratch qkv) ----
    for (int idx = tid; idx < 16384; idx += 256) {
        int j = idx & 31, i = (idx >> 5) & 31, h = (idx >> 10) & 3, qb = idx >> 12;
        const float4* qp = (const float4*)(scr + (qb*32 + i)*384 + h*32);
        const float4* kp = (const float4*)(scr + (qb*32 + j)*384 + 128 + h*32);
        float s = 0.f;
        #pragma unroll
        for (int d = 0; d < 8; d++) {
            float4 qa = qp[d], ka = kp[d];
            s += qa.x*ka.x + qa.y*ka.y + qa.z*ka.z + qa.w*ka.w;
        }
        SC[((qb*4 + h)*32 + i)*33 + j] = s * 0.17677669529663687f;
    }
    __syncthreads();
    for (int rr = tid; rr < 512; rr += 256) {
        float* row = SC + rr*33;
        float m = row[0];
        #pragma unroll
        for (int j = 1; j < 32; j++) m = fmaxf(m, row[j]);
        float ss = 0.f;
        #pragma unroll
        for (int j = 0; j < 32; j++) { float ev = __expf(row[j]-m); row[j] = ev; ss += ev; }
        float inv = 1.f/ss;
        #pragma unroll
        for (int j = 0; j < 32; j++) row[j] *= inv;
    }
    __syncthreads();
    // attn out -> AH/AL (x no longer needed in smem)
    for (int t = tid; t < 4096; t += 256) {
        int r = t >> 5, c = (t & 31) * 4;
        int qb = r >> 5, i = r & 31, h = c >> 5;
        const float* pr = SC + ((qb*4 + h)*32 + i)*33;
        float4 acc = make_float4(0.f, 0.f, 0.f, 0.f);
        #pragma unroll
        for (int j = 0; j < 32; j++) {
            float p = pr[j];
            float4 v = *(const float4*)(scr + (qb*32 + j)*384 + 256 + c);
            acc.x += p*v.x; acc.y += p*v.y; acc.z += p*v.z; acc.w += p*v.w;
        }
        __half h0, l0;
        split_h(acc.x, h0, l0); AH[r*136 + c]   = h0; AL[r*136 + c]   = l0;
        split_h(acc.y, h0, l0); AH[r*136 + c+1] = h0; AL[r*136 + c+1] = l0;
        split_h(acc.z, h0, l0); AH[r*136 + c+2] = h0; AL[r*136 + c+2] = l0;
        split_h(acc.w, h0, l0); AH[r*136 + c+3] = h0; AL[r*136 + c+3] = l0;
    }
    __syncthreads();

    // ---- P4: o = attn @ w_out.T -> scratch cols 0..127 (bias at LN1) ----
    for (int p = 0; p < 2; p++) {
        stageB64(g_wout_h + e*16384, g_wout_l + e*16384, 128, p*64, BH, BL);
        __syncthreads();
        gemm64(AH, AL, BH, BL, CB);
        __syncthreads();
        for (int i = tid; i < 8192; i += 256) {
            int r = i >> 6, c = i & 63;
            scr[r*384 + p*64 + c] = CB[r*68 + c];
        }
        __syncthreads();
    }

    // ---- P5: h = LN1(x + o + b_out) -> scratch cols 128..255 + AH/AL ----
    {
        float4 gv = *(const float4*)(ln1g + e*128 + lane*4);
        float4 bv = *(const float4*)(ln1b + e*128 + lane*4);
        float4 bo = *(const float4*)(b_out + e*128 + lane*4);
        for (int rr = 0; rr < 16; rr++) {
            int r = w*16 + rr;
            int qb = r >> 5, tok = r & 31, b = s_b[qb];
            float4 o4 = *(const float4*)(scr + r*384 + lane*4);
            float4 x4 = make_float4(0.f, 0.f, 0.f, 0.f);
            if (b >= 0) {
                int c = lane*4;
                x4 = (c < 96) ? *(const float4*)(z + (b*NA + tok)*96 + c)
                              : *(const float4*)(a + (b*NA + tok)*32 + c - 96);
            }
            float vx = x4.x+o4.x+bo.x, vy = x4.y+o4.y+bo.y;
            float vz = x4.z+o4.z+bo.z, vw = x4.w+o4.w+bo.w;
            float s = vx+vy+vz+vw;
            #pragma unroll
            for (int o = 16; o; o >>= 1) s += __shfl_xor_sync(0xffffffffu, s, o);
            float mu = s*(1.f/128.f);
            float dx = vx-mu, dy = vy-mu, dz = vz-mu, dw = vw-mu;
            float q = dx*dx+dy*dy+dz*dz+dw*dw;
            #pragma unroll
            for (int o = 16; o; o >>= 1) q += __shfl_xor_sync(0xffffffffu, q, o);
            float rs = rsqrtf(q*(1.f/128.f) + 1e-5f);
            float hx = dx*rs*gv.x + bv.x, hy = dy*rs*gv.y + bv.y;
            float hz = dz*rs*gv.z + bv.z, hw2 = dw*rs*gv.w + bv.w;
            *(float4*)(scr + r*384 + 128 + lane*4) = make_float4(hx, hy, hz, hw2);
            int c = lane*4;
            __half hh, ll;
            split_h(hx, hh, ll);  AH[r*136+c]   = hh; AL[r*136+c]   = ll;
            split_h(hy, hh, ll);  AH[r*136+c+1] = hh; AL[r*136+c+1] = ll;
            split_h(hz, hh, ll);  AH[r*136+c+2] = hh; AL[r*136+c+2] = ll;
            split_h(hw2, hh, ll); AH[r*136+c+3] = hh; AL[r*136+c+3] = ll;
        }
    }
    __syncthreads();

    // ---- P6: FFN with register-resident f accumulator ----
    int m0 = (w >> 1) << 5, n0ff = (w & 1) << 6;
    HC ff[2][4];
    #pragma unroll
    for (int i = 0; i < 2; i++)
        #pragma unroll
        for (int j = 0; j < 4; j++) wmma::fill_fragment(ff[i][j], 0.f);

    for (int ch = 0; ch < 16; ch++) {
        // act chunk = relu(h @ W1[:,ch*64:+64] + b1) -> A2H/A2L
        stageB64(g_w1_h + e*131072, g_w1_l + e*131072, 1024, ch*64, BH, BL);
        __syncthreads();
        gemm64(AH, AL, BH, BL, CB);
        __syncthreads();
        for (int i = tid; i < 8192; i += 256) {
            int r = i >> 6, c = i & 63;
            float v = fmaxf(CB[r*68 + c] + b1[e*1024 + ch*64 + c], 0.f);
            __half h, l; split_h(v, h, l);
            A2H[r*72 + c] = h; A2L[r*72 + c] = l;
        }
        // stage W2 chunk [64 x 128]
        for (int i = tid; i < 1024; i += 256) {
            int r = i >> 4, v8 = i & 15;
            *(int4*)(BH + r*136 + v8*8) =
                *(const int4*)(g_w2_h + e*131072 + (size_t)(ch*64 + r)*128 + v8*8);
            *(int4*)(BL + r*136 + v8*8) =
                *(const int4*)(g_w2_l + e*131072 + (size_t)(ch*64 + r)*128 + v8*8);
        }
        __syncthreads();
        ffn2_acc(A2H, A2L, BH, BL, ff, m0, n0ff);
        __syncthreads();
    }
    // store f -> scratch cols 256..383
    #pragma unroll
    for (int i = 0; i < 2; i++)
        #pragma unroll
        for (int j = 0; j < 4; j++)
            wmma::store_matrix_sync(scr + (size_t)(m0 + 16*i)*384 + 256 + n0ff + 16*j,
                                    ff[i][j], 384, wmma::mem_row_major);
    __syncthreads();

    // ---- P7: y = gate * LN2(h + f + b2) -> g_ys ----
    {
        float4 gv = *(const float4*)(ln2g + e*128 + lane*4);
        float4 bv = *(const float4*)(ln2b + e*128 + lane*4);
        float4 b2v = *(const float4*)(b2 + e*128 + lane*4);
        for (int rr = 0; rr < 16; rr++) {
            int r = w*16 + rr;
            int qb = r >> 5, tok = r & 31, b = s_b[qb];
            if (b < 0) continue;
            float4 h4 = *(const float4*)(scr + r*384 + 128 + lane*4);
            float4 f4 = *(const float4*)(scr + r*384 + 256 + lane*4);
            float vx = h4.x+f4.x+b2v.x, vy = h4.y+f4.y+b2v.y;
            float vz = h4.z+f4.z+b2v.z, vw = h4.w+f4.w+b2v.w;
            float s = vx+vy+vz+vw;
            #pragma unroll
            for (int o = 16; o; o >>= 1) s += __shfl_xor_sync(0xffffffffu, s, o);
            float mu = s*(1.f/128.f);
            float dx = vx-mu, dy = vy-mu, dz = vz-mu, dw = vw-mu;
            float q = dx*dx+dy*dy+dz*dz+dw*dw;
            #pragma unroll
            for (int o = 16; o; o >>= 1) q += __shfl_xor_sync(0xffffffffu, q, o);
            float rs = rsqrtf(q*(1.f/128.f) + 1e-5f);
            float gt = s_g[qb];
            float4 res;
            res.x = (dx*rs*gv.x + bv.x)*gt;
            res.y = (dy*rs*gv.y + bv.y)*gt;
            res.z = (dz*rs*gv.z + bv.z)*gt;
            res.w = (dw*rs*gv.w + bv.w)*gt;
            *(float4*)(g_ys + ((size_t)(s_slot[qb]*NB + b))*4096 + tok*128 + lane*4) = res;
        }
    }
}

// ---------------- head1: hid = relu((ys0+ys1) @ head_w1.T + b1) ----------------
__global__ void __launch_bounds__(256)
head1_kernel(const float* __restrict__ hb1) {
    extern __shared__ char h1sm[];
    __half* XH  = (__half*)(h1sm + H1_XH);    // 64x72
    __half* XL  = (__half*)(h1sm + H1_XL);    // 64x72
    __half* WHL = (__half*)(h1sm + H1_WHL);   // 2 x 64x136
    __half* WH = WHL;
    __half* WL = WHL + 64*136;
    int tid = threadIdx.x, w = tid >> 5;
    int rowbase = blockIdx.x * 64;
    int colbase = blockIdx.y * 128;
    int m0 = (w >> 2) << 5;     // 2 M groups
    int n0 = (w & 3) << 5;      // 4 N groups
    HC c00, c01, c10, c11;
    wmma::fill_fragment(c00, 0.f); wmma::fill_fragment(c01, 0.f);
    wmma::fill_fragment(c10, 0.f); wmma::fill_fragment(c11, 0.f);

    for (int kc = 0; kc < 4096; kc += 64) {
        for (int i = tid; i < 4096; i += 256) {
            int r = i >> 6, cc = i & 63;
            size_t gi = (size_t)(rowbase + r)*4096 + kc + cc;
            float v = g_ys[gi] + g_ys[(size_t)NB*4096 + gi];
            __half h, l; split_h(v, h, l);
            XH[r*72 + cc] = h; XL[r*72 + cc] = l;
        }
        for (int i = tid; i < 1024; i += 256) {
            int r = i >> 4, v8 = i & 15;
            *(int4*)(WH + r*136 + v8*8) =
                *(const int4*)(g_h1_h + (size_t)(kc + r)*HH + colbase + v8*8);
            *(int4*)(WL + r*136 + v8*8) =
                *(const int4*)(g_h1_l + (size_t)(kc + r)*HH + colbase + v8*8);
        }
        __syncthreads();
        #pragma unroll
        for (int k = 0; k < 64; k += 16) {
            HA a0h, a1h, a0l, a1l;
            wmma::load_matrix_sync(a0h, XH + m0*72 + k, 72);
            wmma::load_matrix_sync(a1h, XH + (m0+16)*72 + k, 72);
            wmma::load_matrix_sync(a0l, XL + m0*72 + k, 72);
            wmma::load_matrix_sync(a1l, XL + (m0+16)*72 + k, 72);
            HB b0h, b1h, b0l, b1l;
            wmma::load_matrix_sync(b0h, WH + k*136 + n0, 136);
            wmma::load_matrix_sync(b1h, WH + k*136 + n0 + 16, 136);
            wmma::load_matrix_sync(b0l, WL + k*136 + n0, 136);
            wmma::load_matrix_sync(b1l, WL + k*136 + n0 + 16, 136);
            wmma::mma_sync(c00, a0h, b0h, c00); wmma::mma_sync(c01, a0h, b1h, c01);
            wmma::mma_sync(c10, a1h, b0h, c10); wmma::mma_sync(c11, a1h, b1h, c11);
            wmma::mma_sync(c00, a0l, b0h, c00); wmma::mma_sync(c01, a0l, b1h, c01);
            wmma::mma_sync(c10, a1l, b0h, c10); wmma::mma_sync(c11, a1l, b1h, c11);
            wmma::mma_sync(c00, a0h, b0l, c00); wmma::mma_sync(c01, a0h, b1l, c01);
            wmma::mma_sync(c10, a1h, b0l, c10); wmma::mma_sync(c11, a1h, b1l, c11);
        }
        __syncthreads();
    }
    // write via smem fp32 staging (reuse WHL: 64x132 floats)
    float* OB = (float*)WHL;
    wmma::store_matrix_sync(OB + m0*132 + n0,           c00, 132, wmma::mem_row_major);
    wmma::store_matrix_sync(OB + m0*132 + n0 + 16,      c01, 132, wmma::mem_row_major);
    wmma::store_matrix_sync(OB + (m0+16)*132 + n0,      c10, 132, wmma::mem_row_major);
    wmma::store_matrix_sync(OB + (m0+16)*132 + n0 + 16, c11, 132, wmma::mem_row_major);
    __syncthreads();
    for (int i = tid; i < 8192; i += 256) {
        int r = i >> 7, cc = i & 127;
        g_hid[(size_t)(rowbase + r)*HH + colbase + cc] =
            fmaxf(OB[r*132 + cc] + hb1[colbase + cc], 0.f);
    }
}

// ---------------- head2 ----------------
__global__ void head2_kernel(const float* __restrict__ w2h, const float* __restrict__ b2h,
                             float* __restrict__ out) {
    int b = blockIdx.x;
    int w = threadIdx.x >> 5, lane = threadIdx.x & 31;
    const float* hp = g_hid + (size_t)b*HH;
    const float* wp = w2h + w*HH;
    float s = 0.f;
    for (int i = lane; i < HH; i += 32) s += hp[i]*wp[i];
    #pragma unroll
    for (int o = 16; o; o >>= 1) s += __shfl_xor_sync(0xffffffffu, s, o);
    if (lane == 0) out[b*NRW + w] = s + b2h[w];
}

// ---------------- launch ----------------
extern "C" void kernel_launch(void* const* d_in, const int* in_sizes, int n_in,
                              void* d_out, int out_size) {
    const float* z     = (const float*)d_in[0];
    const float* a     = (const float*)d_in[1];
    const float* w_gate= (const float*)d_in[2];
    const float* w_in  = (const float*)d_in[3];
    const float* b_in  = (const float*)d_in[4];
    const float* w_out = (const float*)d_in[5];
    const float* b_out = (const float*)d_in[6];
    const float* ln1g  = (const float*)d_in[7];
    const float* ln1b  = (const float*)d_in[8];
    const float* w1    = (const float*)d_in[9];
    const float* b1    = (const float*)d_in[10];
    const float* w2    = (const float*)d_in[11];
    const float* b2    = (const float*)d_in[12];
    const float* ln2g  = (const float*)d_in[13];
    const float* ln2b  = (const float*)d_in[14];
    const float* hw1   = (const float*)d_in[15];
    const float* hb1   = (const float*)d_in[16];
    const float* hw2   = (const float*)d_in[17];
    const float* hb2   = (const float*)d_in[18];
    float* out = (float*)d_out;

    cudaFuncSetAttribute((const void*)expert_kernel,
                         cudaFuncAttributeMaxDynamicSharedMemorySize, SMEM_BYTES);
    cudaFuncSetAttribute((const void*)head1_kernel,
                         cudaFuncAttributeMaxDynamicSharedMemorySize, H1_SMEM);

    repack_kernel<<<4096, 256>>>(w_in, w_out, w1, w2, hw1);
    gating_kernel<<<NB, 256>>>(z, a, w_gate, out + 4096);
    sched_kernel<<<1, 256>>>();
    loss_kernel<<<1, 256>>>(out + 4096, out);
    expert_kernel<<<MAXG, 256, SMEM_BYTES>>>(z, a, b_in, b_out, ln1g, ln1b,
                                             b1, b2, ln2g, ln2b);
    head1_kernel<<<dim3(16, 4), 256, H1_SMEM>>>(hb1);
    head2_kernel<<<NB, 128>>>(hw2, hb2, out);
}

// round 7
// speedup vs baseline: 2.0988x; 1.2646x over previous
#include <cuda_runtime.h>
#include <cuda_fp16.h>
#include <mma.h>
#include <math.h>

using namespace nvcuda;

// ---------------- problem constants ----------------
#define NEXP 8
#define NB   1024
#define NA   32
#define DTOK 128
#define FF   1024
#define HH   512
#define NRW  4
#define MAXG 520
#define NT   512     // expert kernel threads

// ---------------- scratch (__device__ globals; no allocs) ----------------
__device__ __half g_win_h [NEXP*DTOK*384];
__device__ __half g_win_l [NEXP*DTOK*384];
__device__ __half g_wout_h[NEXP*DTOK*DTOK];
__device__ __half g_wout_l[NEXP*DTOK*DTOK];
__device__ __half g_w1_h  [NEXP*DTOK*FF];
__device__ __half g_w1_l  [NEXP*DTOK*FF];
__device__ __half g_w2_h  [NEXP*FF*DTOK];
__device__ __half g_w2_l  [NEXP*FF*DTOK];
__device__ __half g_h1_h  [4096*HH];
__device__ __half g_h1_l  [4096*HH];

__device__ float  g_scr   [(size_t)MAXG*128*384];
__device__ float  g_ys    [2u*NB*4096];
__device__ float4 g_assign[NB];
__device__ float  g_lse   [NB];
__device__ float  g_hid   [NB*HH];

__device__ int    g_el_bs [NEXP*2048];
__device__ float  g_el_g  [NEXP*2048];
__device__ int4   g_grp   [MAXG];

// ---------------- expert smem layout (bytes) ----------------
#define OFF_AH   0          // 128x136 half
#define OFF_AL   34816
#define OFF_A2H  69632      // 128x72 half
#define OFF_A2L  88064
#define OFF_B0   106496     // BH0 (18432) + BL0 (18432)
#define OFF_B1   143360
#define OFF_CB   180224     // 128x68 fp32
#define SMEM_BYTES 215040
#define BL_HOFF  9216       // BL offset from buffer base, in halfs

// ---------------- head1 smem layout (bytes) ----------------
#define H1_XH    0
#define H1_XL    9216
#define H1_WHL   18432
#define H1_SMEM  (18432 + 34816)

typedef wmma::fragment<wmma::matrix_a, 16,16,16, __half, wmma::row_major> HA;
typedef wmma::fragment<wmma::matrix_b, 16,16,16, __half, wmma::row_major> HB;
typedef wmma::fragment<wmma::accumulator, 16,16,16, float> HC;

__device__ __forceinline__ void split_h(float v, __half& h, __half& l) {
    h = __float2half_rn(v);
    l = __float2half_rn(v - __half2float(h));
}

__device__ __forceinline__ void cpa16(void* dst, const void* src) {
    unsigned d = (unsigned)__cvta_generic_to_shared(dst);
    asm volatile("cp.async.cg.shared.global [%0], [%1], 16;\n" :: "r"(d), "l"(src));
}
#define CP_COMMIT() asm volatile("cp.async.commit_group;\n" ::: "memory")
#define CP_WAIT1()  asm volatile("cp.async.wait_group 1;\n" ::: "memory")
#define CP_WAIT0()  asm volatile("cp.async.wait_group 0;\n" ::: "memory")

// ---------------- weight repack ----------------
__global__ void repack_kernel(const float* __restrict__ w_in,
                              const float* __restrict__ w_out,
                              const float* __restrict__ w1,
                              const float* __restrict__ w2,
                              const float* __restrict__ hw1) {
    const int N_in  = NEXP*384*DTOK;
    const int N_out = NEXP*DTOK*DTOK;
    const int N_w1  = NEXP*FF*DTOK;
    const int N_w2  = NEXP*DTOK*FF;
    const int N_h1  = HH*4096;
    const int total = N_in + N_out + N_w1 + N_w2 + N_h1;
    for (int i = blockIdx.x*blockDim.x + threadIdx.x; i < total; i += gridDim.x*blockDim.x) {
        float v; int dst; __half h, l;
        if (i < N_in) {
            int e = i / (384*DTOK); int r = i % (384*DTOK);
            int c = r / DTOK, k = r % DTOK;
            v = w_in[i]; split_h(v, h, l);
            dst = e*(384*DTOK) + k*384 + c;
            g_win_h[dst] = h; g_win_l[dst] = l;
        } else if (i < N_in + N_out) {
            int j = i - N_in;
            int e = j / (DTOK*DTOK); int r = j % (DTOK*DTOK);
            int c = r / DTOK, k = r % DTOK;
            v = w_out[j]; split_h(v, h, l);
            dst = e*(DTOK*DTOK) + k*DTOK + c;
            g_wout_h[dst] = h; g_wout_l[dst] = l;
        } else if (i < N_in + N_out + N_w1) {
            int j = i - N_in - N_out;
            int e = j / (FF*DTOK); int r = j % (FF*DTOK);
            int f = r / DTOK, k = r % DTOK;
            v = w1[j]; split_h(v, h, l);
            dst = e*(FF*DTOK) + k*FF + f;
            g_w1_h[dst] = h; g_w1_l[dst] = l;
        } else if (i < N_in + N_out + N_w1 + N_w2) {
            int j = i - N_in - N_out - N_w1;
            int e = j / (DTOK*FF); int r = j % (DTOK*FF);
            int d = r / FF, k = r % FF;
            v = w2[j]; split_h(v, h, l);
            dst = e*(DTOK*FF) + k*DTOK + d;
            g_w2_h[dst] = h; g_w2_l[dst] = l;
        } else {
            int j = i - N_in - N_out - N_w1 - N_w2;
            int c = j / 4096, k = j % 4096;
            v = hw1[j]; split_h(v, h, l);
            dst = k*HH + c;
            g_h1_h[dst] = h; g_h1_l[dst] = l;
        }
    }
}

// ---------------- gating ----------------
__global__ void gating_kernel(const float* __restrict__ z, const float* __restrict__ a,
                              const float* __restrict__ wg, float* __restrict__ gates_out) {
    int b = blockIdx.x;
    int tid = threadIdx.x, w = tid >> 5, lane = tid & 31;
    __shared__ float lg[NEXP];
    float s = 0.f;
    for (int i = lane; i < 4096; i += 32) {
        int n = i >> 7, d = i & 127;
        float xv = (d < 96) ? z[(b*NA + n)*96 + d] : a[(b*NA + n)*32 + d - 96];
        s += xv * wg[i*NEXP + w];
    }
    #pragma unroll
    for (int o = 16; o; o >>= 1) s += __shfl_xor_sync(0xffffffffu, s, o);
    if (lane == 0) lg[w] = s;
    __syncthreads();
    if (tid == 0) {
        int i0 = 0; float v0 = lg[0];
        for (int e = 1; e < NEXP; e++) if (lg[e] > v0) { v0 = lg[e]; i0 = e; }
        int i1 = -1; float v1 = -1e30f;
        for (int e = 0; e < NEXP; e++) if (e != i0 && lg[e] > v1) { v1 = lg[e]; i1 = e; }
        float g0 = 1.f/(1.f + __expf(v1 - v0));
        float g1 = 1.f - g0;
        for (int e = 0; e < NEXP; e++)
            gates_out[b*NEXP + e] = (e == i0) ? g0 : ((e == i1) ? g1 : 0.f);
        g_assign[b] = make_float4((float)i0, g0, (float)i1, g1);
        float se = 0.f;
        for (int e = 0; e < NEXP; e++) se += __expf(lg[e] - v0);
        g_lse[b] = v0 + logf(se);
    }
}

// ---------------- scheduling ----------------
__global__ void sched_kernel() {
    __shared__ int cnt[NEXP];
    int tid = threadIdx.x;
    if (tid < NEXP) cnt[tid] = 0;
    __syncthreads();
    for (int idx = tid; idx < 2*NB; idx += blockDim.x) {
        int b = idx >> 1, slot = idx & 1;
        float4 as = g_assign[b];
        int e = slot ? (int)as.z : (int)as.x;
        float g = slot ? as.w : as.y;
        int pos = atomicAdd(&cnt[e], 1);
        g_el_bs[e*2048 + pos] = b | (slot << 16);
        g_el_g [e*2048 + pos] = g;
    }
    __syncthreads();
    if (tid == 0) {
        int gi = 0;
        for (int e = 0; e < NEXP; e++) {
            for (int s = 0; s < cnt[e]; s += 4) {
                int n = cnt[e] - s; if (n > 4) n = 4;
                g_grp[gi++] = make_int4(e, e*2048 + s, n, 0);
            }
        }
        while (gi < MAXG) g_grp[gi++] = make_int4(-1, 0, 0, 0);
    }
}

// ---------------- balance loss ----------------
__device__ __forceinline__ float cv2_of8(const float* v) {
    float m = 0.f;
    for (int i = 0; i < 8; i++) m += v[i];
    m *= 0.125f;
    float q = 0.f;
    for (int i = 0; i < 8; i++) { float d = v[i]-m; q += d*d; }
    return (q / 7.f) / (m*m + 1e-10f);
}

__global__ void loss_kernel(const float* __restrict__ gates, float* __restrict__ out) {
    __shared__ float imp[NEXP], ldv[NEXP], red[256];
    int tid = threadIdx.x, w = tid >> 5, lane = tid & 31;
    float s = 0.f, c = 0.f;
    for (int b = lane; b < NB; b += 32) {
        float gv = gates[b*NEXP + w];
        s += gv; if (gv > 0.f) c += 1.f;
    }
    #pragma unroll
    for (int o = 16; o; o >>= 1) {
        s += __shfl_xor_sync(0xffffffffu, s, o);
        c += __shfl_xor_sync(0xffffffffu, c, o);
    }
    if (lane == 0) { imp[w] = s; ldv[w] = c; }
    float ls = 0.f;
    for (int b = tid; b < NB; b += 256) ls += g_lse[b];
    red[tid] = ls; __syncthreads();
    for (int o = 128; o; o >>= 1) { if (tid < o) red[tid] += red[tid+o]; __syncthreads(); }
    if (tid == 0)
        out[12288] = cv2_of8(imp) + cv2_of8(ldv) + red[0]*(1.f/1024.f);
}

// ---------------- async staging ----------------
// 128 rows x 64 cols (src ld ldsrc) -> buf (BH ld72, BL at +9216 halfs)
__device__ __forceinline__ void stage64_async(__half* buf, const __half* __restrict__ sh,
                                              const __half* __restrict__ sl,
                                              int ldsrc, int c0) {
    __half* BH = buf; __half* BL = buf + BL_HOFF;
    for (int i = threadIdx.x; i < 1024; i += NT) {
        int r = i >> 3, v = i & 7;
        cpa16(BH + r*72 + v*8, sh + (size_t)r*ldsrc + c0 + v*8);
        cpa16(BL + r*72 + v*8, sl + (size_t)r*ldsrc + c0 + v*8);
    }
}
// W2 chunk 64 rows x 128 cols -> buf (ld 136)
__device__ __forceinline__ void stageW2_async(__half* buf, int e, int ch) {
    __half* BH = buf; __half* BL = buf + BL_HOFF;
    const __half* sh = g_w2_h + e*131072 + (size_t)ch*64*128;
    const __half* sl = g_w2_l + e*131072 + (size_t)ch*64*128;
    for (int i = threadIdx.x; i < 1024; i += NT) {
        int r = i >> 4, v = i & 15;
        cpa16(BH + r*136 + v*8, sh + (size_t)r*128 + v*8);
        cpa16(BL + r*136 + v*8, sl + (size_t)r*128 + v*8);
    }
}

// ---------------- GEMM helpers (16 warps) ----------------
// C[128x64] = A[128x128] @ B[128x64]  (A ld136, B ld72, C ld68, 3-pass)
__device__ __forceinline__ void gemm64(const __half* AHs, const __half* ALs,
                                       const __half* buf, float* CB) {
    const __half* BHs = buf;
    const __half* BLs = buf + BL_HOFF;
    int w = threadIdx.x >> 5;
    int m0 = (w >> 1) << 4;       // 0..112
    int n0 = (w & 1) << 5;        // 0, 32
    HC c0, c1;
    wmma::fill_fragment(c0, 0.f);
    wmma::fill_fragment(c1, 0.f);
    #pragma unroll 2
    for (int k = 0; k < 128; k += 16) {
        HA ah, al;
        wmma::load_matrix_sync(ah, AHs + m0*136 + k, 136);
        wmma::load_matrix_sync(al, ALs + m0*136 + k, 136);
        HB bh0, bh1, bl0, bl1;
        wmma::load_matrix_sync(bh0, BHs + k*72 + n0, 72);
        wmma::load_matrix_sync(bh1, BHs + k*72 + n0 + 16, 72);
        wmma::load_matrix_sync(bl0, BLs + k*72 + n0, 72);
        wmma::load_matrix_sync(bl1, BLs + k*72 + n0 + 16, 72);
        wmma::mma_sync(c0, ah, bh0, c0); wmma::mma_sync(c1, ah, bh1, c1);
        wmma::mma_sync(c0, al, bh0, c0); wmma::mma_sync(c1, al, bh1, c1);
        wmma::mma_sync(c0, ah, bl0, c0); wmma::mma_sync(c1, ah, bl1, c1);
    }
    wmma::store_matrix_sync(CB + m0*68 + n0,      c0, 68, wmma::mem_row_major);
    wmma::store_matrix_sync(CB + m0*68 + n0 + 16, c1, 68, wmma::mem_row_major);
}

// ff[4] += act[128x64] @ W2chunk[64x128]   (A2 ld72, B ld136)
__device__ __forceinline__ void ffn2_acc(const __half* A2H, const __half* A2L,
                                         const __half* buf, HC ff[4], int m0, int n0) {
    const __half* BHs = buf;
    const __half* BLs = buf + BL_HOFF;
    #pragma unroll
    for (int k = 0; k < 64; k += 16) {
        HA ah, al;
        wmma::load_matrix_sync(ah, A2H + m0*72 + k, 72);
        wmma::load_matrix_sync(al, A2L + m0*72 + k, 72);
        #pragma unroll
        for (int j = 0; j < 4; j++) {
            HB bh, bl;
            wmma::load_matrix_sync(bh, BHs + k*136 + n0 + 16*j, 136);
            wmma::load_matrix_sync(bl, BLs + k*136 + n0 + 16*j, 136);
            wmma::mma_sync(ff[j], ah, bh, ff[j]);
            wmma::mma_sync(ff[j], al, bh, ff[j]);
            wmma::mma_sync(ff[j], ah, bl, ff[j]);
        }
    }
}

// ---------------- expert kernel ----------------
__global__ void __launch_bounds__(NT, 1)
expert_kernel(const float* __restrict__ z, const float* __restrict__ a,
              const float* __restrict__ b_in, const float* __restrict__ b_out,
              const float* __restrict__ ln1g, const float* __restrict__ ln1b,
              const float* __restrict__ b1, const float* __restrict__ b2,
              const float* __restrict__ ln2g, const float* __restrict__ ln2b) {
    extern __shared__ char sm8[];
    __half* AH  = (__half*)(sm8 + OFF_AH);
    __half* AL  = (__half*)(sm8 + OFF_AL);
    __half* A2H = (__half*)(sm8 + OFF_A2H);
    __half* A2L = (__half*)(sm8 + OFF_A2L);
    __half* B0  = (__half*)(sm8 + OFF_B0);
    __half* B1  = (__half*)(sm8 + OFF_B1);
    float*  CB  = (float*)(sm8 + OFF_CB);
    float*  SC  = (float*)(sm8 + OFF_B0);   // scores alias over B0+B1

    int tid = threadIdx.x, w = tid >> 5, lane = tid & 31;
    int4 grp = g_grp[blockIdx.x];
    int e = grp.x;
    if (e < 0) return;

    __shared__ int s_b[4], s_slot[4];
    __shared__ float s_g[4];
    if (tid < 4) {
        if (tid < grp.z) {
            int v = g_el_bs[grp.y + tid];
            s_b[tid] = v & 0xffff; s_slot[tid] = v >> 16;
            s_g[tid] = g_el_g[grp.y + tid];
        } else { s_b[tid] = -1; s_slot[tid] = 0; s_g[tid] = 0.f; }
    }
    float* scr = g_scr + (size_t)blockIdx.x * 49152;
    const __half* winh = g_win_h + e*49152;
    const __half* winl = g_win_l + e*49152;

    // prefetch qkv tile 0 while loading x
    stage64_async(B0, winh, winl, 384, 0);
    CP_COMMIT();
    __syncthreads();   // s_b visible

    // ---- P1: x = concat(z,a) -> AH/AL ----
    for (int i = tid; i < 16384; i += NT) {
        int r = i >> 7, c = i & 127;
        int b = s_b[r >> 5], tok = r & 31;
        float v = 0.f;
        if (b >= 0) v = (c < 96) ? z[(b*NA + tok)*96 + c] : a[(b*NA + tok)*32 + c - 96];
        __half h, l; split_h(v, h, l);
        AH[r*136 + c] = h; AL[r*136 + c] = l;
    }
    __syncthreads();

    // ---- P2: qkv = x @ w_in.T + b_in -> scratch ----
    #pragma unroll 1
    for (int p = 0; p < 6; p++) {
        if (p < 5) { stage64_async((p & 1) ? B0 : B1, winh, winl, 384, (p+1)*64); CP_COMMIT(); }
        if (p < 5) { CP_WAIT1(); } else { CP_WAIT0(); }
        __syncthreads();
        gemm64(AH, AL, (p & 1) ? B1 : B0, CB);
        __syncthreads();
        for (int i = tid; i < 8192; i += NT) {
            int r = i >> 6, c = i & 63;
            scr[r*384 + p*64 + c] = CB[r*68 + c] + b_in[e*384 + p*64 + c];
        }
    }
    __syncthreads();

    // ---- P3: attention ----
    for (int idx = tid; idx < 16384; idx += NT) {
        int j = idx & 31, i = (idx >> 5) & 31, h = (idx >> 10) & 3, qb = idx >> 12;
        const float4* qp = (const float4*)(scr + (qb*32 + i)*384 + h*32);
        const float4* kp = (const float4*)(scr + (qb*32 + j)*384 + 128 + h*32);
        float s = 0.f;
        #pragma unroll
        for (int d = 0; d < 8; d++) {
            float4 qa = qp[d], ka = kp[d];
            s += qa.x*ka.x + qa.y*ka.y + qa.z*ka.z + qa.w*ka.w;
        }
        SC[((qb*4 + h)*32 + i)*33 + j] = s * 0.17677669529663687f;
    }
    __syncthreads();
    if (tid < 512) {
        float* row = SC + tid*33;
        float m = row[0];
        #pragma unroll
        for (int j = 1; j < 32; j++) m = fmaxf(m, row[j]);
        float ss = 0.f;
        #pragma unroll
        for (int j = 0; j < 32; j++) { float ev = __expf(row[j]-m); row[j] = ev; ss += ev; }
        float inv = 1.f/ss;
        #pragma unroll
        for (int j = 0; j < 32; j++) row[j] *= inv;
    }
    __syncthreads();
    for (int t = tid; t < 4096; t += NT) {
        int r = t >> 5, c = (t & 31) * 4;
        int qb = r >> 5, i = r & 31, h = c >> 5;
        const float* pr = SC + ((qb*4 + h)*32 + i)*33;
        float4 acc = make_float4(0.f, 0.f, 0.f, 0.f);
        #pragma unroll
        for (int j = 0; j < 32; j++) {
            float p = pr[j];
            float4 v = *(const float4*)(scr + (qb*32 + j)*384 + 256 + c);
            acc.x += p*v.x; acc.y += p*v.y; acc.z += p*v.z; acc.w += p*v.w;
        }
        __half h0, l0;
        split_h(acc.x, h0, l0); AH[r*136 + c]   = h0; AL[r*136 + c]   = l0;
        split_h(acc.y, h0, l0); AH[r*136 + c+1] = h0; AL[r*136 + c+1] = l0;
        split_h(acc.z, h0, l0); AH[r*136 + c+2] = h0; AL[r*136 + c+2] = l0;
        split_h(acc.w, h0, l0); AH[r*136 + c+3] = h0; AL[r*136 + c+3] = l0;
    }
    __syncthreads();   // SC no longer needed; B0/B1 free

    // ---- P4: o = attn @ w_out.T, with W1_0 / W2_0 prefetch ----
    const __half* wouth = g_wout_h + e*16384;
    const __half* woutl = g_wout_l + e*16384;
    stage64_async(B0, wouth, woutl, 128, 0);   CP_COMMIT();
    stage64_async(B1, wouth, woutl, 128, 64);  CP_COMMIT();
    CP_WAIT1(); __syncthreads();
    gemm64(AH, AL, B0, CB);
    __syncthreads();
    stage64_async(B0, g_w1_h + e*131072, g_w1_l + e*131072, 1024, 0); CP_COMMIT();
    for (int i = tid; i < 8192; i += NT) {
        int r = i >> 6, c = i & 63;
        scr[r*384 + c] = CB[r*68 + c];
    }
    CP_WAIT1(); __syncthreads();
    gemm64(AH, AL, B1, CB);
    __syncthreads();
    stageW2_async(B1, e, 0); CP_COMMIT();
    for (int i = tid; i < 8192; i += NT) {
        int r = i >> 6, c = i & 63;
        scr[r*384 + 64 + c] = CB[r*68 + c];
    }
    __syncthreads();

    // ---- P5: h = LN1(x + o + b_out) -> scratch 128.. + AH/AL ----
    {
        float4 gv = *(const float4*)(ln1g + e*128 + lane*4);
        float4 bv = *(const float4*)(ln1b + e*128 + lane*4);
        float4 bo = *(const float4*)(b_out + e*128 + lane*4);
        for (int rr = 0; rr < 8; rr++) {
            int r = w*8 + rr;
            int qb = r >> 5, tok = r & 31, b = s_b[qb];
            float4 o4 = *(const float4*)(scr + r*384 + lane*4);
            float4 x4 = make_float4(0.f, 0.f, 0.f, 0.f);
            if (b >= 0) {
                int c = lane*4;
                x4 = (c < 96) ? *(const float4*)(z + (b*NA + tok)*96 + c)
                              : *(const float4*)(a + (b*NA + tok)*32 + c - 96);
            }
            float vx = x4.x+o4.x+bo.x, vy = x4.y+o4.y+bo.y;
            float vz = x4.z+o4.z+bo.z, vw = x4.w+o4.w+bo.w;
            float s = vx+vy+vz+vw;
            #pragma unroll
            for (int o = 16; o; o >>= 1) s += __shfl_xor_sync(0xffffffffu, s, o);
            float mu = s*(1.f/128.f);
            float dx = vx-mu, dy = vy-mu, dz = vz-mu, dw = vw-mu;
            float q = dx*dx+dy*dy+dz*dz+dw*dw;
            #pragma unroll
            for (int o = 16; o; o >>= 1) q += __shfl_xor_sync(0xffffffffu, q, o);
            float rs = rsqrtf(q*(1.f/128.f) + 1e-5f);
            float hx = dx*rs*gv.x + bv.x, hy = dy*rs*gv.y + bv.y;
            float hz = dz*rs*gv.z + bv.z, hw2 = dw*rs*gv.w + bv.w;
            *(float4*)(scr + r*384 + 128 + lane*4) = make_float4(hx, hy, hz, hw2);
            int c = lane*4;
            __half hh, ll;
            split_h(hx, hh, ll);  AH[r*136+c]   = hh; AL[r*136+c]   = ll;
            split_h(hy, hh, ll);  AH[r*136+c+1] = hh; AL[r*136+c+1] = ll;
            split_h(hz, hh, ll);  AH[r*136+c+2] = hh; AL[r*136+c+2] = ll;
            split_h(hw2, hh, ll); AH[r*136+c+3] = hh; AL[r*136+c+3] = ll;
        }
    }
    __syncthreads();

    // ---- P6: FFN, pipelined W1(B0)/W2(B1), f accumulator in registers ----
    int m0 = (w >> 1) << 4, n0ff = (w & 1) << 6;
    HC ff[4];
    #pragma unroll
    for (int j = 0; j < 4; j++) wmma::fill_fragment(ff[j], 0.f);

    #pragma unroll 1
    for (int ch = 0; ch < 16; ch++) {
        // pending: [W1_ch, W2_ch]
        CP_WAIT1(); __syncthreads();                     // B0 = W1_ch ready
        gemm64(AH, AL, B0, CB);
        __syncthreads();
        if (ch < 15) { stage64_async(B0, g_w1_h + e*131072, g_w1_l + e*131072, 1024, (ch+1)*64); CP_COMMIT(); }
        for (int i = tid; i < 8192; i += NT) {
            int r = i >> 6, c = i & 63;
            float v = fmaxf(CB[r*68 + c] + b1[e*1024 + ch*64 + c], 0.f);
            __half h, l; split_h(v, h, l);
            A2H[r*72 + c] = h; A2L[r*72 + c] = l;
        }
        if (ch < 15) { CP_WAIT1(); } else { CP_WAIT0(); }
        __syncthreads();                                 // B1 = W2_ch ready, A2 visible
        ffn2_acc(A2H, A2L, B1, ff, m0, n0ff);
        __syncthreads();
        if (ch < 15) { stageW2_async(B1, e, ch+1); CP_COMMIT(); }
    }
    #pragma unroll
    for (int j = 0; j < 4; j++)
        wmma::store_matrix_sync(scr + (size_t)m0*384 + 256 + n0ff + 16*j,
                                ff[j], 384, wmma::mem_row_major);
    __syncthreads();

    // ---- P7: y = gate * LN2(h + f + b2) -> g_ys ----
    {
        float4 gv = *(const float4*)(ln2g + e*128 + lane*4);
        float4 bv = *(const float4*)(ln2b + e*128 + lane*4);
        float4 b2v = *(const float4*)(b2 + e*128 + lane*4);
        for (int rr = 0; rr < 8; rr++) {
            int r = w*8 + rr;
            int qb = r >> 5, tok = r & 31, b = s_b[qb];
            if (b < 0) continue;
            float4 h4 = *(const float4*)(scr + r*384 + 128 + lane*4);
            float4 f4 = *(const float4*)(scr + r*384 + 256 + lane*4);
            float vx = h4.x+f4.x+b2v.x, vy = h4.y+f4.y+b2v.y;
            float vz = h4.z+f4.z+b2v.z, vw = h4.w+f4.w+b2v.w;
            float s = vx+vy+vz+vw;
            #pragma unroll
            for (int o = 16; o; o >>= 1) s += __shfl_xor_sync(0xffffffffu, s, o);
            float mu = s*(1.f/128.f);
            float dx = vx-mu, dy = vy-mu, dz = vz-mu, dw = vw-mu;
            float q = dx*dx+dy*dy+dz*dz+dw*dw;
            #pragma unroll
            for (int o = 16; o; o >>= 1) q += __shfl_xor_sync(0xffffffffu, q, o);
            float rs = rsqrtf(q*(1.f/128.f) + 1e-5f);
            float gt = s_g[qb];
            float4 res;
            res.x = (dx*rs*gv.x + bv.x)*gt;
            res.y = (dy*rs*gv.y + bv.y)*gt;
            res.z = (dz*rs*gv.z + bv.z)*gt;
            res.w = (dw*rs*gv.w + bv.w)*gt;
            *(float4*)(g_ys + ((size_t)(s_slot[qb]*NB + b))*4096 + tok*128 + lane*4) = res;
        }
    }
}

// ---------------- head1 ----------------
__global__ void __launch_bounds__(256)
head1_kernel(const float* __restrict__ hb1) {
    extern __shared__ char h1sm[];
    __half* XH  = (__half*)(h1sm + H1_XH);
    __half* XL  = (__half*)(h1sm + H1_XL);
    __half* WHL = (__half*)(h1sm + H1_WHL);
    __half* WH = WHL;
    __half* WL = WHL + 64*136;
    int tid = threadIdx.x, w = tid >> 5;
    int rowbase = blockIdx.x * 64;
    int colbase = blockIdx.y * 128;
    int m0 = (w >> 2) << 5;
    int n0 = (w & 3) << 5;
    HC c00, c01, c10, c11;
    wmma::fill_fragment(c00, 0.f); wmma::fill_fragment(c01, 0.f);
    wmma::fill_fragment(c10, 0.f); wmma::fill_fragment(c11, 0.f);

    for (int kc = 0; kc < 4096; kc += 64) {
        // async W prefetch overlapped with scalar X staging
        for (int i = tid; i < 1024; i += 256) {
            int r = i >> 4, v8 = i & 15;
            cpa16(WH + r*136 + v8*8, g_h1_h + (size_t)(kc + r)*HH + colbase + v8*8);
            cpa16(WL + r*136 + v8*8, g_h1_l + (size_t)(kc + r)*HH + colbase + v8*8);
        }
        CP_COMMIT();
        for (int i = tid; i < 4096; i += 256) {
            int r = i >> 6, cc = i & 63;
            size_t gi = (size_t)(rowbase + r)*4096 + kc + cc;
            float v = g_ys[gi] + g_ys[(size_t)NB*4096 + gi];
            __half h, l; split_h(v, h, l);
            XH[r*72 + cc] = h; XL[r*72 + cc] = l;
        }
        CP_WAIT0();
        __syncthreads();
        #pragma unroll
        for (int k = 0; k < 64; k += 16) {
            HA a0h, a1h, a0l, a1l;
            wmma::load_matrix_sync(a0h, XH + m0*72 + k, 72);
            wmma::load_matrix_sync(a1h, XH + (m0+16)*72 + k, 72);
            wmma::load_matrix_sync(a0l, XL + m0*72 + k, 72);
            wmma::load_matrix_sync(a1l, XL + (m0+16)*72 + k, 72);
            HB b0h, b1h, b0l, b1l;
            wmma::load_matrix_sync(b0h, WH + k*136 + n0, 136);
            wmma::load_matrix_sync(b1h, WH + k*136 + n0 + 16, 136);
            wmma::load_matrix_sync(b0l, WL + k*136 + n0, 136);
            wmma::load_matrix_sync(b1l, WL + k*136 + n0 + 16, 136);
            wmma::mma_sync(c00, a0h, b0h, c00); wmma::mma_sync(c01, a0h, b1h, c01);
            wmma::mma_sync(c10, a1h, b0h, c10); wmma::mma_sync(c11, a1h, b1h, c11);
            wmma::mma_sync(c00, a0l, b0h, c00); wmma::mma_sync(c01, a0l, b1h, c01);
            wmma::mma_sync(c10, a1l, b0h, c10); wmma::mma_sync(c11, a1l, b1h, c11);
            wmma::mma_sync(c00, a0h, b0l, c00); wmma::mma_sync(c01, a0h, b1l, c01);
            wmma::mma_sync(c10, a1h, b0l, c10); wmma::mma_sync(c11, a1h, b1l, c11);
        }
        __syncthreads();
    }
    float* OB = (float*)WHL;
    wmma::store_matrix_sync(OB + m0*132 + n0,           c00, 132, wmma::mem_row_major);
    wmma::store_matrix_sync(OB + m0*132 + n0 + 16,      c01, 132, wmma::mem_row_major);
    wmma::store_matrix_sync(OB + (m0+16)*132 + n0,      c10, 132, wmma::mem_row_major);
    wmma::store_matrix_sync(OB + (m0+16)*132 + n0 + 16, c11, 132, wmma::mem_row_major);
    __syncthreads();
    for (int i = tid; i < 8192; i += 256) {
        int r = i >> 7, cc = i & 127;
        g_hid[(size_t)(rowbase + r)*HH + colbase + cc] =
            fmaxf(OB[r*132 + cc] + hb1[colbase + cc], 0.f);
    }
}

// ---------------- head2 ----------------
__global__ void head2_kernel(const float* __restrict__ w2h, const float* __restrict__ b2h,
                             float* __restrict__ out) {
    int b = blockIdx.x;
    int w = threadIdx.x >> 5, lane = threadIdx.x & 31;
    const float* hp = g_hid + (size_t)b*HH;
    const float* wp = w2h + w*HH;
    float s = 0.f;
    for (int i = lane; i < HH; i += 32) s += hp[i]*wp[i];
    #pragma unroll
    for (int o = 16; o; o >>= 1) s += __shfl_xor_sync(0xffffffffu, s, o);
    if (lane == 0) out[b*NRW + w] = s + b2h[w];
}

// ---------------- launch ----------------
extern "C" void kernel_launch(void* const* d_in, const int* in_sizes, int n_in,
                              void* d_out, int out_size) {
    const float* z     = (const float*)d_in[0];
    const float* a     = (const float*)d_in[1];
    const float* w_gate= (const float*)d_in[2];
    const float* w_in  = (const float*)d_in[3];
    const float* b_in  = (const float*)d_in[4];
    const float* w_out = (const float*)d_in[5];
    const float* b_out = (const float*)d_in[6];
    const float* ln1g  = (const float*)d_in[7];
    const float* ln1b  = (const float*)d_in[8];
    const float* w1    = (const float*)d_in[9];
    const float* b1    = (const float*)d_in[10];
    const float* w2    = (const float*)d_in[11];
    const float* b2    = (const float*)d_in[12];
    const float* ln2g  = (const float*)d_in[13];
    const float* ln2b  = (const float*)d_in[14];
    const float* hw1   = (const float*)d_in[15];
    const float* hb1   = (const float*)d_in[16];
    const float* hw2   = (const float*)d_in[17];
    const float* hb2   = (const float*)d_in[18];
    float* out = (float*)d_out;

    cudaFuncSetAttribute((const void*)expert_kernel,
                         cudaFuncAttributeMaxDynamicSharedMemorySize, SMEM_BYTES);
    cudaFuncSetAttribute((const void*)head1_kernel,
                         cudaFuncAttributeMaxDynamicSharedMemorySize, H1_SMEM);

    repack_kernel<<<4096, 256>>>(w_in, w_out, w1, w2, hw1);
    gating_kernel<<<NB, 256>>>(z, a, w_gate, out + 4096);
    sched_kernel<<<1, 256>>>();
    loss_kernel<<<1, 256>>>(out + 4096, out);
    expert_kernel<<<MAXG, NT, SMEM_BYTES>>>(z, a, b_in, b_out, ln1g, ln1b,
                                            b1, b2, ln2g, ln2b);
    head1_kernel<<<dim3(16, 4), 256, H1_SMEM>>>(hb1);
    head2_kernel<<<NB, 128>>>(hw2, hb2, out);
}

// round 8
// speedup vs baseline: 2.1119x; 1.0062x over previous
#include <cuda_runtime.h>
#include <cuda_fp16.h>
#include <mma.h>
#include <math.h>

using namespace nvcuda;

// ---------------- problem constants ----------------
#define NEXP 8
#define NB   1024
#define NA   32
#define DTOK 128
#define FF   1024
#define HH   512
#define NRW  4
#define MAXG 520
#define NT   512     // expert kernel threads

// ---------------- scratch (__device__ globals; no allocs) ----------------
__device__ __half g_win_h [NEXP*DTOK*384];
__device__ __half g_win_l [NEXP*DTOK*384];
__device__ __half g_wout_h[NEXP*DTOK*DTOK];
__device__ __half g_wout_l[NEXP*DTOK*DTOK];
__device__ __half g_w1_h  [NEXP*DTOK*FF];
__device__ __half g_w1_l  [NEXP*DTOK*FF];
__device__ __half g_w2_h  [NEXP*FF*DTOK];
__device__ __half g_w2_l  [NEXP*FF*DTOK];
__device__ __half g_h1_h  [4096*HH];
__device__ __half g_h1_l  [4096*HH];

__device__ float  g_scr   [(size_t)MAXG*128*384];
__device__ float  g_ys    [2u*NB*4096];
__device__ float4 g_assign[NB];
__device__ float  g_lse   [NB];
__device__ float  g_hid   [NB*HH];

__device__ int    g_el_bs [NEXP*2048];
__device__ float  g_el_g  [NEXP*2048];
__device__ int4   g_grp   [MAXG];

// ---------------- expert smem layout (bytes) ----------------
#define OFF_AH   0          // 128x136 half
#define OFF_AL   34816
#define OFF_A2H  69632      // 128x72 half
#define OFF_A2L  88064
#define OFF_B0   106496     // BH0 (18432) + BL0 (18432)
#define OFF_B1   143360
#define OFF_CB   180224     // 128x68 fp32
#define SMEM_BYTES 215040
#define BL_HOFF  9216       // BL offset from buffer base, in halfs

// ---------------- head1 smem layout (bytes) ----------------
#define H1_XH    0
#define H1_XL    9216
#define H1_WHL   18432
#define H1_SMEM  (18432 + 34816)

typedef wmma::fragment<wmma::matrix_a, 16,16,16, __half, wmma::row_major> HA;
typedef wmma::fragment<wmma::matrix_b, 16,16,16, __half, wmma::row_major> HB;
typedef wmma::fragment<wmma::accumulator, 16,16,16, float> HC;

__device__ __forceinline__ void split_h(float v, __half& h, __half& l) {
    h = __float2half_rn(v);
    l = __float2half_rn(v - __half2float(h));
}

__device__ __forceinline__ void cpa16(void* dst, const void* src) {
    unsigned d = (unsigned)__cvta_generic_to_shared(dst);
    asm volatile("cp.async.cg.shared.global [%0], [%1], 16;\n" :: "r"(d), "l"(src));
}
#define CP_COMMIT() asm volatile("cp.async.commit_group;\n" ::: "memory")
#define CP_WAIT1()  asm volatile("cp.async.wait_group 1;\n" ::: "memory")
#define CP_WAIT0()  asm volatile("cp.async.wait_group 0;\n" ::: "memory")

// ---------------- weight repack ----------------
__global__ void repack_kernel(const float* __restrict__ w_in,
                              const float* __restrict__ w_out,
                              const float* __restrict__ w1,
                              const float* __restrict__ w2,
                              const float* __restrict__ hw1) {
    const int N_in  = NEXP*384*DTOK;
    const int N_out = NEXP*DTOK*DTOK;
    const int N_w1  = NEXP*FF*DTOK;
    const int N_w2  = NEXP*DTOK*FF;
    const int N_h1  = HH*4096;
    const int total = N_in + N_out + N_w1 + N_w2 + N_h1;
    for (int i = blockIdx.x*blockDim.x + threadIdx.x; i < total; i += gridDim.x*blockDim.x) {
        float v; int dst; __half h, l;
        if (i < N_in) {
            int e = i / (384*DTOK); int r = i % (384*DTOK);
            int c = r / DTOK, k = r % DTOK;
            v = w_in[i]; split_h(v, h, l);
            dst = e*(384*DTOK) + k*384 + c;
            g_win_h[dst] = h; g_win_l[dst] = l;
        } else if (i < N_in + N_out) {
            int j = i - N_in;
            int e = j / (DTOK*DTOK); int r = j % (DTOK*DTOK);
            int c = r / DTOK, k = r % DTOK;
            v = w_out[j]; split_h(v, h, l);
            dst = e*(DTOK*DTOK) + k*DTOK + c;
            g_wout_h[dst] = h; g_wout_l[dst] = l;
        } else if (i < N_in + N_out + N_w1) {
            int j = i - N_in - N_out;
            int e = j / (FF*DTOK); int r = j % (FF*DTOK);
            int f = r / DTOK, k = r % DTOK;
            v = w1[j]; split_h(v, h, l);
            dst = e*(FF*DTOK) + k*FF + f;
            g_w1_h[dst] = h; g_w1_l[dst] = l;
        } else if (i < N_in + N_out + N_w1 + N_w2) {
            int j = i - N_in - N_out - N_w1;
            int e = j / (DTOK*FF); int r = j % (DTOK*FF);
            int d = r / FF, k = r % FF;
            v = w2[j]; split_h(v, h, l);
            dst = e*(DTOK*FF) + k*DTOK + d;
            g_w2_h[dst] = h; g_w2_l[dst] = l;
        } else {
            int j = i - N_in - N_out - N_w1 - N_w2;
            int c = j / 4096, k = j % 4096;
            v = hw1[j]; split_h(v, h, l);
            dst = k*HH + c;
            g_h1_h[dst] = h; g_h1_l[dst] = l;
        }
    }
}

// ---------------- gating ----------------
__global__ void gating_kernel(const float* __restrict__ z, const float* __restrict__ a,
                              const float* __restrict__ wg, float* __restrict__ gates_out) {
    int b = blockIdx.x;
    int tid = threadIdx.x, w = tid >> 5, lane = tid & 31;
    __shared__ float lg[NEXP];
    float s = 0.f;
    for (int i = lane; i < 4096; i += 32) {
        int n = i >> 7, d = i & 127;
        float xv = (d < 96) ? z[(b*NA + n)*96 + d] : a[(b*NA + n)*32 + d - 96];
        s += xv * wg[i*NEXP + w];
    }
    #pragma unroll
    for (int o = 16; o; o >>= 1) s += __shfl_xor_sync(0xffffffffu, s, o);
    if (lane == 0) lg[w] = s;
    __syncthreads();
    if (tid == 0) {
        int i0 = 0; float v0 = lg[0];
        for (int e = 1; e < NEXP; e++) if (lg[e] > v0) { v0 = lg[e]; i0 = e; }
        int i1 = -1; float v1 = -1e30f;
        for (int e = 0; e < NEXP; e++) if (e != i0 && lg[e] > v1) { v1 = lg[e]; i1 = e; }
        float g0 = 1.f/(1.f + __expf(v1 - v0));
        float g1 = 1.f - g0;
        for (int e = 0; e < NEXP; e++)
            gates_out[b*NEXP + e] = (e == i0) ? g0 : ((e == i1) ? g1 : 0.f);
        g_assign[b] = make_float4((float)i0, g0, (float)i1, g1);
        float se = 0.f;
        for (int e = 0; e < NEXP; e++) se += __expf(lg[e] - v0);
        g_lse[b] = v0 + logf(se);
    }
}

// ---------------- scheduling ----------------
__global__ void sched_kernel() {
    __shared__ int cnt[NEXP];
    int tid = threadIdx.x;
    if (tid < NEXP) cnt[tid] = 0;
    __syncthreads();
    for (int idx = tid; idx < 2*NB; idx += blockDim.x) {
        int b = idx >> 1, slot = idx & 1;
        float4 as = g_assign[b];
        int e = slot ? (int)as.z : (int)as.x;
        float g = slot ? as.w : as.y;
        int pos = atomicAdd(&cnt[e], 1);
        g_el_bs[e*2048 + pos] = b | (slot << 16);
        g_el_g [e*2048 + pos] = g;
    }
    __syncthreads();
    if (tid == 0) {
        int gi = 0;
        for (int e = 0; e < NEXP; e++) {
            for (int s = 0; s < cnt[e]; s += 4) {
                int n = cnt[e] - s; if (n > 4) n = 4;
                g_grp[gi++] = make_int4(e, e*2048 + s, n, 0);
            }
        }
        while (gi < MAXG) g_grp[gi++] = make_int4(-1, 0, 0, 0);
    }
}

// ---------------- balance loss ----------------
__device__ __forceinline__ float cv2_of8(const float* v) {
    float m = 0.f;
    for (int i = 0; i < 8; i++) m += v[i];
    m *= 0.125f;
    float q = 0.f;
    for (int i = 0; i < 8; i++) { float d = v[i]-m; q += d*d; }
    return (q / 7.f) / (m*m + 1e-10f);
}

__global__ void loss_kernel(const float* __restrict__ gates, float* __restrict__ out) {
    __shared__ float imp[NEXP], ldv[NEXP], red[256];
    int tid = threadIdx.x, w = tid >> 5, lane = tid & 31;
    float s = 0.f, c = 0.f;
    for (int b = lane; b < NB; b += 32) {
        float gv = gates[b*NEXP + w];
        s += gv; if (gv > 0.f) c += 1.f;
    }
    #pragma unroll
    for (int o = 16; o; o >>= 1) {
        s += __shfl_xor_sync(0xffffffffu, s, o);
        c += __shfl_xor_sync(0xffffffffu, c, o);
    }
    if (lane == 0) { imp[w] = s; ldv[w] = c; }
    float ls = 0.f;
    for (int b = tid; b < NB; b += 256) ls += g_lse[b];
    red[tid] = ls; __syncthreads();
    for (int o = 128; o; o >>= 1) { if (tid < o) red[tid] += red[tid+o]; __syncthreads(); }
    if (tid == 0)
        out[12288] = cv2_of8(imp) + cv2_of8(ldv) + red[0]*(1.f/1024.f);
}

// ---------------- async staging ----------------
// 128 rows x 64 cols (src ld ldsrc) -> buf (BH ld72, BL at +9216 halfs)
__device__ __forceinline__ void stage64_async(__half* buf, const __half* __restrict__ sh,
                                              const __half* __restrict__ sl,
                                              int ldsrc, int c0) {
    __half* BH = buf; __half* BL = buf + BL_HOFF;
    for (int i = threadIdx.x; i < 1024; i += NT) {
        int r = i >> 3, v = i & 7;
        cpa16(BH + r*72 + v*8, sh + (size_t)r*ldsrc + c0 + v*8);
        cpa16(BL + r*72 + v*8, sl + (size_t)r*ldsrc + c0 + v*8);
    }
}
// W2 chunk 64 rows x 128 cols -> buf (ld 136)
__device__ __forceinline__ void stageW2_async(__half* buf, int e, int ch) {
    __half* BH = buf; __half* BL = buf + BL_HOFF;
    const __half* sh = g_w2_h + e*131072 + (size_t)ch*64*128;
    const __half* sl = g_w2_l + e*131072 + (size_t)ch*64*128;
    for (int i = threadIdx.x; i < 1024; i += NT) {
        int r = i >> 4, v = i & 15;
        cpa16(BH + r*136 + v*8, sh + (size_t)r*128 + v*8);
        cpa16(BL + r*136 + v*8, sl + (size_t)r*128 + v*8);
    }
}

// ---------------- GEMM helpers (16 warps) ----------------
// C[128x64] = A[128x128] @ B[128x64]  (A ld136, B ld72, C ld68, 3-pass)
__device__ __forceinline__ void gemm64(const __half* AHs, const __half* ALs,
                                       const __half* buf, float* CB) {
    const __half* BHs = buf;
    const __half* BLs = buf + BL_HOFF;
    int w = threadIdx.x >> 5;
    int m0 = (w >> 1) << 4;       // 0..112
    int n0 = (w & 1) << 5;        // 0, 32
    HC c0, c1;
    wmma::fill_fragment(c0, 0.f);
    wmma::fill_fragment(c1, 0.f);
    #pragma unroll 2
    for (int k = 0; k < 128; k += 16) {
        HA ah, al;
        wmma::load_matrix_sync(ah, AHs + m0*136 + k, 136);
        wmma::load_matrix_sync(al, ALs + m0*136 + k, 136);
        HB bh0, bh1, bl0, bl1;
        wmma::load_matrix_sync(bh0, BHs + k*72 + n0, 72);
        wmma::load_matrix_sync(bh1, BHs + k*72 + n0 + 16, 72);
        wmma::load_matrix_sync(bl0, BLs + k*72 + n0, 72);
        wmma::load_matrix_sync(bl1, BLs + k*72 + n0 + 16, 72);
        wmma::mma_sync(c0, ah, bh0, c0); wmma::mma_sync(c1, ah, bh1, c1);
        wmma::mma_sync(c0, al, bh0, c0); wmma::mma_sync(c1, al, bh1, c1);
        wmma::mma_sync(c0, ah, bl0, c0); wmma::mma_sync(c1, ah, bl1, c1);
    }
    wmma::store_matrix_sync(CB + m0*68 + n0,      c0, 68, wmma::mem_row_major);
    wmma::store_matrix_sync(CB + m0*68 + n0 + 16, c1, 68, wmma::mem_row_major);
}

// ff[4] += act[128x64] @ W2chunk[64x128]   (A2 ld72, B ld136)
__device__ __forceinline__ void ffn2_acc(const __half* A2H, const __half* A2L,
                                         const __half* buf, HC ff[4], int m0, int n0) {
    const __half* BHs = buf;
    const __half* BLs = buf + BL_HOFF;
    #pragma unroll
    for (int k = 0; k < 64; k += 16) {
        HA ah, al;
        wmma::load_matrix_sync(ah, A2H + m0*72 + k, 72);
        wmma::load_matrix_sync(al, A2L + m0*72 + k, 72);
        #pragma unroll
        for (int j = 0; j < 4; j++) {
            HB bh, bl;
            wmma::load_matrix_sync(bh, BHs + k*136 + n0 + 16*j, 136);
            wmma::load_matrix_sync(bl, BLs + k*136 + n0 + 16*j, 136);
            wmma::mma_sync(ff[j], ah, bh, ff[j]);
            wmma::mma_sync(ff[j], al, bh, ff[j]);
            wmma::mma_sync(ff[j], ah, bl, ff[j]);
        }
    }
}

// ---------------- expert kernel ----------------
__global__ void __launch_bounds__(NT, 1)
expert_kernel(const float* __restrict__ z, const float* __restrict__ a,
              const float* __restrict__ b_in, const float* __restrict__ b_out,
              const float* __restrict__ ln1g, const float* __restrict__ ln1b,
              const float* __restrict__ b1, const float* __restrict__ b2,
              const float* __restrict__ ln2g, const float* __restrict__ ln2b) {
    extern __shared__ char sm8[];
    __half* AH  = (__half*)(sm8 + OFF_AH);
    __half* AL  = (__half*)(sm8 + OFF_AL);
    __half* A2H = (__half*)(sm8 + OFF_A2H);
    __half* A2L = (__half*)(sm8 + OFF_A2L);
    __half* B0  = (__half*)(sm8 + OFF_B0);
    __half* B1  = (__half*)(sm8 + OFF_B1);
    float*  CB  = (float*)(sm8 + OFF_CB);
    float*  SC  = (float*)(sm8 + OFF_B0);   // scores alias over B0+B1

    int tid = threadIdx.x, w = tid >> 5, lane = tid & 31;
    int4 grp = g_grp[blockIdx.x];
    int e = grp.x;
    if (e < 0) return;

    __shared__ int s_b[4], s_slot[4];
    __shared__ float s_g[4];
    if (tid < 4) {
        if (tid < grp.z) {
            int v = g_el_bs[grp.y + tid];
            s_b[tid] = v & 0xffff; s_slot[tid] = v >> 16;
            s_g[tid] = g_el_g[grp.y + tid];
        } else { s_b[tid] = -1; s_slot[tid] = 0; s_g[tid] = 0.f; }
    }
    float* scr = g_scr + (size_t)blockIdx.x * 49152;
    const __half* winh = g_win_h + e*49152;
    const __half* winl = g_win_l + e*49152;

    // prefetch qkv tile 0 while loading x
    stage64_async(B0, winh, winl, 384, 0);
    CP_COMMIT();
    __syncthreads();   // s_b visible

    // ---- P1: x = concat(z,a) -> AH/AL ----
    for (int i = tid; i < 16384; i += NT) {
        int r = i >> 7, c = i & 127;
        int b = s_b[r >> 5], tok = r & 31;
        float v = 0.f;
        if (b >= 0) v = (c < 96) ? z[(b*NA + tok)*96 + c] : a[(b*NA + tok)*32 + c - 96];
        __half h, l; split_h(v, h, l);
        AH[r*136 + c] = h; AL[r*136 + c] = l;
    }
    __syncthreads();

    // ---- P2: qkv = x @ w_in.T + b_in -> scratch ----
    #pragma unroll 1
    for (int p = 0; p < 6; p++) {
        if (p < 5) { stage64_async((p & 1) ? B0 : B1, winh, winl, 384, (p+1)*64); CP_COMMIT(); }
        if (p < 5) { CP_WAIT1(); } else { CP_WAIT0(); }
        __syncthreads();
        gemm64(AH, AL, (p & 1) ? B1 : B0, CB);
        __syncthreads();
        for (int i = tid; i < 8192; i += NT) {
            int r = i >> 6, c = i & 63;
            scr[r*384 + p*64 + c] = CB[r*68 + c] + b_in[e*384 + p*64 + c];
        }
    }
    __syncthreads();

    // ---- P3: attention ----
    for (int idx = tid; idx < 16384; idx += NT) {
        int j = idx & 31, i = (idx >> 5) & 31, h = (idx >> 10) & 3, qb = idx >> 12;
        const float4* qp = (const float4*)(scr + (qb*32 + i)*384 + h*32);
        const float4* kp = (const float4*)(scr + (qb*32 + j)*384 + 128 + h*32);
        float s = 0.f;
        #pragma unroll
        for (int d = 0; d < 8; d++) {
            float4 qa = qp[d], ka = kp[d];
            s += qa.x*ka.x + qa.y*ka.y + qa.z*ka.z + qa.w*ka.w;
        }
        SC[((qb*4 + h)*32 + i)*33 + j] = s * 0.17677669529663687f;
    }
    __syncthreads();
    if (tid < 512) {
        float* row = SC + tid*33;
        float m = row[0];
        #pragma unroll
        for (int j = 1; j < 32; j++) m = fmaxf(m, row[j]);
        float ss = 0.f;
        #pragma unroll
        for (int j = 0; j < 32; j++) { float ev = __expf(row[j]-m); row[j] = ev; ss += ev; }
        float inv = 1.f/ss;
        #pragma unroll
        for (int j = 0; j < 32; j++) row[j] *= inv;
    }
    __syncthreads();
    for (int t = tid; t < 4096; t += NT) {
        int r = t >> 5, c = (t & 31) * 4;
        int qb = r >> 5, i = r & 31, h = c >> 5;
        const float* pr = SC + ((qb*4 + h)*32 + i)*33;
        float4 acc = make_float4(0.f, 0.f, 0.f, 0.f);
        #pragma unroll
        for (int j = 0; j < 32; j++) {
            float p = pr[j];
            float4 v = *(const float4*)(scr + (qb*32 + j)*384 + 256 + c);
            acc.x += p*v.x; acc.y += p*v.y; acc.z += p*v.z; acc.w += p*v.w;
        }
        __half h0, l0;
        split_h(acc.x, h0, l0); AH[r*136 + c]   = h0; AL[r*136 + c]   = l0;
        split_h(acc.y, h0, l0); AH[r*136 + c+1] = h0; AL[r*136 + c+1] = l0;
        split_h(acc.z, h0, l0); AH[r*136 + c+2] = h0; AL[r*136 + c+2] = l0;
        split_h(acc.w, h0, l0); AH[r*136 + c+3] = h0; AL[r*136 + c+3] = l0;
    }
    __syncthreads();   // SC no longer needed; B0/B1 free

    // ---- P4: o = attn @ w_out.T, with W1_0 / W2_0 prefetch ----
    const __half* wouth = g_wout_h + e*16384;
    const __half* woutl = g_wout_l + e*16384;
    stage64_async(B0, wouth, woutl, 128, 0);   CP_COMMIT();
    stage64_async(B1, wouth, woutl, 128, 64);  CP_COMMIT();
    CP_WAIT1(); __syncthreads();
    gemm64(AH, AL, B0, CB);
    __syncthreads();
    stage64_async(B0, g_w1_h + e*131072, g_w1_l + e*131072, 1024, 0); CP_COMMIT();
    for (int i = tid; i < 8192; i += NT) {
        int r = i >> 6, c = i & 63;
        scr[r*384 + c] = CB[r*68 + c];
    }
    CP_WAIT1(); __syncthreads();
    gemm64(AH, AL, B1, CB);
    __syncthreads();
    stageW2_async(B1, e, 0); CP_COMMIT();
    for (int i = tid; i < 8192; i += NT) {
        int r = i >> 6, c = i & 63;
        scr[r*384 + 64 + c] = CB[r*68 + c];
    }
    __syncthreads();

    // ---- P5: h = LN1(x + o + b_out) -> scratch 128.. + AH/AL ----
    {
        float4 gv = *(const float4*)(ln1g + e*128 + lane*4);
        float4 bv = *(const float4*)(ln1b + e*128 + lane*4);
        float4 bo = *(const float4*)(b_out + e*128 + lane*4);
        for (int rr = 0; rr < 8; rr++) {
            int r = w*8 + rr;
            int qb = r >> 5, tok = r & 31, b = s_b[qb];
            float4 o4 = *(const float4*)(scr + r*384 + lane*4);
            float4 x4 = make_float4(0.f, 0.f, 0.f, 0.f);
            if (b >= 0) {
                int c = lane*4;
                x4 = (c < 96) ? *(const float4*)(z + (b*NA + tok)*96 + c)
                              : *(const float4*)(a + (b*NA + tok)*32 + c - 96);
            }
            float vx = x4.x+o4.x+bo.x, vy = x4.y+o4.y+bo.y;
            float vz = x4.z+o4.z+bo.z, vw = x4.w+o4.w+bo.w;
            float s = vx+vy+vz+vw;
            #pragma unroll
            for (int o = 16; o; o >>= 1) s += __shfl_xor_sync(0xffffffffu, s, o);
            float mu = s*(1.f/128.f);
            float dx = vx-mu, dy = vy-mu, dz = vz-mu, dw = vw-mu;
            float q = dx*dx+dy*dy+dz*dz+dw*dw;
            #pragma unroll
            for (int o = 16; o; o >>= 1) q += __shfl_xor_sync(0xffffffffu, q, o);
            float rs = rsqrtf(q*(1.f/128.f) + 1e-5f);
            float hx = dx*rs*gv.x + bv.x, hy = dy*rs*gv.y + bv.y;
            float hz = dz*rs*gv.z + bv.z, hw2 = dw*rs*gv.w + bv.w;
            *(float4*)(scr + r*384 + 128 + lane*4) = make_float4(hx, hy, hz, hw2);
            int c = lane*4;
            __half hh, ll;
            split_h(hx, hh, ll);  AH[r*136+c]   = hh; AL[r*136+c]   = ll;
            split_h(hy, hh, ll);  AH[r*136+c+1] = hh; AL[r*136+c+1] = ll;
            split_h(hz, hh, ll);  AH[r*136+c+2] = hh; AL[r*136+c+2] = ll;
            split_h(hw2, hh, ll); AH[r*136+c+3] = hh; AL[r*136+c+3] = ll;
        }
    }
    __syncthreads();

    // ---- P6: FFN, pipelined W1(B0)/W2(B1), f accumulator in registers ----
    int m0 = (w >> 1) << 4, n0ff = (w & 1) << 6;
    HC ff[4];
    #pragma unroll
    for (int j = 0; j < 4; j++) wmma::fill_fragment(ff[j], 0.f);

    #pragma unroll 1
    for (int ch = 0; ch < 16; ch++) {
        // pending: [W1_ch, W2_ch]
        CP_WAIT1(); __syncthreads();                     // B0 = W1_ch ready
        gemm64(AH, AL, B0, CB);
        __syncthreads();
        if (ch < 15) { stage64_async(B0, g_w1_h + e*131072, g_w1_l + e*131072, 1024, (ch+1)*64); CP_COMMIT(); }
        for (int i = tid; i < 8192; i += NT) {
            int r = i >> 6, c = i & 63;
            float v = fmaxf(CB[r*68 + c] + b1[e*1024 + ch*64 + c], 0.f);
            __half h, l; split_h(v, h, l);
            A2H[r*72 + c] = h; A2L[r*72 + c] = l;
        }
        if (ch < 15) { CP_WAIT1(); } else { CP_WAIT0(); }
        __syncthreads();                                 // B1 = W2_ch ready, A2 visible
        ffn2_acc(A2H, A2L, B1, ff, m0, n0ff);
        __syncthreads();
        if (ch < 15) { stageW2_async(B1, e, ch+1); CP_COMMIT(); }
    }
    #pragma unroll
    for (int j = 0; j < 4; j++)
        wmma::store_matrix_sync(scr + (size_t)m0*384 + 256 + n0ff + 16*j,
                                ff[j], 384, wmma::mem_row_major);
    __syncthreads();

    // ---- P7: y = gate * LN2(h + f + b2) -> g_ys ----
    {
        float4 gv = *(const float4*)(ln2g + e*128 + lane*4);
        float4 bv = *(const float4*)(ln2b + e*128 + lane*4);
        float4 b2v = *(const float4*)(b2 + e*128 + lane*4);
        for (int rr = 0; rr < 8; rr++) {
            int r = w*8 + rr;
            int qb = r >> 5, tok = r & 31, b = s_b[qb];
            if (b < 0) continue;
            float4 h4 = *(const float4*)(scr + r*384 + 128 + lane*4);
            float4 f4 = *(const float4*)(scr + r*384 + 256 + lane*4);
            float vx = h4.x+f4.x+b2v.x, vy = h4.y+f4.y+b2v.y;
            float vz = h4.z+f4.z+b2v.z, vw = h4.w+f4.w+b2v.w;
            float s = vx+vy+vz+vw;
            #pragma unroll
            for (int o = 16; o; o >>= 1) s += __shfl_xor_sync(0xffffffffu, s, o);
            float mu = s*(1.f/128.f);
            float dx = vx-mu, dy = vy-mu, dz = vz-mu, dw = vw-mu;
            float q = dx*dx+dy*dy+dz*dz+dw*dw;
            #pragma unroll
            for (int o = 16; o; o >>= 1) q += __shfl_xor_sync(0xffffffffu, q, o);
            float rs = rsqrtf(q*(1.f/128.f) + 1e-5f);
            float gt = s_g[qb];
            float4 res;
            res.x = (dx*rs*gv.x + bv.x)*gt;
            res.y = (dy*rs*gv.y + bv.y)*gt;
            res.z = (dz*rs*gv.z + bv.z)*gt;
            res.w = (dw*rs*gv.w + bv.w)*gt;
            *(float4*)(g_ys + ((size_t)(s_slot[qb]*NB + b))*4096 + tok*128 + lane*4) = res;
        }
    }
}

// ---------------- head1 ----------------
__global__ void __launch_bounds__(256)
head1_kernel(const float* __restrict__ hb1) {
    extern __shared__ char h1sm[];
    __half* XH  = (__half*)(h1sm + H1_XH);
    __half* XL  = (__half*)(h1sm + H1_XL);
    __half* WHL = (__half*)(h1sm + H1_WHL);
    __half* WH = WHL;
    __half* WL = WHL + 64*136;
    int tid = threadIdx.x, w = tid >> 5;
    int rowbase = blockIdx.x * 64;
    int colbase = blockIdx.y * 128;
    int m0 = (w >> 2) << 5;
    int n0 = (w & 3) << 5;
    HC c00, c01, c10, c11;
    wmma::fill_fragment(c00, 0.f); wmma::fill_fragment(c01, 0.f);
    wmma::fill_fragment(c10, 0.f); wmma::fill_fragment(c11, 0.f);

    for (int kc = 0; kc < 4096; kc += 64) {
        // async W prefetch overlapped with scalar X staging
        for (int i = tid; i < 1024; i += 256) {
            int r = i >> 4, v8 = i & 15;
            cpa16(WH + r*136 + v8*8, g_h1_h + (size_t)(kc + r)*HH + colbase + v8*8);
            cpa16(WL + r*136 + v8*8, g_h1_l + (size_t)(kc + r)*HH + colbase + v8*8);
        }
        CP_COMMIT();
        for (int i = tid; i < 4096; i += 256) {
            int r = i >> 6, cc = i & 63;
            size_t gi = (size_t)(rowbase + r)*4096 + kc + cc;
            float v = g_ys[gi] + g_ys[(size_t)NB*4096 + gi];
            __half h, l; split_h(v, h, l);
            XH[r*72 + cc] = h; XL[r*72 + cc] = l;
        }
        CP_WAIT0();
        __syncthreads();
        #pragma unroll
        for (int k = 0; k < 64; k += 16) {
            HA a0h, a1h, a0l, a1l;
            wmma::load_matrix_sync(a0h, XH + m0*72 + k, 72);
            wmma::load_matrix_sync(a1h, XH + (m0+16)*72 + k, 72);
            wmma::load_matrix_sync(a0l, XL + m0*72 + k, 72);
            wmma::load_matrix_sync(a1l, XL + (m0+16)*72 + k, 72);
            HB b0h, b1h, b0l, b1l;
            wmma::load_matrix_sync(b0h, WH + k*136 + n0, 136);
            wmma::load_matrix_sync(b1h, WH + k*136 + n0 + 16, 136);
            wmma::load_matrix_sync(b0l, WL + k*136 + n0, 136);
            wmma::load_matrix_sync(b1l, WL + k*136 + n0 + 16, 136);
            wmma::mma_sync(c00, a0h, b0h, c00); wmma::mma_sync(c01, a0h, b1h, c01);
            wmma::mma_sync(c10, a1h, b0h, c10); wmma::mma_sync(c11, a1h, b1h, c11);
            wmma::mma_sync(c00, a0l, b0h, c00); wmma::mma_sync(c01, a0l, b1h, c01);
            wmma::mma_sync(c10, a1l, b0h, c10); wmma::mma_sync(c11, a1l, b1h, c11);
            wmma::mma_sync(c00, a0h, b0l, c00); wmma::mma_sync(c01, a0h, b1l, c01);
            wmma::mma_sync(c10, a1h, b0l, c10); wmma::mma_sync(c11, a1h, b1l, c11);
        }
        __syncthreads();
    }
    float* OB = (float*)WHL;
    wmma::store_matrix_sync(OB + m0*132 + n0,           c00, 132, wmma::mem_row_major);
    wmma::store_matrix_sync(OB + m0*132 + n0 + 16,      c01, 132, wmma::mem_row_major);
    wmma::store_matrix_sync(OB + (m0+16)*132 + n0,      c10, 132, wmma::mem_row_major);
    wmma::store_matrix_sync(OB + (m0+16)*132 + n0 + 16, c11, 132, wmma::mem_row_major);
    __syncthreads();
    for (int i = tid; i < 8192; i += 256) {
        int r = i >> 7, cc = i & 127;
        g_hid[(size_t)(rowbase + r)*HH + colbase + cc] =
            fmaxf(OB[r*132 + cc] + hb1[colbase + cc], 0.f);
    }
}

// ---------------- head2 ----------------
__global__ void head2_kernel(const float* __restrict__ w2h, const float* __restrict__ b2h,
                             float* __restrict__ out) {
    int b = blockIdx.x;
    int w = threadIdx.x >> 5, lane = threadIdx.x & 31;
    const float* hp = g_hid + (size_t)b*HH;
    const float* wp = w2h + w*HH;
    float s = 0.f;
    for (int i = lane; i < HH; i += 32) s += hp[i]*wp[i];
    #pragma unroll
    for (int o = 16; o; o >>= 1) s += __shfl_xor_sync(0xffffffffu, s, o);
    if (lane == 0) out[b*NRW + w] = s + b2h[w];
}

// ---------------- launch ----------------
extern "C" void kernel_launch(void* const* d_in, const int* in_sizes, int n_in,
                              void* d_out, int out_size) {
    const float* z     = (const float*)d_in[0];
    const float* a     = (const float*)d_in[1];
    const float* w_gate= (const float*)d_in[2];
    const float* w_in  = (const float*)d_in[3];
    const float* b_in  = (const float*)d_in[4];
    const float* w_out = (const float*)d_in[5];
    const float* b_out = (const float*)d_in[6];
    const float* ln1g  = (const float*)d_in[7];
    const float* ln1b  = (const float*)d_in[8];
    const float* w1    = (const float*)d_in[9];
    const float* b1    = (const float*)d_in[10];
    const float* w2    = (const float*)d_in[11];
    const float* b2    = (const float*)d_in[12];
    const float* ln2g  = (const float*)d_in[13];
    const float* ln2b  = (const float*)d_in[14];
    const float* hw1   = (const float*)d_in[15];
    const float* hb1   = (const float*)d_in[16];
    const float* hw2   = (const float*)d_in[17];
    const float* hb2   = (const float*)d_in[18];
    float* out = (float*)d_out;

    cudaFuncSetAttribute((const void*)expert_kernel,
                         cudaFuncAttributeMaxDynamicSharedMemorySize, SMEM_BYTES);
    cudaFuncSetAttribute((const void*)head1_kernel,
                         cudaFuncAttributeMaxDynamicSharedMemorySize, H1_SMEM);

    repack_kernel<<<4096, 256>>>(w_in, w_out, w1, w2, hw1);
    gating_kernel<<<NB, 256>>>(z, a, w_gate, out + 4096);
    sched_kernel<<<1, 256>>>();
    loss_kernel<<<1, 256>>>(out + 4096, out);
    expert_kernel<<<MAXG, NT, SMEM_BYTES>>>(z, a, b_in, b_out, ln1g, ln1b,
                                            b1, b2, ln2g, ln2b);
    head1_kernel<<<dim3(16, 4), 256, H1_SMEM>>>(hb1);
    head2_kernel<<<NB, 128>>>(hw2, hb2, out);
}

// round 12
// speedup vs baseline: 2.3136x; 1.0955x over previous
#include <cuda_runtime.h>
#include <cuda_fp16.h>
#include <mma.h>
#include <math.h>

using namespace nvcuda;

#define NEXP 8
#define NB   1024
#define NA   32
#define DTOK 128
#define FF   1024
#define HH   512
#define NRW  4
#define MAXG 1032
#define NT   256

// ---------------- scratch ----------------
__device__ __half g_win_h [NEXP*DTOK*384];
__device__ __half g_win_l [NEXP*DTOK*384];
__device__ __half g_wout_h[NEXP*DTOK*DTOK];
__device__ __half g_wout_l[NEXP*DTOK*DTOK];
__device__ __half g_w1_h  [NEXP*DTOK*FF];
__device__ __half g_w1_l  [NEXP*DTOK*FF];
__device__ __half g_w2_h  [NEXP*FF*DTOK];
__device__ __half g_w2_l  [NEXP*FF*DTOK];
__device__ __half g_h1_h  [4096*HH];
__device__ __half g_h1_l  [4096*HH];

__device__ float  g_scr   [(size_t)MAXG*64*384];
__device__ float  g_ys    [2u*NB*4096];
__device__ float4 g_assign[NB];
__device__ float  g_lse   [NB];
__device__ float  g_hid   [NB*HH];
__device__ int    g_el_bs [NEXP*2048];
__device__ float  g_el_g  [NEXP*2048];
__device__ int4   g_grp   [MAXG];

// ---------------- expert smem (bytes), total 90112 -> 2 blocks/SM ----------------
#define OFF_AH   0          // 64x136 half
#define OFF_AL   17408
#define OFF_B    34816      // BH (18432) + BL (18432); SC alias
#define OFF_A2H  71680      // 64x72 half; CB (64x68 fp32) aliases here
#define OFF_A2L  80896
#define SMEM_BYTES 90112
#define BL_HOFF  9216       // halfs

// ---------------- head1 smem ----------------
#define H1_XH    0          // 32x72 half
#define H1_XL    4608
#define H1_WHL   9216       // 2 x 64x136 half (34816); OB fp32 alias
#define H1_SMEM  (9216 + 34816)

typedef wmma::fragment<wmma::matrix_a, 16,16,16, __half, wmma::row_major> HA;
typedef wmma::fragment<wmma::matrix_b, 16,16,16, __half, wmma::row_major> HB;
typedef wmma::fragment<wmma::accumulator, 16,16,16, float> HC;

__device__ __forceinline__ void split_h(float v, __half& h, __half& l) {
    h = __float2half_rn(v);
    l = __float2half_rn(v - __half2float(h));
}
__device__ __forceinline__ void cpa16(void* dst, const void* src) {
    unsigned d = (unsigned)__cvta_generic_to_shared(dst);
    asm volatile("cp.async.cg.shared.global [%0], [%1], 16;\n" :: "r"(d), "l"(src));
}
#define CP_COMMIT() asm volatile("cp.async.commit_group;\n" ::: "memory")
#define CP_WAIT0()  asm volatile("cp.async.wait_group 0;\n" ::: "memory")

// ---------------- repack (transposed + hi/lo split) ----------------
__global__ void repack_kernel(const float* __restrict__ w_in,
                              const float* __restrict__ w_out,
                              const float* __restrict__ w1,
                              const float* __restrict__ w2,
                              const float* __restrict__ hw1) {
    const int N_in  = NEXP*384*DTOK;
    const int N_out = NEXP*DTOK*DTOK;
    const int N_w1  = NEXP*FF*DTOK;
    const int N_w2  = NEXP*DTOK*FF;
    const int N_h1  = HH*4096;
    const int total = N_in + N_out + N_w1 + N_w2 + N_h1;
    for (int i = blockIdx.x*blockDim.x + threadIdx.x; i < total; i += gridDim.x*blockDim.x) {
        float v; int dst; __half h, l;
        if (i < N_in) {
            int e = i / (384*DTOK); int r = i % (384*DTOK);
            int c = r / DTOK, k = r % DTOK;
            v = w_in[i]; split_h(v, h, l);
            dst = e*(384*DTOK) + k*384 + c;
            g_win_h[dst] = h; g_win_l[dst] = l;
        } else if (i < N_in + N_out) {
            int j = i - N_in;
            int e = j / (DTOK*DTOK); int r = j % (DTOK*DTOK);
            int c = r / DTOK, k = r % DTOK;
            v = w_out[j]; split_h(v, h, l);
            dst = e*(DTOK*DTOK) + k*DTOK + c;
            g_wout_h[dst] = h; g_wout_l[dst] = l;
        } else if (i < N_in + N_out + N_w1) {
            int j = i - N_in - N_out;
            int e = j / (FF*DTOK); int r = j % (FF*DTOK);
            int f = r / DTOK, k = r % DTOK;
            v = w1[j]; split_h(v, h, l);
            dst = e*(FF*DTOK) + k*FF + f;
            g_w1_h[dst] = h; g_w1_l[dst] = l;
        } else if (i < N_in + N_out + N_w1 + N_w2) {
            int j = i - N_in - N_out - N_w1;
            int e = j / (DTOK*FF); int r = j % (DTOK*FF);
            int d = r / FF, k = r % FF;
            v = w2[j]; split_h(v, h, l);
            dst = e*(DTOK*FF) + k*DTOK + d;
            g_w2_h[dst] = h; g_w2_l[dst] = l;
        } else {
            int j = i - N_in - N_out - N_w1 - N_w2;
            int c = j / 4096, k = j % 4096;
            v = hw1[j]; split_h(v, h, l);
            dst = k*HH + c;
            g_h1_h[dst] = h; g_h1_l[dst] = l;
        }
    }
}

// ---------------- gating ----------------
__global__ void gating_kernel(const float* __restrict__ z, const float* __restrict__ a,
                              const float* __restrict__ wg, float* __restrict__ gates_out) {
    int b = blockIdx.x;
    int tid = threadIdx.x, w = tid >> 5, lane = tid & 31;
    __shared__ float lg[NEXP];
    float s = 0.f;
    for (int i = lane; i < 4096; i += 32) {
        int n = i >> 7, d = i & 127;
        float xv = (d < 96) ? z[(b*NA + n)*96 + d] : a[(b*NA + n)*32 + d - 96];
        s += xv * wg[i*NEXP + w];
    }
    #pragma unroll
    for (int o = 16; o; o >>= 1) s += __shfl_xor_sync(0xffffffffu, s, o);
    if (lane == 0) lg[w] = s;
    __syncthreads();
    if (tid == 0) {
        int i0 = 0; float v0 = lg[0];
        for (int e = 1; e < NEXP; e++) if (lg[e] > v0) { v0 = lg[e]; i0 = e; }
        int i1 = -1; float v1 = -1e30f;
        for (int e = 0; e < NEXP; e++) if (e != i0 && lg[e] > v1) { v1 = lg[e]; i1 = e; }
        float g0 = 1.f/(1.f + __expf(v1 - v0));
        float g1 = 1.f - g0;
        for (int e = 0; e < NEXP; e++)
            gates_out[b*NEXP + e] = (e == i0) ? g0 : ((e == i1) ? g1 : 0.f);
        g_assign[b] = make_float4((float)i0, g0, (float)i1, g1);
        float se = 0.f;
        for (int e = 0; e < NEXP; e++) se += __expf(lg[e] - v0);
        g_lse[b] = v0 + logf(se);
    }
}

// ---------------- scheduling: groups of 2 ----------------
__global__ void sched_kernel() {
    __shared__ int cnt[NEXP];
    int tid = threadIdx.x;
    if (tid < NEXP) cnt[tid] = 0;
    __syncthreads();
    for (int idx = tid; idx < 2*NB; idx += blockDim.x) {
        int b = idx >> 1, slot = idx & 1;
        float4 as = g_assign[b];
        int e = slot ? (int)as.z : (int)as.x;
        float g = slot ? as.w : as.y;
        int pos = atomicAdd(&cnt[e], 1);
        g_el_bs[e*2048 + pos] = b | (slot << 16);
        g_el_g [e*2048 + pos] = g;
    }
    __syncthreads();
    if (tid == 0) {
        int gi = 0;
        for (int e = 0; e < NEXP; e++)
            for (int s = 0; s < cnt[e]; s += 2) {
                int n = cnt[e] - s; if (n > 2) n = 2;
                g_grp[gi++] = make_int4(e, e*2048 + s, n, 0);
            }
        while (gi < MAXG) g_grp[gi++] = make_int4(-1, 0, 0, 0);
    }
}

// ---------------- balance loss ----------------
__device__ __forceinline__ float cv2_of8(const float* v) {
    float m = 0.f;
    for (int i = 0; i < 8; i++) m += v[i];
    m *= 0.125f;
    float q = 0.f;
    for (int i = 0; i < 8; i++) { float d = v[i]-m; q += d*d; }
    return (q / 7.f) / (m*m + 1e-10f);
}
__global__ void loss_kernel(const float* __restrict__ gates, float* __restrict__ out) {
    __shared__ float imp[NEXP], ldv[NEXP], red[256];
    int tid = threadIdx.x, w = tid >> 5, lane = tid & 31;
    float s = 0.f, c = 0.f;
    for (int b = lane; b < NB; b += 32) {
        float gv = gates[b*NEXP + w];
        s += gv; if (gv > 0.f) c += 1.f;
    }
    #pragma unroll
    for (int o = 16; o; o >>= 1) {
        s += __shfl_xor_sync(0xffffffffu, s, o);
        c += __shfl_xor_sync(0xffffffffu, c, o);
    }
    if (lane == 0) { imp[w] = s; ldv[w] = c; }
    float ls = 0.f;
    for (int b = tid; b < NB; b += 256) ls += g_lse[b];
    red[tid] = ls; __syncthreads();
    for (int o = 128; o; o >>= 1) { if (tid < o) red[tid] += red[tid+o]; __syncthreads(); }
    if (tid == 0)
        out[12288] = cv2_of8(imp) + cv2_of8(ldv) + red[0]*(1.f/1024.f);
}

// ---------------- staging (256 threads) ----------------
__device__ __forceinline__ void stage64_async(__half* buf, const __half* __restrict__ sh,
                                              const __half* __restrict__ sl,
                                              int ldsrc, int c0) {
    __half* BH = buf; __half* BL = buf + BL_HOFF;
    for (int i = threadIdx.x; i < 1024; i += NT) {
        int r = i >> 3, v = i & 7;
        cpa16(BH + r*72 + v*8, sh + (size_t)r*ldsrc + c0 + v*8);
        cpa16(BL + r*72 + v*8, sl + (size_t)r*ldsrc + c0 + v*8);
    }
    CP_COMMIT();
}
__device__ __forceinline__ void stageW2_async(__half* buf, int e, int ch) {
    __half* BH = buf; __half* BL = buf + BL_HOFF;
    const __half* sh = g_w2_h + e*131072 + (size_t)ch*64*128;
    const __half* sl = g_w2_l + e*131072 + (size_t)ch*64*128;
    for (int i = threadIdx.x; i < 1024; i += NT) {
        int r = i >> 4, v = i & 15;
        cpa16(BH + r*136 + v*8, sh + (size_t)r*128 + v*8);
        cpa16(BL + r*136 + v*8, sl + (size_t)r*128 + v*8);
    }
    CP_COMMIT();
}

// ---------------- GEMM helpers (8 warps, M=64) ----------------
// C[64x64] = A[64x128] @ B[128x64]  (A ld136, B ld72, C ld68, 3-pass)
__device__ __forceinline__ void gemm64(const __half* AHs, const __half* ALs,
                                       const __half* buf, float* CB) {
    const __half* BHs = buf;
    const __half* BLs = buf + BL_HOFF;
    int w = threadIdx.x >> 5;
    int m0 = (w >> 1) << 4;       // 0,16,32,48
    int n0 = (w & 1) << 5;        // 0,32
    HC c0, c1;
    wmma::fill_fragment(c0, 0.f);
    wmma::fill_fragment(c1, 0.f);
    #pragma unroll 2
    for (int k = 0; k < 128; k += 16) {
        HA ah, al;
        wmma::load_matrix_sync(ah, AHs + m0*136 + k, 136);
        wmma::load_matrix_sync(al, ALs + m0*136 + k, 136);
        HB bh0, bh1, bl0, bl1;
        wmma::load_matrix_sync(bh0, BHs + k*72 + n0, 72);
        wmma::load_matrix_sync(bh1, BHs + k*72 + n0 + 16, 72);
        wmma::load_matrix_sync(bl0, BLs + k*72 + n0, 72);
        wmma::load_matrix_sync(bl1, BLs + k*72 + n0 + 16, 72);
        wmma::mma_sync(c0, ah, bh0, c0); wmma::mma_sync(c1, ah, bh1, c1);
        wmma::mma_sync(c0, al, bh0, c0); wmma::mma_sync(c1, al, bh1, c1);
        wmma::mma_sync(c0, ah, bl0, c0); wmma::mma_sync(c1, ah, bl1, c1);
    }
    wmma::store_matrix_sync(CB + m0*68 + n0,      c0, 68, wmma::mem_row_major);
    wmma::store_matrix_sync(CB + m0*68 + n0 + 16, c1, 68, wmma::mem_row_major);
}
// ff[4] += act[64x64] @ W2chunk[64x128]  (A2 ld72, B ld136)
__device__ __forceinline__ void ffn2_acc(const __half* A2H, const __half* A2L,
                                         const __half* buf, HC ff[4], int m0, int n0) {
    const __half* BHs = buf;
    const __half* BLs = buf + BL_HOFF;
    #pragma unroll
    for (int k = 0; k < 64; k += 16) {
        HA ah, al;
        wmma::load_matrix_sync(ah, A2H + m0*72 + k, 72);
        wmma::load_matrix_sync(al, A2L + m0*72 + k, 72);
        #pragma unroll
        for (int j = 0; j < 4; j++) {
            HB bh, bl;
            wmma::load_matrix_sync(bh, BHs + k*136 + n0 + 16*j, 136);
            wmma::load_matrix_sync(bl, BLs + k*136 + n0 + 16*j, 136);
            wmma::mma_sync(ff[j], ah, bh, ff[j]);
            wmma::mma_sync(ff[j], al, bh, ff[j]);
            wmma::mma_sync(ff[j], ah, bl, ff[j]);
        }
    }
}

// ---------------- expert kernel: one block = expert x 2 (b,slot) ----------------
__global__ void __launch_bounds__(NT, 2)
expert_kernel(const float* __restrict__ z, const float* __restrict__ a,
              const float* __restrict__ b_in, const float* __restrict__ b_out,
              const float* __restrict__ ln1g, const float* __restrict__ ln1b,
              const float* __restrict__ b1, const float* __restrict__ b2,
              const float* __restrict__ ln2g, const float* __restrict__ ln2b) {
    extern __shared__ char sm8[];
    __half* AH  = (__half*)(sm8 + OFF_AH);
    __half* AL  = (__half*)(sm8 + OFF_AL);
    __half* B   = (__half*)(sm8 + OFF_B);
    __half* A2H = (__half*)(sm8 + OFF_A2H);
    __half* A2L = (__half*)(sm8 + OFF_A2L);
    float*  CB  = (float*)(sm8 + OFF_A2H);   // alias (rd-then-wr via regs)
    float*  SC  = (float*)(sm8 + OFF_B);     // scores alias over B

    int tid = threadIdx.x, w = tid >> 5, lane = tid & 31;
    int4 grp = g_grp[blockIdx.x];
    int e = grp.x;
    if (e < 0) return;

    __shared__ int s_b[2], s_slot[2];
    __shared__ float s_g[2];
    if (tid < 2) {
        if (tid < grp.z) {
            int v = g_el_bs[grp.y + tid];
            s_b[tid] = v & 0xffff; s_slot[tid] = v >> 16;
            s_g[tid] = g_el_g[grp.y + tid];
        } else { s_b[tid] = -1; s_slot[tid] = 0; s_g[tid] = 0.f; }
    }
    float* scr = g_scr + (size_t)blockIdx.x * 24576;
    const __half* winh = g_win_h + e*49152;
    const __half* winl = g_win_l + e*49152;

    stage64_async(B, winh, winl, 384, 0);   // qkv tile 0
    __syncthreads();                         // s_b visible

    // ---- P1: x -> AH/AL ----
    for (int i = tid; i < 8192; i += NT) {
        int r = i >> 7, c = i & 127;
        int b = s_b[r >> 5], tok = r & 31;
        float v = 0.f;
        if (b >= 0) v = (c < 96) ? z[(b*NA + tok)*96 + c] : a[(b*NA + tok)*32 + c - 96];
        __half h, l; split_h(v, h, l);
        AH[r*136 + c] = h; AL[r*136 + c] = l;
    }
    __syncthreads();

    // ---- P2: qkv = x @ w_in.T + b_in -> scr ----
    #pragma unroll 1
    for (int p = 0; p < 6; p++) {
        CP_WAIT0(); __syncthreads();
        gemm64(AH, AL, B, CB);
        __syncthreads();
        if (p < 5) stage64_async(B, winh, winl, 384, (p+1)*64);
        for (int i = tid; i < 4096; i += NT) {
            int r = i >> 6, c = i & 63;
            scr[r*384 + p*64 + c] = CB[r*68 + c] + b_in[e*384 + p*64 + c];
        }
        __syncthreads();
    }

    // ---- P3: attention ----
    for (int idx = tid; idx < 8192; idx += NT) {
        int j = idx & 31, i = (idx >> 5) & 31, h = (idx >> 10) & 3, qb = idx >> 12;
        const float4* qp = (const float4*)(scr + (qb*32+i)*384 + h*32);
        const float4* kp = (const float4*)(scr + (qb*32+j)*384 + 128 + h*32);
        float s = 0.f;
        #pragma unroll
        for (int d = 0; d < 8; d++) {
            float4 qa = qp[d], ka = kp[d];
            s += qa.x*ka.x + qa.y*ka.y + qa.z*ka.z + qa.w*ka.w;
        }
        SC[((qb*4+h)*32 + i)*33 + j] = s * 0.17677669529663687f;
    }
    __syncthreads();
    {   // 256 rows, one per thread
        float* row = SC + tid*33;
        float m = row[0];
        #pragma unroll
        for (int j = 1; j < 32; j++) m = fmaxf(m, row[j]);
        float ss = 0.f;
        #pragma unroll
        for (int j = 0; j < 32; j++) { float ev = __expf(row[j]-m); row[j] = ev; ss += ev; }
        float inv = 1.f/ss;
        #pragma unroll
        for (int j = 0; j < 32; j++) row[j] *= inv;
    }
    __syncthreads();
    for (int t = tid; t < 2048; t += NT) {
        int r = t >> 5, c = (t & 31)*4;
        int qb = r >> 5, i = r & 31, h = c >> 5;
        const float* pr = SC + ((qb*4+h)*32 + i)*33;
        float4 acc = make_float4(0.f,0.f,0.f,0.f);
        #pragma unroll
        for (int j = 0; j < 32; j++) {
            float p = pr[j];
            float4 vv = *(const float4*)(scr + (qb*32+j)*384 + 256 + c);
            acc.x += p*vv.x; acc.y += p*vv.y; acc.z += p*vv.z; acc.w += p*vv.w;
        }
        __half h0, l0;
        split_h(acc.x, h0, l0); AH[r*136+c]   = h0; AL[r*136+c]   = l0;
        split_h(acc.y, h0, l0); AH[r*136+c+1] = h0; AL[r*136+c+1] = l0;
        split_h(acc.z, h0, l0); AH[r*136+c+2] = h0; AL[r*136+c+2] = l0;
        split_h(acc.w, h0, l0); AH[r*136+c+3] = h0; AL[r*136+c+3] = l0;
    }
    __syncthreads();   // SC done; B free

    // ---- P4: o = attn @ w_out.T -> scr cols 0..127 ----
    const __half* wouth = g_wout_h + e*16384;
    const __half* woutl = g_wout_l + e*16384;
    #pragma unroll 1
    for (int p = 0; p < 2; p++) {
        stage64_async(B, wouth, woutl, 128, p*64);
        CP_WAIT0(); __syncthreads();
        gemm64(AH, AL, B, CB);
        __syncthreads();
        for (int i = tid; i < 4096; i += NT) {
            int r = i >> 6, c = i & 63;
            scr[r*384 + p*64 + c] = CB[r*68 + c];
        }
        __syncthreads();
    }
    stage64_async(B, g_w1_h + e*131072, g_w1_l + e*131072, 1024, 0);  // W1_0

    // ---- P5: h = LN1(x + o + b_out) -> scr 128.. + AH/AL ----
    {
        float4 gv = *(const float4*)(ln1g + e*128 + lane*4);
        float4 bv = *(const float4*)(ln1b + e*128 + lane*4);
        float4 bo = *(const float4*)(b_out + e*128 + lane*4);
        for (int rr = 0; rr < 8; rr++) {
            int r = w*8 + rr, qb = r >> 5, tok = r & 31, b = s_b[qb];
            float4 o4 = *(const float4*)(scr + r*384 + lane*4);
            float4 x4 = make_float4(0.f,0.f,0.f,0.f);
            if (b >= 0) {
                int c = lane*4;
                x4 = (c < 96) ? *(const float4*)(z + (b*NA+tok)*96 + c)
                              : *(const float4*)(a + (b*NA+tok)*32 + c - 96);
            }
            float vx = x4.x+o4.x+bo.x, vy = x4.y+o4.y+bo.y;
            float vz = x4.z+o4.z+bo.z, vw = x4.w+o4.w+bo.w;
            float s = vx+vy+vz+vw;
            #pragma unroll
            for (int o = 16; o; o >>= 1) s += __shfl_xor_sync(0xffffffffu, s, o);
            float mu = s*(1.f/128.f);
            float dx = vx-mu, dy = vy-mu, dz = vz-mu, dw = vw-mu;
            float q = dx*dx+dy*dy+dz*dz+dw*dw;
            #pragma unroll
            for (int o = 16; o; o >>= 1) q += __shfl_xor_sync(0xffffffffu, q, o);
            float rs = rsqrtf(q*(1.f/128.f) + 1e-5f);
            float hx = dx*rs*gv.x + bv.x, hy = dy*rs*gv.y + bv.y;
            float hz = dz*rs*gv.z + bv.z, hw2 = dw*rs*gv.w + bv.w;
            *(float4*)(scr + r*384 + 128 + lane*4) = make_float4(hx, hy, hz, hw2);
            int c = lane*4;
            __half hh, ll;
            split_h(hx, hh, ll);  AH[r*136+c]   = hh; AL[r*136+c]   = ll;
            split_h(hy, hh, ll);  AH[r*136+c+1] = hh; AL[r*136+c+1] = ll;
            split_h(hz, hh, ll);  AH[r*136+c+2] = hh; AL[r*136+c+2] = ll;
            split_h(hw2, hh, ll); AH[r*136+c+3] = hh; AL[r*136+c+3] = ll;
        }
    }
    __syncthreads();

    // ---- P6: FFN, f accumulator in registers ----
    int m0 = (w >> 1) << 4, n0ff = (w & 1) << 6;
    HC ff[4];
    #pragma unroll
    for (int j = 0; j < 4; j++) wmma::fill_fragment(ff[j], 0.f);

    #pragma unroll 1
    for (int ch = 0; ch < 16; ch++) {
        CP_WAIT0(); __syncthreads();           // W1_ch in B
        gemm64(AH, AL, B, CB);
        __syncthreads();                        // B free, CB ready
        stageW2_async(B, e, ch);                // async W2_ch
        float tv[16];
        #pragma unroll
        for (int r = 0; r < 16; r++) {
            int i = tid + r*256;
            tv[r] = CB[(i >> 6)*68 + (i & 63)];   // honor CB stride 68
        }
        __syncthreads();                        // CB reads done (alias A2)
        #pragma unroll
        for (int r = 0; r < 16; r++) {
            int i = tid + r*256;
            float v = fmaxf(tv[r] + b1[e*1024 + ch*64 + (i & 63)], 0.f);
            __half h, l; split_h(v, h, l);
            int rr = i >> 6, cc = i & 63;
            A2H[rr*72 + cc] = h; A2L[rr*72 + cc] = l;
        }
        CP_WAIT0(); __syncthreads();            // W2 ready + A2 visible
        ffn2_acc(A2H, A2L, B, ff, m0, n0ff);
        __syncthreads();
        if (ch < 15) stage64_async(B, g_w1_h + e*131072, g_w1_l + e*131072, 1024, (ch+1)*64);
    }
    #pragma unroll
    for (int j = 0; j < 4; j++)
        wmma::store_matrix_sync(scr + (size_t)m0*384 + 256 + n0ff + 16*j,
                                ff[j], 384, wmma::mem_row_major);
    __syncthreads();

    // ---- P7: y = gate * LN2(h + f + b2) ----
    {
        float4 gv = *(const float4*)(ln2g + e*128 + lane*4);
        float4 bv = *(const float4*)(ln2b + e*128 + lane*4);
        float4 b2v = *(const float4*)(b2 + e*128 + lane*4);
        for (int rr = 0; rr < 8; rr++) {
            int r = w*8 + rr, qb = r >> 5, tok = r & 31, b = s_b[qb];
            if (b < 0) continue;
            float4 h4 = *(const float4*)(scr + r*384 + 128 + lane*4);
            float4 f4 = *(const float4*)(scr + r*384 + 256 + lane*4);
            float vx = h4.x+f4.x+b2v.x, vy = h4.y+f4.y+b2v.y;
            float vz = h4.z+f4.z+b2v.z, vw = h4.w+f4.w+b2v.w;
            float s = vx+vy+vz+vw;
            #pragma unroll
            for (int o = 16; o; o >>= 1) s += __shfl_xor_sync(0xffffffffu, s, o);
            float mu = s*(1.f/128.f);
            float dx = vx-mu, dy = vy-mu, dz = vz-mu, dw = vw-mu;
            float q = dx*dx+dy*dy+dz*dz+dw*dw;
            #pragma unroll
            for (int o = 16; o; o >>= 1) q += __shfl_xor_sync(0xffffffffu, q, o);
            float rs = rsqrtf(q*(1.f/128.f) + 1e-5f);
            float gt = s_g[qb];
            float4 res;
            res.x = (dx*rs*gv.x + bv.x)*gt; res.y = (dy*rs*gv.y + bv.y)*gt;
            res.z = (dz*rs*gv.z + bv.z)*gt; res.w = (dw*rs*gv.w + bv.w)*gt;
            *(float4*)(g_ys + ((size_t)(s_slot[qb]*NB + b))*4096 + tok*128 + lane*4) = res;
        }
    }
}

// ---------------- head1: M=32 tiles, 128 blocks ----------------
__global__ void __launch_bounds__(256)
head1_kernel(const float* __restrict__ hb1) {
    extern __shared__ char h1sm[];
    __half* XH  = (__half*)(h1sm + H1_XH);    // 32x72
    __half* XL  = (__half*)(h1sm + H1_XL);
    __half* WHL = (__half*)(h1sm + H1_WHL);   // 2 x 64x136
    __half* WH = WHL;
    __half* WL = WHL + 64*136;
    int tid = threadIdx.x, w = tid >> 5;
    int rowbase = blockIdx.x * 32;
    int colbase = blockIdx.y * 128;
    int m0 = (w >> 2) << 4;    // 0,16
    int n0 = (w & 3) << 5;     // 0..96
    HC c0, c1;
    wmma::fill_fragment(c0, 0.f);
    wmma::fill_fragment(c1, 0.f);

    for (int kc = 0; kc < 4096; kc += 64) {
        for (int i = tid; i < 1024; i += 256) {
            int r = i >> 4, v8 = i & 15;
            cpa16(WH + r*136 + v8*8, g_h1_h + (size_t)(kc + r)*HH + colbase + v8*8);
            cpa16(WL + r*136 + v8*8, g_h1_l + (size_t)(kc + r)*HH + colbase + v8*8);
        }
        CP_COMMIT();
        for (int i = tid; i < 2048; i += 256) {
            int r = i >> 6, cc = i & 63;
            size_t gi = (size_t)(rowbase + r)*4096 + kc + cc;
            float v = g_ys[gi] + g_ys[(size_t)NB*4096 + gi];
            __half h, l; split_h(v, h, l);
            XH[r*72 + cc] = h; XL[r*72 + cc] = l;
        }
        CP_WAIT0();
        __syncthreads();
        #pragma unroll
        for (int k = 0; k < 64; k += 16) {
            HA ah, al;
            wmma::load_matrix_sync(ah, XH + m0*72 + k, 72);
            wmma::load_matrix_sync(al, XL + m0*72 + k, 72);
            HB bh0, bh1, bl0, bl1;
            wmma::load_matrix_sync(bh0, WH + k*136 + n0, 136);
            wmma::load_matrix_sync(bh1, WH + k*136 + n0 + 16, 136);
            wmma::load_matrix_sync(bl0, WL + k*136 + n0, 136);
            wmma::load_matrix_sync(bl1, WL + k*136 + n0 + 16, 136);
            wmma::mma_sync(c0, ah, bh0, c0); wmma::mma_sync(c1, ah, bh1, c1);
            wmma::mma_sync(c0, al, bh0, c0); wmma::mma_sync(c1, al, bh1, c1);
            wmma::mma_sync(c0, ah, bl0, c0); wmma::mma_sync(c1, ah, bl1, c1);
        }
        __syncthreads();
    }
    float* OB = (float*)WHL;   // 32x132 fp32
    wmma::store_matrix_sync(OB + m0*132 + n0,      c0, 132, wmma::mem_row_major);
    wmma::store_matrix_sync(OB + m0*132 + n0 + 16, c1, 132, wmma::mem_row_major);
    __syncthreads();
    for (int i = tid; i < 4096; i += 256) {
        int r = i >> 7, cc = i & 127;
        g_hid[(size_t)(rowbase + r)*HH + colbase + cc] =
            fmaxf(OB[r*132 + cc] + hb1[colbase + cc], 0.f);
    }
}

// ---------------- head2 ----------------
__global__ void head2_kernel(const float* __restrict__ w2h, const float* __restrict__ b2h,
                             float* __restrict__ out) {
    int b = blockIdx.x, w = threadIdx.x >> 5, lane = threadIdx.x & 31;
    const float* hp = g_hid + (size_t)b*HH;
    const float* wp = w2h + w*HH;
    float s = 0.f;
    for (int i = lane; i < HH; i += 32) s += hp[i]*wp[i];
    #pragma unroll
    for (int o = 16; o; o >>= 1) s += __shfl_xor_sync(0xffffffffu, s, o);
    if (lane == 0) out[b*NRW + w] = s + b2h[w];
}

// ---------------- launch ----------------
extern "C" void kernel_launch(void* const* d_in, const int* in_sizes, int n_in,
                              void* d_out, int out_size) {
    const float* z     = (const float*)d_in[0];
    const float* a     = (const float*)d_in[1];
    const float* w_gate= (const float*)d_in[2];
    const float* w_in  = (const float*)d_in[3];
    const float* b_in  = (const float*)d_in[4];
    const float* w_out = (const float*)d_in[5];
    const float* b_out = (const float*)d_in[6];
    const float* ln1g  = (const float*)d_in[7];
    const float* ln1b  = (const float*)d_in[8];
    const float* w1    = (const float*)d_in[9];
    const float* b1    = (const float*)d_in[10];
    const float* w2    = (const float*)d_in[11];
    const float* b2    = (const float*)d_in[12];
    const float* ln2g  = (const float*)d_in[13];
    const float* ln2b  = (const float*)d_in[14];
    const float* hw1   = (const float*)d_in[15];
    const float* hb1   = (const float*)d_in[16];
    const float* hw2   = (const float*)d_in[17];
    const float* hb2   = (const float*)d_in[18];
    float* out = (float*)d_out;

    cudaFuncSetAttribute((const void*)expert_kernel,
                         cudaFuncAttributeMaxDynamicSharedMemorySize, SMEM_BYTES);
    cudaFuncSetAttribute((const void*)head1_kernel,
                         cudaFuncAttributeMaxDynamicSharedMemorySize, H1_SMEM);

    repack_kernel<<<4096, 256>>>(w_in, w_out, w1, w2, hw1);
    gating_kernel<<<NB, 256>>>(z, a, w_gate, out + 4096);
    sched_kernel<<<1, 256>>>();
    loss_kernel<<<1, 256>>>(out + 4096, out);
    expert_kernel<<<MAXG, NT, SMEM_BYTES>>>(z, a, b_in, b_out, ln1g, ln1b,
                                            b1, b2, ln2g, ln2b);
    head1_kernel<<<dim3(32, 4), 256, H1_SMEM>>>(hb1);
    head2_kernel<<<NB, 128>>>(hw2, hb2, out);
}

// round 13
// speedup vs baseline: 2.9039x; 1.2552x over previous
#include <cuda_runtime.h>
#include <cuda_fp16.h>
#include <mma.h>
#include <math.h>

using namespace nvcuda;

#define NEXP 8
#define NB   1024
#define NA   32
#define DTOK 128
#define FF   1024
#define HH   512
#define NRW  4
#define MAXG 1032
#define NT   256

// ---------------- scratch ----------------
// weights: hi half only (2-pass scheme corrects A quantization, not B)
__device__ __half g_win_h [NEXP*DTOK*384];
__device__ __half g_wout_h[NEXP*DTOK*DTOK];
__device__ __half g_w1_h  [NEXP*DTOK*FF];
__device__ __half g_w2_h  [NEXP*FF*DTOK];
__device__ __half g_h1_h  [4096*HH];

__device__ float  g_scr   [(size_t)MAXG*64*384];
__device__ float  g_ys    [2u*NB*4096];
__device__ float4 g_assign[NB];
__device__ float  g_lse   [NB];
__device__ float  g_hid   [NB*HH];
__device__ int    g_el_bs [NEXP*2048];
__device__ float  g_el_g  [NEXP*2048];
__device__ int4   g_grp   [MAXG];

// ---------------- expert smem (bytes), total 90112 -> 2 blocks/SM ----------------
#define OFF_AH   0          // 64x136 half (17408)
#define OFF_AL   17408
#define OFF_B0   34816      // 18432 (128x72 half or 64x136 half)
#define OFF_B1   53248      // 18432
#define OFF_A2H  71680      // 64x72 half (9216); CB (64x68 fp32, 17408) aliases A2H+A2L
#define OFF_A2L  80896
#define SMEM_BYTES 90112

// ---------------- head1 smem ----------------
#define H1_XH    0          // 32x72 half
#define H1_XL    4608
#define H1_WH    9216       // 64x136 half (17408); OB (32x132 fp32 = 16896) alias
#define H1_SMEM  (9216 + 17408)

typedef wmma::fragment<wmma::matrix_a, 16,16,16, __half, wmma::row_major> HA;
typedef wmma::fragment<wmma::matrix_b, 16,16,16, __half, wmma::row_major> HB;
typedef wmma::fragment<wmma::accumulator, 16,16,16, float> HC;

__device__ __forceinline__ void split_h(float v, __half& h, __half& l) {
    h = __float2half_rn(v);
    l = __float2half_rn(v - __half2float(h));
}
__device__ __forceinline__ void cpa16(void* dst, const void* src) {
    unsigned d = (unsigned)__cvta_generic_to_shared(dst);
    asm volatile("cp.async.cg.shared.global [%0], [%1], 16;\n" :: "r"(d), "l"(src));
}
#define CP_COMMIT() asm volatile("cp.async.commit_group;\n" ::: "memory")
#define CP_WAIT0()  asm volatile("cp.async.wait_group 0;\n" ::: "memory")
#define CP_WAIT1()  asm volatile("cp.async.wait_group 1;\n" ::: "memory")

// ---------------- repack (transposed, fp16 hi only) ----------------
__global__ void repack_kernel(const float* __restrict__ w_in,
                              const float* __restrict__ w_out,
                              const float* __restrict__ w1,
                              const float* __restrict__ w2,
                              const float* __restrict__ hw1) {
    const int N_in  = NEXP*384*DTOK;
    const int N_out = NEXP*DTOK*DTOK;
    const int N_w1  = NEXP*FF*DTOK;
    const int N_w2  = NEXP*DTOK*FF;
    const int N_h1  = HH*4096;
    const int total = N_in + N_out + N_w1 + N_w2 + N_h1;
    for (int i = blockIdx.x*blockDim.x + threadIdx.x; i < total; i += gridDim.x*blockDim.x) {
        if (i < N_in) {
            int e = i / (384*DTOK); int r = i % (384*DTOK);
            int c = r / DTOK, k = r % DTOK;
            g_win_h[e*(384*DTOK) + k*384 + c] = __float2half_rn(w_in[i]);
        } else if (i < N_in + N_out) {
            int j = i - N_in;
            int e = j / (DTOK*DTOK); int r = j % (DTOK*DTOK);
            int c = r / DTOK, k = r % DTOK;
            g_wout_h[e*(DTOK*DTOK) + k*DTOK + c] = __float2half_rn(w_out[j]);
        } else if (i < N_in + N_out + N_w1) {
            int j = i - N_in - N_out;
            int e = j / (FF*DTOK); int r = j % (FF*DTOK);
            int f = r / DTOK, k = r % DTOK;
            g_w1_h[e*(FF*DTOK) + k*FF + f] = __float2half_rn(w1[j]);
        } else if (i < N_in + N_out + N_w1 + N_w2) {
            int j = i - N_in - N_out - N_w1;
            int e = j / (DTOK*FF); int r = j % (DTOK*FF);
            int d = r / FF, k = r % FF;
            g_w2_h[e*(DTOK*FF) + k*DTOK + d] = __float2half_rn(w2[j]);
        } else {
            int j = i - N_in - N_out - N_w1 - N_w2;
            int c = j / 4096, k = j % 4096;
            g_h1_h[k*HH + c] = __float2half_rn(hw1[j]);
        }
    }
}

// ---------------- gating ----------------
__global__ void gating_kernel(const float* __restrict__ z, const float* __restrict__ a,
                              const float* __restrict__ wg, float* __restrict__ gates_out) {
    int b = blockIdx.x;
    int tid = threadIdx.x, w = tid >> 5, lane = tid & 31;
    __shared__ float lg[NEXP];
    float s = 0.f;
    for (int i = lane; i < 4096; i += 32) {
        int n = i >> 7, d = i & 127;
        float xv = (d < 96) ? z[(b*NA + n)*96 + d] : a[(b*NA + n)*32 + d - 96];
        s += xv * wg[i*NEXP + w];
    }
    #pragma unroll
    for (int o = 16; o; o >>= 1) s += __shfl_xor_sync(0xffffffffu, s, o);
    if (lane == 0) lg[w] = s;
    __syncthreads();
    if (tid == 0) {
        int i0 = 0; float v0 = lg[0];
        for (int e = 1; e < NEXP; e++) if (lg[e] > v0) { v0 = lg[e]; i0 = e; }
        int i1 = -1; float v1 = -1e30f;
        for (int e = 0; e < NEXP; e++) if (e != i0 && lg[e] > v1) { v1 = lg[e]; i1 = e; }
        float g0 = 1.f/(1.f + __expf(v1 - v0));
        float g1 = 1.f - g0;
        for (int e = 0; e < NEXP; e++)
            gates_out[b*NEXP + e] = (e == i0) ? g0 : ((e == i1) ? g1 : 0.f);
        g_assign[b] = make_float4((float)i0, g0, (float)i1, g1);
        float se = 0.f;
        for (int e = 0; e < NEXP; e++) se += __expf(lg[e] - v0);
        g_lse[b] = v0 + logf(se);
    }
}

// ---------------- scheduling: groups of 2 ----------------
__global__ void sched_kernel() {
    __shared__ int cnt[NEXP];
    int tid = threadIdx.x;
    if (tid < NEXP) cnt[tid] = 0;
    __syncthreads();
    for (int idx = tid; idx < 2*NB; idx += blockDim.x) {
        int b = idx >> 1, slot = idx & 1;
        float4 as = g_assign[b];
        int e = slot ? (int)as.z : (int)as.x;
        float g = slot ? as.w : as.y;
        int pos = atomicAdd(&cnt[e], 1);
        g_el_bs[e*2048 + pos] = b | (slot << 16);
        g_el_g [e*2048 + pos] = g;
    }
    __syncthreads();
    if (tid == 0) {
        int gi = 0;
        for (int e = 0; e < NEXP; e++)
            for (int s = 0; s < cnt[e]; s += 2) {
                int n = cnt[e] - s; if (n > 2) n = 2;
                g_grp[gi++] = make_int4(e, e*2048 + s, n, 0);
            }
        while (gi < MAXG) g_grp[gi++] = make_int4(-1, 0, 0, 0);
    }
}

// ---------------- balance loss ----------------
__device__ __forceinline__ float cv2_of8(const float* v) {
    float m = 0.f;
    for (int i = 0; i < 8; i++) m += v[i];
    m *= 0.125f;
    float q = 0.f;
    for (int i = 0; i < 8; i++) { float d = v[i]-m; q += d*d; }
    return (q / 7.f) / (m*m + 1e-10f);
}
__global__ void loss_kernel(const float* __restrict__ gates, float* __restrict__ out) {
    __shared__ float imp[NEXP], ldv[NEXP], red[256];
    int tid = threadIdx.x, w = tid >> 5, lane = tid & 31;
    float s = 0.f, c = 0.f;
    for (int b = lane; b < NB; b += 32) {
        float gv = gates[b*NEXP + w];
        s += gv; if (gv > 0.f) c += 1.f;
    }
    #pragma unroll
    for (int o = 16; o; o >>= 1) {
        s += __shfl_xor_sync(0xffffffffu, s, o);
        c += __shfl_xor_sync(0xffffffffu, c, o);
    }
    if (lane == 0) { imp[w] = s; ldv[w] = c; }
    float ls = 0.f;
    for (int b = tid; b < NB; b += 256) ls += g_lse[b];
    red[tid] = ls; __syncthreads();
    for (int o = 128; o; o >>= 1) { if (tid < o) red[tid] += red[tid+o]; __syncthreads(); }
    if (tid == 0)
        out[12288] = cv2_of8(imp) + cv2_of8(ldv) + red[0]*(1.f/1024.f);
}

// ---------------- staging (hi only) ----------------
// [128 rows x 64 cols] -> buf ld 72
__device__ __forceinline__ void stage64_async(__half* buf, const __half* __restrict__ sh,
                                              int ldsrc, int c0) {
    for (int i = threadIdx.x; i < 1024; i += NT) {
        int r = i >> 3, v = i & 7;
        cpa16(buf + r*72 + v*8, sh + (size_t)r*ldsrc + c0 + v*8);
    }
    CP_COMMIT();
}
// W2 chunk [64 rows x 128 cols] -> buf ld 136
__device__ __forceinline__ void stageW2_async(__half* buf, int e, int ch) {
    const __half* sh = g_w2_h + e*131072 + (size_t)ch*64*128;
    for (int i = threadIdx.x; i < 1024; i += NT) {
        int r = i >> 4, v = i & 15;
        cpa16(buf + r*136 + v*8, sh + (size_t)r*128 + v*8);
    }
    CP_COMMIT();
}

// ---------------- GEMM helpers (8 warps, M=64, 2-pass) ----------------
// C[64x64] = (Ah+Al)[64x128] @ Bh[128x64]
__device__ __forceinline__ void gemm64(const __half* AHs, const __half* ALs,
                                       const __half* BHs, float* CB) {
    int w = threadIdx.x >> 5;
    int m0 = (w >> 1) << 4;
    int n0 = (w & 1) << 5;
    HC c0, c1;
    wmma::fill_fragment(c0, 0.f);
    wmma::fill_fragment(c1, 0.f);
    #pragma unroll 2
    for (int k = 0; k < 128; k += 16) {
        HA ah, al;
        wmma::load_matrix_sync(ah, AHs + m0*136 + k, 136);
        wmma::load_matrix_sync(al, ALs + m0*136 + k, 136);
        HB bh0, bh1;
        wmma::load_matrix_sync(bh0, BHs + k*72 + n0, 72);
        wmma::load_matrix_sync(bh1, BHs + k*72 + n0 + 16, 72);
        wmma::mma_sync(c0, ah, bh0, c0); wmma::mma_sync(c1, ah, bh1, c1);
        wmma::mma_sync(c0, al, bh0, c0); wmma::mma_sync(c1, al, bh1, c1);
    }
    wmma::store_matrix_sync(CB + m0*68 + n0,      c0, 68, wmma::mem_row_major);
    wmma::store_matrix_sync(CB + m0*68 + n0 + 16, c1, 68, wmma::mem_row_major);
}
// ff[4] += act(h+l)[64x64] @ W2chunk_h[64x128]
__device__ __forceinline__ void ffn2_acc(const __half* A2H, const __half* A2L,
                                         const __half* BHs, HC ff[4], int m0, int n0) {
    #pragma unroll
    for (int k = 0; k < 64; k += 16) {
        HA ah, al;
        wmma::load_matrix_sync(ah, A2H + m0*72 + k, 72);
        wmma::load_matrix_sync(al, A2L + m0*72 + k, 72);
        #pragma unroll
        for (int j = 0; j < 4; j++) {
            HB bh;
            wmma::load_matrix_sync(bh, BHs + k*136 + n0 + 16*j, 136);
            wmma::mma_sync(ff[j], ah, bh, ff[j]);
            wmma::mma_sync(ff[j], al, bh, ff[j]);
        }
    }
}

// ---------------- expert kernel: one block = expert x 2 (b,slot) ----------------
__global__ void __launch_bounds__(NT, 2)
expert_kernel(const float* __restrict__ z, const float* __restrict__ a,
              const float* __restrict__ b_in, const float* __restrict__ b_out,
              const float* __restrict__ ln1g, const float* __restrict__ ln1b,
              const float* __restrict__ b1, const float* __restrict__ b2,
              const float* __restrict__ ln2g, const float* __restrict__ ln2b) {
    extern __shared__ char sm8[];
    __half* AH  = (__half*)(sm8 + OFF_AH);
    __half* AL  = (__half*)(sm8 + OFF_AL);
    __half* B0  = (__half*)(sm8 + OFF_B0);
    __half* B1  = (__half*)(sm8 + OFF_B1);
    __half* A2H = (__half*)(sm8 + OFF_A2H);
    __half* A2L = (__half*)(sm8 + OFF_A2L);
    float*  CB  = (float*)(sm8 + OFF_A2H);   // alias (rd-to-regs then wr)
    float*  SC  = (float*)(sm8 + OFF_B0);    // scores alias over B0+B1 (33792 B)

    int tid = threadIdx.x, w = tid >> 5, lane = tid & 31;
    int4 grp = g_grp[blockIdx.x];
    int e = grp.x;
    if (e < 0) return;

    __shared__ int s_b[2], s_slot[2];
    __shared__ float s_g[2];
    if (tid < 2) {
        if (tid < grp.z) {
            int v = g_el_bs[grp.y + tid];
            s_b[tid] = v & 0xffff; s_slot[tid] = v >> 16;
            s_g[tid] = g_el_g[grp.y + tid];
        } else { s_b[tid] = -1; s_slot[tid] = 0; s_g[tid] = 0.f; }
    }
    float* scr = g_scr + (size_t)blockIdx.x * 24576;
    const __half* winh = g_win_h + e*49152;

    stage64_async(B0, winh, 384, 0);   // qkv tile 0
    __syncthreads();                    // s_b visible

    // ---- P1: x -> AH/AL ----
    for (int i = tid; i < 8192; i += NT) {
        int r = i >> 7, c = i & 127;
        int b = s_b[r >> 5], tok = r & 31;
        float v = 0.f;
        if (b >= 0) v = (c < 96) ? z[(b*NA + tok)*96 + c] : a[(b*NA + tok)*32 + c - 96];
        __half h, l; split_h(v, h, l);
        AH[r*136 + c] = h; AL[r*136 + c] = l;
    }
    __syncthreads();

    // ---- P2: qkv = x @ w_in.T + b_in -> scr (double-buffered B) ----
    #pragma unroll 1
    for (int p = 0; p < 6; p++) {
        __half* bc = (p & 1) ? B1 : B0;
        if (p < 5) stage64_async((p & 1) ? B0 : B1, winh, 384, (p+1)*64);
        if (p < 5) { CP_WAIT1(); } else { CP_WAIT0(); }
        __syncthreads();
        gemm64(AH, AL, bc, CB);
        __syncthreads();
        for (int i = tid; i < 4096; i += NT) {
            int r = i >> 6, c = i & 63;
            scr[r*384 + p*64 + c] = CB[r*68 + c] + b_in[e*384 + p*64 + c];
        }
        __syncthreads();
    }

    // ---- P3: attention ----
    for (int idx = tid; idx < 8192; idx += NT) {
        int j = idx & 31, i = (idx >> 5) & 31, h = (idx >> 10) & 3, qb = idx >> 12;
        const float4* qp = (const float4*)(scr + (qb*32+i)*384 + h*32);
        const float4* kp = (const float4*)(scr + (qb*32+j)*384 + 128 + h*32);
        float s = 0.f;
        #pragma unroll
        for (int d = 0; d < 8; d++) {
            float4 qa = qp[d], ka = kp[d];
            s += qa.x*ka.x + qa.y*ka.y + qa.z*ka.z + qa.w*ka.w;
        }
        SC[((qb*4+h)*32 + i)*33 + j] = s * 0.17677669529663687f;
    }
    __syncthreads();
    {   // 256 rows, one per thread
        float* row = SC + tid*33;
        float m = row[0];
        #pragma unroll
        for (int j = 1; j < 32; j++) m = fmaxf(m, row[j]);
        float ss = 0.f;
        #pragma unroll
        for (int j = 0; j < 32; j++) { float ev = __expf(row[j]-m); row[j] = ev; ss += ev; }
        float inv = 1.f/ss;
        #pragma unroll
        for (int j = 0; j < 32; j++) row[j] *= inv;
    }
    __syncthreads();
    for (int t = tid; t < 2048; t += NT) {
        int r = t >> 5, c = (t & 31)*4;
        int qb = r >> 5, i = r & 31, h = c >> 5;
        const float* pr = SC + ((qb*4+h)*32 + i)*33;
        float4 acc = make_float4(0.f,0.f,0.f,0.f);
        #pragma unroll
        for (int j = 0; j < 32; j++) {
            float p = pr[j];
            float4 vv = *(const float4*)(scr + (qb*32+j)*384 + 256 + c);
            acc.x += p*vv.x; acc.y += p*vv.y; acc.z += p*vv.z; acc.w += p*vv.w;
        }
        __half h0, l0;
        split_h(acc.x, h0, l0); AH[r*136+c]   = h0; AL[r*136+c]   = l0;
        split_h(acc.y, h0, l0); AH[r*136+c+1] = h0; AL[r*136+c+1] = l0;
        split_h(acc.z, h0, l0); AH[r*136+c+2] = h0; AL[r*136+c+2] = l0;
        split_h(acc.w, h0, l0); AH[r*136+c+3] = h0; AL[r*136+c+3] = l0;
    }
    __syncthreads();   // SC done; B0/B1 free

    // ---- P4: o = attn @ w_out.T -> scr cols 0..127; prefetch W1_0/W2_0 ----
    const __half* wouth = g_wout_h + e*16384;
    stage64_async(B0, wouth, 128, 0);    // G1
    stage64_async(B1, wouth, 128, 64);   // G2
    CP_WAIT1(); __syncthreads();         // G1 done
    gemm64(AH, AL, B0, CB);
    __syncthreads();
    stage64_async(B0, g_w1_h + e*131072, 1024, 0);   // G3 = W1_0
    for (int i = tid; i < 4096; i += NT) {
        int r = i >> 6, c = i & 63;
        scr[r*384 + c] = CB[r*68 + c];
    }
    CP_WAIT1(); __syncthreads();         // G2 done
    gemm64(AH, AL, B1, CB);
    __syncthreads();
    stageW2_async(B1, e, 0);             // G4 = W2_0
    for (int i = tid; i < 4096; i += NT) {
        int r = i >> 6, c = i & 63;
        scr[r*384 + 64 + c] = CB[r*68 + c];
    }
    __syncthreads();

    // ---- P5: h = LN1(x + o + b_out) -> scr 128.. + AH/AL ----
    {
        float4 gv = *(const float4*)(ln1g + e*128 + lane*4);
        float4 bv = *(const float4*)(ln1b + e*128 + lane*4);
        float4 bo = *(const float4*)(b_out + e*128 + lane*4);
        for (int rr = 0; rr < 8; rr++) {
            int r = w*8 + rr, qb = r >> 5, tok = r & 31, b = s_b[qb];
            float4 o4 = *(const float4*)(scr + r*384 + lane*4);
            float4 x4 = make_float4(0.f,0.f,0.f,0.f);
            if (b >= 0) {
                int c = lane*4;
                x4 = (c < 96) ? *(const float4*)(z + (b*NA+tok)*96 + c)
                              : *(const float4*)(a + (b*NA+tok)*32 + c - 96);
            }
            float vx = x4.x+o4.x+bo.x, vy = x4.y+o4.y+bo.y;
            float vz = x4.z+o4.z+bo.z, vw = x4.w+o4.w+bo.w;
            float s = vx+vy+vz+vw;
            #pragma unroll
            for (int o = 16; o; o >>= 1) s += __shfl_xor_sync(0xffffffffu, s, o);
            float mu = s*(1.f/128.f);
            float dx = vx-mu, dy = vy-mu, dz = vz-mu, dw = vw-mu;
            float q = dx*dx+dy*dy+dz*dz+dw*dw;
            #pragma unroll
            for (int o = 16; o; o >>= 1) q += __shfl_xor_sync(0xffffffffu, q, o);
            float rs = rsqrtf(q*(1.f/128.f) + 1e-5f);
            float hx = dx*rs*gv.x + bv.x, hy = dy*rs*gv.y + bv.y;
            float hz = dz*rs*gv.z + bv.z, hw2 = dw*rs*gv.w + bv.w;
            *(float4*)(scr + r*384 + 128 + lane*4) = make_float4(hx, hy, hz, hw2);
            int c = lane*4;
            __half hh, ll;
            split_h(hx, hh, ll);  AH[r*136+c]   = hh; AL[r*136+c]   = ll;
            split_h(hy, hh, ll);  AH[r*136+c+1] = hh; AL[r*136+c+1] = ll;
            split_h(hz, hh, ll);  AH[r*136+c+2] = hh; AL[r*136+c+2] = ll;
            split_h(hw2, hh, ll); AH[r*136+c+3] = hh; AL[r*136+c+3] = ll;
        }
    }
    __syncthreads();

    // ---- P6: FFN, pending [W1_ch(B0), W2_ch(B1)], f acc in registers ----
    int m0 = (w >> 1) << 4, n0ff = (w & 1) << 6;
    HC ff[4];
    #pragma unroll
    for (int j = 0; j < 4; j++) wmma::fill_fragment(ff[j], 0.f);

    #pragma unroll 1
    for (int ch = 0; ch < 16; ch++) {
        CP_WAIT1(); __syncthreads();            // W1_ch (B0) ready
        gemm64(AH, AL, B0, CB);
        __syncthreads();                         // B0 free, CB ready
        if (ch < 15) stage64_async(B0, g_w1_h + e*131072, 1024, (ch+1)*64);
        float tv[16];
        #pragma unroll
        for (int r = 0; r < 16; r++) {
            int i = tid + r*256;
            tv[r] = CB[(i >> 6)*68 + (i & 63)];
        }
        __syncthreads();                         // CB reads done (alias A2)
        #pragma unroll
        for (int r = 0; r < 16; r++) {
            int i = tid + r*256;
            float v = fmaxf(tv[r] + b1[e*1024 + ch*64 + (i & 63)], 0.f);
            __half h, l; split_h(v, h, l);
            int rr = i >> 6, cc = i & 63;
            A2H[rr*72 + cc] = h; A2L[rr*72 + cc] = l;
        }
        if (ch < 15) { CP_WAIT1(); } else { CP_WAIT0(); }
        __syncthreads();                         // W2_ch (B1) ready + A2 visible
        ffn2_acc(A2H, A2L, B1, ff, m0, n0ff);
        __syncthreads();
        if (ch < 15) stageW2_async(B1, e, ch+1);
    }
    #pragma unroll
    for (int j = 0; j < 4; j++)
        wmma::store_matrix_sync(scr + (size_t)m0*384 + 256 + n0ff + 16*j,
                                ff[j], 384, wmma::mem_row_major);
    __syncthreads();

    // ---- P7: y = gate * LN2(h + f + b2) ----
    {
        float4 gv = *(const float4*)(ln2g + e*128 + lane*4);
        float4 bv = *(const float4*)(ln2b + e*128 + lane*4);
        float4 b2v = *(const float4*)(b2 + e*128 + lane*4);
        for (int rr = 0; rr < 8; rr++) {
            int r = w*8 + rr, qb = r >> 5, tok = r & 31, b = s_b[qb];
            if (b < 0) continue;
            float4 h4 = *(const float4*)(scr + r*384 + 128 + lane*4);
            float4 f4 = *(const float4*)(scr + r*384 + 256 + lane*4);
            float vx = h4.x+f4.x+b2v.x, vy = h4.y+f4.y+b2v.y;
            float vz = h4.z+f4.z+b2v.z, vw = h4.w+f4.w+b2v.w;
            float s = vx+vy+vz+vw;
            #pragma unroll
            for (int o = 16; o; o >>= 1) s += __shfl_xor_sync(0xffffffffu, s, o);
            float mu = s*(1.f/128.f);
            float dx = vx-mu, dy = vy-mu, dz = vz-mu, dw = vw-mu;
            float q = dx*dx+dy*dy+dz*dz+dw*dw;
            #pragma unroll
            for (int o = 16; o; o >>= 1) q += __shfl_xor_sync(0xffffffffu, q, o);
            float rs = rsqrtf(q*(1.f/128.f) + 1e-5f);
            float gt = s_g[qb];
            float4 res;
            res.x = (dx*rs*gv.x + bv.x)*gt; res.y = (dy*rs*gv.y + bv.y)*gt;
            res.z = (dz*rs*gv.z + bv.z)*gt; res.w = (dw*rs*gv.w + bv.w)*gt;
            *(float4*)(g_ys + ((size_t)(s_slot[qb]*NB + b))*4096 + tok*128 + lane*4) = res;
        }
    }
}

// ---------------- head1: M=32 tiles, 128 blocks, 2-pass ----------------
__global__ void __launch_bounds__(256)
head1_kernel(const float* __restrict__ hb1) {
    extern __shared__ char h1sm[];
    __half* XH = (__half*)(h1sm + H1_XH);    // 32x72
    __half* XL = (__half*)(h1sm + H1_XL);
    __half* WH = (__half*)(h1sm + H1_WH);    // 64x136
    int tid = threadIdx.x, w = tid >> 5;
    int rowbase = blockIdx.x * 32;
    int colbase = blockIdx.y * 128;
    int m0 = (w >> 2) << 4;    // 0,16
    int n0 = (w & 3) << 5;     // 0..96
    HC c0, c1;
    wmma::fill_fragment(c0, 0.f);
    wmma::fill_fragment(c1, 0.f);

    for (int kc = 0; kc < 4096; kc += 64) {
        for (int i = tid; i < 1024; i += 256) {
            int r = i >> 4, v8 = i & 15;
            cpa16(WH + r*136 + v8*8, g_h1_h + (size_t)(kc + r)*HH + colbase + v8*8);
        }
        CP_COMMIT();
        for (int i = tid; i < 2048; i += 256) {
            int r = i >> 6, cc = i & 63;
            size_t gi = (size_t)(rowbase + r)*4096 + kc + cc;
            float v = g_ys[gi] + g_ys[(size_t)NB*4096 + gi];
            __half h, l; split_h(v, h, l);
            XH[r*72 + cc] = h; XL[r*72 + cc] = l;
        }
        CP_WAIT0();
        __syncthreads();
        #pragma unroll
        for (int k = 0; k < 64; k += 16) {
            HA ah, al;
            wmma::load_matrix_sync(ah, XH + m0*72 + k, 72);
            wmma::load_matrix_sync(al, XL + m0*72 + k, 72);
            HB bh0, bh1;
            wmma::load_matrix_sync(bh0, WH + k*136 + n0, 136);
            wmma::load_matrix_sync(bh1, WH + k*136 + n0 + 16, 136);
            wmma::mma_sync(c0, ah, bh0, c0); wmma::mma_sync(c1, ah, bh1, c1);
            wmma::mma_sync(c0, al, bh0, c0); wmma::mma_sync(c1, al, bh1, c1);
        }
        __syncthreads();
    }
    float* OB = (float*)WH;   // 32x132 fp32 (16896 B <= 17408)
    wmma::store_matrix_sync(OB + m0*132 + n0,      c0, 132, wmma::mem_row_major);
    wmma::store_matrix_sync(OB + m0*132 + n0 + 16, c1, 132, wmma::mem_row_major);
    __syncthreads();
    for (int i = tid; i < 4096; i += 256) {
        int r = i >> 7, cc = i & 127;
        g_hid[(size_t)(rowbase + r)*HH + colbase + cc] =
            fmaxf(OB[r*132 + cc] + hb1[colbase + cc], 0.f);
    }
}

// ---------------- head2 ----------------
__global__ void head2_kernel(const float* __restrict__ w2h, const float* __restrict__ b2h,
                             float* __restrict__ out) {
    int b = blockIdx.x, w = threadIdx.x >> 5, lane = threadIdx.x & 31;
    const float* hp = g_hid + (size_t)b*HH;
    const float* wp = w2h + w*HH;
    float s = 0.f;
    for (int i = lane; i < HH; i += 32) s += hp[i]*wp[i];
    #pragma unroll
    for (int o = 16; o; o >>= 1) s += __shfl_xor_sync(0xffffffffu, s, o);
    if (lane == 0) out[b*NRW + w] = s + b2h[w];
}

// ---------------- launch ----------------
extern "C" void kernel_launch(void* const* d_in, const int* in_sizes, int n_in,
                              void* d_out, int out_size) {
    const float* z     = (const float*)d_in[0];
    const float* a     = (const float*)d_in[1];
    const float* w_gate= (const float*)d_in[2];
    const float* w_in  = (const float*)d_in[3];
    const float* b_in  = (const float*)d_in[4];
    const float* w_out = (const float*)d_in[5];
    const float* b_out = (const float*)d_in[6];
    const float* ln1g  = (const float*)d_in[7];
    const float* ln1b  = (const float*)d_in[8];
    const float* w1    = (const float*)d_in[9];
    const float* b1    = (const float*)d_in[10];
    const float* w2    = (const float*)d_in[11];
    const float* b2    = (const float*)d_in[12];
    const float* ln2g  = (const float*)d_in[13];
    const float* ln2b  = (const float*)d_in[14];
    const float* hw1   = (const float*)d_in[15];
    const float* hb1   = (const float*)d_in[16];
    const float* hw2   = (const float*)d_in[17];
    const float* hb2   = (const float*)d_in[18];
    float* out = (float*)d_out;

    cudaFuncSetAttribute((const void*)expert_kernel,
                         cudaFuncAttributeMaxDynamicSharedMemorySize, SMEM_BYTES);
    cudaFuncSetAttribute((const void*)head1_kernel,
                         cudaFuncAttributeMaxDynamicSharedMemorySize, H1_SMEM);

    repack_kernel<<<4096, 256>>>(w_in, w_out, w1, w2, hw1);
    gating_kernel<<<NB, 256>>>(z, a, w_gate, out + 4096);
    sched_kernel<<<1, 256>>>();
    loss_kernel<<<1, 256>>>(out + 4096, out);
    expert_kernel<<<MAXG, NT, SMEM_BYTES>>>(z, a, b_in, b_out, ln1g, ln1b,
                                            b1, b2, ln2g, ln2b);
    head1_kernel<<<dim3(32, 4), 256, H1_SMEM>>>(hb1);
    head2_kernel<<<NB, 128>>>(hw2, hb2, out);
}

// round 14
// speedup vs baseline: 3.0330x; 1.0444x over previous
#include <cuda_runtime.h>
#include <cuda_fp16.h>
#include <mma.h>
#include <math.h>

using namespace nvcuda;

#define NEXP 8
#define NB   1024
#define NA   32
#define DTOK 128
#define FF   1024
#define HH   512
#define NRW  4
#define MAXG 1032
#define NT   256

// ---------------- scratch (weights fp16, transposed) ----------------
__device__ __half g_win_h [NEXP*DTOK*384];
__device__ __half g_wout_h[NEXP*DTOK*DTOK];
__device__ __half g_w1_h  [NEXP*DTOK*FF];
__device__ __half g_w2_h  [NEXP*FF*DTOK];
__device__ __half g_h1_h  [4096*HH];

__device__ float  g_scr   [(size_t)MAXG*64*384];
__device__ float  g_ys    [2u*NB*4096];
__device__ float4 g_assign[NB];
__device__ float  g_lse   [NB];
__device__ float  g_hid   [NB*HH];
__device__ int    g_el_bs [NEXP*2048];
__device__ float  g_el_g  [NEXP*2048];
__device__ int4   g_grp   [MAXG];

// ---------------- expert smem (bytes), total 71680 -> 3 blocks/SM ----------------
#define OFF_AH   0          // 64x136 half (17408)
#define OFF_B0   17408      // 18432
#define OFF_B1   35840      // 18432
#define OFF_A2H  54272      // 64x72 half (9216); CB (64x68 fp32 = 17408) aliases 54272..71680
#define SMEM_BYTES 71680

// ---------------- head1 smem ----------------
#define H1_XH    0          // 32x72 half (4608)
#define H1_WH    4608       // 64x136 half (17408); OB (32x132 fp32 = 16896) alias
#define H1_SMEM  (4608 + 17408)

typedef wmma::fragment<wmma::matrix_a, 16,16,16, __half, wmma::row_major> HA;
typedef wmma::fragment<wmma::matrix_b, 16,16,16, __half, wmma::row_major> HB;
typedef wmma::fragment<wmma::accumulator, 16,16,16, float> HC;

__device__ __forceinline__ void cpa16(void* dst, const void* src) {
    unsigned d = (unsigned)__cvta_generic_to_shared(dst);
    asm volatile("cp.async.cg.shared.global [%0], [%1], 16;\n" :: "r"(d), "l"(src));
}
#define CP_COMMIT() asm volatile("cp.async.commit_group;\n" ::: "memory")
#define CP_WAIT0()  asm volatile("cp.async.wait_group 0;\n" ::: "memory")
#define CP_WAIT1()  asm volatile("cp.async.wait_group 1;\n" ::: "memory")

// ---------------- repack (transposed, fp16) ----------------
__global__ void repack_kernel(const float* __restrict__ w_in,
                              const float* __restrict__ w_out,
                              const float* __restrict__ w1,
                              const float* __restrict__ w2,
                              const float* __restrict__ hw1) {
    const int N_in  = NEXP*384*DTOK;
    const int N_out = NEXP*DTOK*DTOK;
    const int N_w1  = NEXP*FF*DTOK;
    const int N_w2  = NEXP*DTOK*FF;
    const int N_h1  = HH*4096;
    const int total = N_in + N_out + N_w1 + N_w2 + N_h1;
    for (int i = blockIdx.x*blockDim.x + threadIdx.x; i < total; i += gridDim.x*blockDim.x) {
        if (i < N_in) {
            int e = i / (384*DTOK); int r = i % (384*DTOK);
            int c = r / DTOK, k = r % DTOK;
            g_win_h[e*(384*DTOK) + k*384 + c] = __float2half_rn(w_in[i]);
        } else if (i < N_in + N_out) {
            int j = i - N_in;
            int e = j / (DTOK*DTOK); int r = j % (DTOK*DTOK);
            int c = r / DTOK, k = r % DTOK;
            g_wout_h[e*(DTOK*DTOK) + k*DTOK + c] = __float2half_rn(w_out[j]);
        } else if (i < N_in + N_out + N_w1) {
            int j = i - N_in - N_out;
            int e = j / (FF*DTOK); int r = j % (FF*DTOK);
            int f = r / DTOK, k = r % DTOK;
            g_w1_h[e*(FF*DTOK) + k*FF + f] = __float2half_rn(w1[j]);
        } else if (i < N_in + N_out + N_w1 + N_w2) {
            int j = i - N_in - N_out - N_w1;
            int e = j / (DTOK*FF); int r = j % (DTOK*FF);
            int d = r / FF, k = r % FF;
            g_w2_h[e*(DTOK*FF) + k*DTOK + d] = __float2half_rn(w2[j]);
        } else {
            int j = i - N_in - N_out - N_w1 - N_w2;
            int c = j / 4096, k = j % 4096;
            g_h1_h[k*HH + c] = __float2half_rn(hw1[j]);
        }
    }
}

// ---------------- gating ----------------
__global__ void gating_kernel(const float* __restrict__ z, const float* __restrict__ a,
                              const float* __restrict__ wg, float* __restrict__ gates_out) {
    int b = blockIdx.x;
    int tid = threadIdx.x, w = tid >> 5, lane = tid & 31;
    __shared__ float lg[NEXP];
    float s = 0.f;
    for (int i = lane; i < 4096; i += 32) {
        int n = i >> 7, d = i & 127;
        float xv = (d < 96) ? z[(b*NA + n)*96 + d] : a[(b*NA + n)*32 + d - 96];
        s += xv * wg[i*NEXP + w];
    }
    #pragma unroll
    for (int o = 16; o; o >>= 1) s += __shfl_xor_sync(0xffffffffu, s, o);
    if (lane == 0) lg[w] = s;
    __syncthreads();
    if (tid == 0) {
        int i0 = 0; float v0 = lg[0];
        for (int e = 1; e < NEXP; e++) if (lg[e] > v0) { v0 = lg[e]; i0 = e; }
        int i1 = -1; float v1 = -1e30f;
        for (int e = 0; e < NEXP; e++) if (e != i0 && lg[e] > v1) { v1 = lg[e]; i1 = e; }
        float g0 = 1.f/(1.f + __expf(v1 - v0));
        float g1 = 1.f - g0;
        for (int e = 0; e < NEXP; e++)
            gates_out[b*NEXP + e] = (e == i0) ? g0 : ((e == i1) ? g1 : 0.f);
        g_assign[b] = make_float4((float)i0, g0, (float)i1, g1);
        float se = 0.f;
        for (int e = 0; e < NEXP; e++) se += __expf(lg[e] - v0);
        g_lse[b] = v0 + logf(se);
    }
}

// ---------------- scheduling: groups of 2 ----------------
__global__ void sched_kernel() {
    __shared__ int cnt[NEXP];
    int tid = threadIdx.x;
    if (tid < NEXP) cnt[tid] = 0;
    __syncthreads();
    for (int idx = tid; idx < 2*NB; idx += blockDim.x) {
        int b = idx >> 1, slot = idx & 1;
        float4 as = g_assign[b];
        int e = slot ? (int)as.z : (int)as.x;
        float g = slot ? as.w : as.y;
        int pos = atomicAdd(&cnt[e], 1);
        g_el_bs[e*2048 + pos] = b | (slot << 16);
        g_el_g [e*2048 + pos] = g;
    }
    __syncthreads();
    if (tid == 0) {
        int gi = 0;
        for (int e = 0; e < NEXP; e++)
            for (int s = 0; s < cnt[e]; s += 2) {
                int n = cnt[e] - s; if (n > 2) n = 2;
                g_grp[gi++] = make_int4(e, e*2048 + s, n, 0);
            }
        while (gi < MAXG) g_grp[gi++] = make_int4(-1, 0, 0, 0);
    }
}

// ---------------- balance loss ----------------
__device__ __forceinline__ float cv2_of8(const float* v) {
    float m = 0.f;
    for (int i = 0; i < 8; i++) m += v[i];
    m *= 0.125f;
    float q = 0.f;
    for (int i = 0; i < 8; i++) { float d = v[i]-m; q += d*d; }
    return (q / 7.f) / (m*m + 1e-10f);
}
__global__ void loss_kernel(const float* __restrict__ gates, float* __restrict__ out) {
    __shared__ float imp[NEXP], ldv[NEXP], red[256];
    int tid = threadIdx.x, w = tid >> 5, lane = tid & 31;
    float s = 0.f, c = 0.f;
    for (int b = lane; b < NB; b += 32) {
        float gv = gates[b*NEXP + w];
        s += gv; if (gv > 0.f) c += 1.f;
    }
    #pragma unroll
    for (int o = 16; o; o >>= 1) {
        s += __shfl_xor_sync(0xffffffffu, s, o);
        c += __shfl_xor_sync(0xffffffffu, c, o);
    }
    if (lane == 0) { imp[w] = s; ldv[w] = c; }
    float ls = 0.f;
    for (int b = tid; b < NB; b += 256) ls += g_lse[b];
    red[tid] = ls; __syncthreads();
    for (int o = 128; o; o >>= 1) { if (tid < o) red[tid] += red[tid+o]; __syncthreads(); }
    if (tid == 0)
        out[12288] = cv2_of8(imp) + cv2_of8(ldv) + red[0]*(1.f/1024.f);
}

// ---------------- staging ----------------
__device__ __forceinline__ void stage64_async(__half* buf, const __half* __restrict__ sh,
                                              int ldsrc, int c0) {
    for (int i = threadIdx.x; i < 1024; i += NT) {
        int r = i >> 3, v = i & 7;
        cpa16(buf + r*72 + v*8, sh + (size_t)r*ldsrc + c0 + v*8);
    }
    CP_COMMIT();
}
__device__ __forceinline__ void stageW2_async(__half* buf, int e, int ch) {
    const __half* sh = g_w2_h + e*131072 + (size_t)ch*64*128;
    for (int i = threadIdx.x; i < 1024; i += NT) {
        int r = i >> 4, v = i & 15;
        cpa16(buf + r*136 + v*8, sh + (size_t)r*128 + v*8);
    }
    CP_COMMIT();
}

// ---------------- GEMM helpers (8 warps, M=64, 1-pass fp16) ----------------
// C[64x64] = A[64x128] @ B[128x64]
__device__ __forceinline__ void gemm64(const __half* AHs, const __half* BHs, float* CB) {
    int w = threadIdx.x >> 5;
    int m0 = (w >> 1) << 4;
    int n0 = (w & 1) << 5;
    HC c0, c1;
    wmma::fill_fragment(c0, 0.f);
    wmma::fill_fragment(c1, 0.f);
    #pragma unroll 2
    for (int k = 0; k < 128; k += 16) {
        HA ah;
        wmma::load_matrix_sync(ah, AHs + m0*136 + k, 136);
        HB bh0, bh1;
        wmma::load_matrix_sync(bh0, BHs + k*72 + n0, 72);
        wmma::load_matrix_sync(bh1, BHs + k*72 + n0 + 16, 72);
        wmma::mma_sync(c0, ah, bh0, c0);
        wmma::mma_sync(c1, ah, bh1, c1);
    }
    wmma::store_matrix_sync(CB + m0*68 + n0,      c0, 68, wmma::mem_row_major);
    wmma::store_matrix_sync(CB + m0*68 + n0 + 16, c1, 68, wmma::mem_row_major);
}
// ff[4] += act[64x64] @ W2chunk[64x128]
__device__ __forceinline__ void ffn2_acc(const __half* A2H, const __half* BHs,
                                         HC ff[4], int m0, int n0) {
    #pragma unroll
    for (int k = 0; k < 64; k += 16) {
        HA ah;
        wmma::load_matrix_sync(ah, A2H + m0*72 + k, 72);
        #pragma unroll
        for (int j = 0; j < 4; j++) {
            HB bh;
            wmma::load_matrix_sync(bh, BHs + k*136 + n0 + 16*j, 136);
            wmma::mma_sync(ff[j], ah, bh, ff[j]);
        }
    }
}

// ---------------- expert kernel: one block = expert x 2 (b,slot) ----------------
__global__ void __launch_bounds__(NT, 3)
expert_kernel(const float* __restrict__ z, const float* __restrict__ a,
              const float* __restrict__ b_in, const float* __restrict__ b_out,
              const float* __restrict__ ln1g, const float* __restrict__ ln1b,
              const float* __restrict__ b1, const float* __restrict__ b2,
              const float* __restrict__ ln2g, const float* __restrict__ ln2b) {
    extern __shared__ char sm8[];
    __half* AH  = (__half*)(sm8 + OFF_AH);
    __half* B0  = (__half*)(sm8 + OFF_B0);
    __half* B1  = (__half*)(sm8 + OFF_B1);
    __half* A2H = (__half*)(sm8 + OFF_A2H);
    float*  CB  = (float*)(sm8 + OFF_A2H);   // alias (rd-to-regs then wr)
    float*  SC  = (float*)(sm8 + OFF_B0);    // scores alias over B0+B1

    int tid = threadIdx.x, w = tid >> 5, lane = tid & 31;
    int4 grp = g_grp[blockIdx.x];
    int e = grp.x;
    if (e < 0) return;

    __shared__ int s_b[2], s_slot[2];
    __shared__ float s_g[2];
    if (tid < 2) {
        if (tid < grp.z) {
            int v = g_el_bs[grp.y + tid];
            s_b[tid] = v & 0xffff; s_slot[tid] = v >> 16;
            s_g[tid] = g_el_g[grp.y + tid];
        } else { s_b[tid] = -1; s_slot[tid] = 0; s_g[tid] = 0.f; }
    }
    float* scr = g_scr + (size_t)blockIdx.x * 24576;
    const __half* winh = g_win_h + e*49152;

    stage64_async(B0, winh, 384, 0);   // qkv tile 0
    __syncthreads();                    // s_b visible

    // ---- P1: x -> AH ----
    for (int i = tid; i < 8192; i += NT) {
        int r = i >> 7, c = i & 127;
        int b = s_b[r >> 5], tok = r & 31;
        float v = 0.f;
        if (b >= 0) v = (c < 96) ? z[(b*NA + tok)*96 + c] : a[(b*NA + tok)*32 + c - 96];
        AH[r*136 + c] = __float2half_rn(v);
    }
    __syncthreads();

    // ---- P2: qkv = x @ w_in.T + b_in -> scr (double-buffered B) ----
    #pragma unroll 1
    for (int p = 0; p < 6; p++) {
        __half* bc = (p & 1) ? B1 : B0;
        if (p < 5) stage64_async((p & 1) ? B0 : B1, winh, 384, (p+1)*64);
        if (p < 5) { CP_WAIT1(); } else { CP_WAIT0(); }
        __syncthreads();
        gemm64(AH, bc, CB);
        __syncthreads();
        for (int i = tid; i < 4096; i += NT) {
            int r = i >> 6, c = i & 63;
            scr[r*384 + p*64 + c] = CB[r*68 + c] + b_in[e*384 + p*64 + c];
        }
        __syncthreads();
    }

    // ---- P3: attention ----
    for (int idx = tid; idx < 8192; idx += NT) {
        int j = idx & 31, i = (idx >> 5) & 31, h = (idx >> 10) & 3, qb = idx >> 12;
        const float4* qp = (const float4*)(scr + (qb*32+i)*384 + h*32);
        const float4* kp = (const float4*)(scr + (qb*32+j)*384 + 128 + h*32);
        float s = 0.f;
        #pragma unroll
        for (int d = 0; d < 8; d++) {
            float4 qa = qp[d], ka = kp[d];
            s += qa.x*ka.x + qa.y*ka.y + qa.z*ka.z + qa.w*ka.w;
        }
        SC[((qb*4+h)*32 + i)*33 + j] = s * 0.17677669529663687f;
    }
    __syncthreads();
    {
        float* row = SC + tid*33;
        float m = row[0];
        #pragma unroll
        for (int j = 1; j < 32; j++) m = fmaxf(m, row[j]);
        float ss = 0.f;
        #pragma unroll
        for (int j = 0; j < 32; j++) { float ev = __expf(row[j]-m); row[j] = ev; ss += ev; }
        float inv = 1.f/ss;
        #pragma unroll
        for (int j = 0; j < 32; j++) row[j] *= inv;
    }
    __syncthreads();
    for (int t = tid; t < 2048; t += NT) {
        int r = t >> 5, c = (t & 31)*4;
        int qb = r >> 5, i = r & 31, h = c >> 5;
        const float* pr = SC + ((qb*4+h)*32 + i)*33;
        float4 acc = make_float4(0.f,0.f,0.f,0.f);
        #pragma unroll
        for (int j = 0; j < 32; j++) {
            float p = pr[j];
            float4 vv = *(const float4*)(scr + (qb*32+j)*384 + 256 + c);
            acc.x += p*vv.x; acc.y += p*vv.y; acc.z += p*vv.z; acc.w += p*vv.w;
        }
        AH[r*136+c]   = __float2half_rn(acc.x);
        AH[r*136+c+1] = __float2half_rn(acc.y);
        AH[r*136+c+2] = __float2half_rn(acc.z);
        AH[r*136+c+3] = __float2half_rn(acc.w);
    }
    __syncthreads();   // SC done; B0/B1 free

    // ---- P4: o = attn @ w_out.T -> scr cols 0..127; prefetch W1_0/W2_0 ----
    const __half* wouth = g_wout_h + e*16384;
    stage64_async(B0, wouth, 128, 0);    // G1
    stage64_async(B1, wouth, 128, 64);   // G2
    CP_WAIT1(); __syncthreads();         // G1 done
    gemm64(AH, B0, CB);
    __syncthreads();
    stage64_async(B0, g_w1_h + e*131072, 1024, 0);   // G3 = W1_0
    for (int i = tid; i < 4096; i += NT) {
        int r = i >> 6, c = i & 63;
        scr[r*384 + c] = CB[r*68 + c];
    }
    CP_WAIT1(); __syncthreads();         // G2 done
    gemm64(AH, B1, CB);
    __syncthreads();
    stageW2_async(B1, e, 0);             // G4 = W2_0
    for (int i = tid; i < 4096; i += NT) {
        int r = i >> 6, c = i & 63;
        scr[r*384 + 64 + c] = CB[r*68 + c];
    }
    __syncthreads();

    // ---- P5: h = LN1(x + o + b_out) -> scr 128.. + AH ----
    {
        float4 gv = *(const float4*)(ln1g + e*128 + lane*4);
        float4 bv = *(const float4*)(ln1b + e*128 + lane*4);
        float4 bo = *(const float4*)(b_out + e*128 + lane*4);
        for (int rr = 0; rr < 8; rr++) {
            int r = w*8 + rr, qb = r >> 5, tok = r & 31, b = s_b[qb];
            float4 o4 = *(const float4*)(scr + r*384 + lane*4);
            float4 x4 = make_float4(0.f,0.f,0.f,0.f);
            if (b >= 0) {
                int c = lane*4;
                x4 = (c < 96) ? *(const float4*)(z + (b*NA+tok)*96 + c)
                              : *(const float4*)(a + (b*NA+tok)*32 + c - 96);
            }
            float vx = x4.x+o4.x+bo.x, vy = x4.y+o4.y+bo.y;
            float vz = x4.z+o4.z+bo.z, vw = x4.w+o4.w+bo.w;
            float s = vx+vy+vz+vw;
            #pragma unroll
            for (int o = 16; o; o >>= 1) s += __shfl_xor_sync(0xffffffffu, s, o);
            float mu = s*(1.f/128.f);
            float dx = vx-mu, dy = vy-mu, dz = vz-mu, dw = vw-mu;
            float q = dx*dx+dy*dy+dz*dz+dw*dw;
            #pragma unroll
            for (int o = 16; o; o >>= 1) q += __shfl_xor_sync(0xffffffffu, q, o);
            float rs = rsqrtf(q*(1.f/128.f) + 1e-5f);
            float hx = dx*rs*gv.x + bv.x, hy = dy*rs*gv.y + bv.y;
            float hz = dz*rs*gv.z + bv.z, hw2 = dw*rs*gv.w + bv.w;
            *(float4*)(scr + r*384 + 128 + lane*4) = make_float4(hx, hy, hz, hw2);
            int c = lane*4;
            AH[r*136+c]   = __float2half_rn(hx);
            AH[r*136+c+1] = __float2half_rn(hy);
            AH[r*136+c+2] = __float2half_rn(hz);
            AH[r*136+c+3] = __float2half_rn(hw2);
        }
    }
    __syncthreads();

    // ---- P6: FFN, pending [W1_ch(B0), W2_ch(B1)], f acc in registers ----
    int m0 = (w >> 1) << 4, n0ff = (w & 1) << 6;
    HC ff[4];
    #pragma unroll
    for (int j = 0; j < 4; j++) wmma::fill_fragment(ff[j], 0.f);

    #pragma unroll 1
    for (int ch = 0; ch < 16; ch++) {
        CP_WAIT1(); __syncthreads();            // W1_ch (B0) ready
        gemm64(AH, B0, CB);
        __syncthreads();                         // B0 free, CB ready
        if (ch < 15) stage64_async(B0, g_w1_h + e*131072, 1024, (ch+1)*64);
        float tv[16];
        #pragma unroll
        for (int r = 0; r < 16; r++) {
            int i = tid + r*256;
            tv[r] = CB[(i >> 6)*68 + (i & 63)];
        }
        __syncthreads();                         // CB reads done (alias A2H)
        #pragma unroll
        for (int r = 0; r < 16; r++) {
            int i = tid + r*256;
            float v = fmaxf(tv[r] + b1[e*1024 + ch*64 + (i & 63)], 0.f);
            A2H[(i >> 6)*72 + (i & 63)] = __float2half_rn(v);
        }
        if (ch < 15) { CP_WAIT1(); } else { CP_WAIT0(); }
        __syncthreads();                         // W2_ch (B1) ready + A2 visible
        ffn2_acc(A2H, B1, ff, m0, n0ff);
        __syncthreads();
        if (ch < 15) stageW2_async(B1, e, ch+1);
    }
    #pragma unroll
    for (int j = 0; j < 4; j++)
        wmma::store_matrix_sync(scr + (size_t)m0*384 + 256 + n0ff + 16*j,
                                ff[j], 384, wmma::mem_row_major);
    __syncthreads();

    // ---- P7: y = gate * LN2(h + f + b2) ----
    {
        float4 gv = *(const float4*)(ln2g + e*128 + lane*4);
        float4 bv = *(const float4*)(ln2b + e*128 + lane*4);
        float4 b2v = *(const float4*)(b2 + e*128 + lane*4);
        for (int rr = 0; rr < 8; rr++) {
            int r = w*8 + rr, qb = r >> 5, tok = r & 31, b = s_b[qb];
            if (b < 0) continue;
            float4 h4 = *(const float4*)(scr + r*384 + 128 + lane*4);
            float4 f4 = *(const float4*)(scr + r*384 + 256 + lane*4);
            float vx = h4.x+f4.x+b2v.x, vy = h4.y+f4.y+b2v.y;
            float vz = h4.z+f4.z+b2v.z, vw = h4.w+f4.w+b2v.w;
            float s = vx+vy+vz+vw;
            #pragma unroll
            for (int o = 16; o; o >>= 1) s += __shfl_xor_sync(0xffffffffu, s, o);
            float mu = s*(1.f/128.f);
            float dx = vx-mu, dy = vy-mu, dz = vz-mu, dw = vw-mu;
            float q = dx*dx+dy*dy+dz*dz+dw*dw;
            #pragma unroll
            for (int o = 16; o; o >>= 1) q += __shfl_xor_sync(0xffffffffu, q, o);
            float rs = rsqrtf(q*(1.f/128.f) + 1e-5f);
            float gt = s_g[qb];
            float4 res;
            res.x = (dx*rs*gv.x + bv.x)*gt; res.y = (dy*rs*gv.y + bv.y)*gt;
            res.z = (dz*rs*gv.z + bv.z)*gt; res.w = (dw*rs*gv.w + bv.w)*gt;
            *(float4*)(g_ys + ((size_t)(s_slot[qb]*NB + b))*4096 + tok*128 + lane*4) = res;
        }
    }
}

// ---------------- head1: M=32 tiles, 128 blocks, 1-pass ----------------
__global__ void __launch_bounds__(256)
head1_kernel(const float* __restrict__ hb1) {
    extern __shared__ char h1sm[];
    __half* XH = (__half*)(h1sm + H1_XH);    // 32x72
    __half* WH = (__half*)(h1sm + H1_WH);    // 64x136
    int tid = threadIdx.x, w = tid >> 5;
    int rowbase = blockIdx.x * 32;
    int colbase = blockIdx.y * 128;
    int m0 = (w >> 2) << 4;    // 0,16
    int n0 = (w & 3) << 5;     // 0..96
    HC c0, c1;
    wmma::fill_fragment(c0, 0.f);
    wmma::fill_fragment(c1, 0.f);

    for (int kc = 0; kc < 4096; kc += 64) {
        for (int i = tid; i < 1024; i += 256) {
            int r = i >> 4, v8 = i & 15;
            cpa16(WH + r*136 + v8*8, g_h1_h + (size_t)(kc + r)*HH + colbase + v8*8);
        }
        CP_COMMIT();
        for (int i = tid; i < 2048; i += 256) {
            int r = i >> 6, cc = i & 63;
            size_t gi = (size_t)(rowbase + r)*4096 + kc + cc;
            float v = g_ys[gi] + g_ys[(size_t)NB*4096 + gi];
            XH[r*72 + cc] = __float2half_rn(v);
        }
        CP_WAIT0();
        __syncthreads();
        #pragma unroll
        for (int k = 0; k < 64; k += 16) {
            HA ah;
            wmma::load_matrix_sync(ah, XH + m0*72 + k, 72);
            HB bh0, bh1;
            wmma::load_matrix_sync(bh0, WH + k*136 + n0, 136);
            wmma::load_matrix_sync(bh1, WH + k*136 + n0 + 16, 136);
            wmma::mma_sync(c0, ah, bh0, c0);
            wmma::mma_sync(c1, ah, bh1, c1);
        }
        __syncthreads();
    }
    float* OB = (float*)WH;   // 32x132 fp32
    wmma::store_matrix_sync(OB + m0*132 + n0,      c0, 132, wmma::mem_row_major);
    wmma::store_matrix_sync(OB + m0*132 + n0 + 16, c1, 132, wmma::mem_row_major);
    __syncthreads();
    for (int i = tid; i < 4096; i += 256) {
        int r = i >> 7, cc = i & 127;
        g_hid[(size_t)(rowbase + r)*HH + colbase + cc] =
            fmaxf(OB[r*132 + cc] + hb1[colbase + cc], 0.f);
    }
}

// ---------------- head2 ----------------
__global__ void head2_kernel(const float* __restrict__ w2h, const float* __restrict__ b2h,
                             float* __restrict__ out) {
    int b = blockIdx.x, w = threadIdx.x >> 5, lane = threadIdx.x & 31;
    const float* hp = g_hid + (size_t)b*HH;
    const float* wp = w2h + w*HH;
    float s = 0.f;
    for (int i = lane; i < HH; i += 32) s += hp[i]*wp[i];
    #pragma unroll
    for (int o = 16; o; o >>= 1) s += __shfl_xor_sync(0xffffffffu, s, o);
    if (lane == 0) out[b*NRW + w] = s + b2h[w];
}

// ---------------- launch ----------------
extern "C" void kernel_launch(void* const* d_in, const int* in_sizes, int n_in,
                              void* d_out, int out_size) {
    const float* z     = (const float*)d_in[0];
    const float* a     = (const float*)d_in[1];
    const float* w_gate= (const float*)d_in[2];
    const float* w_in  = (const float*)d_in[3];
    const float* b_in  = (const float*)d_in[4];
    const float* w_out = (const float*)d_in[5];
    const float* b_out = (const float*)d_in[6];
    const float* ln1g  = (const float*)d_in[7];
    const float* ln1b  = (const float*)d_in[8];
    const float* w1    = (const float*)d_in[9];
    const float* b1    = (const float*)d_in[10];
    const float* w2    = (const float*)d_in[11];
    const float* b2    = (const float*)d_in[12];
    const float* ln2g  = (const float*)d_in[13];
    const float* ln2b  = (const float*)d_in[14];
    const float* hw1   = (const float*)d_in[15];
    const float* hb1   = (const float*)d_in[16];
    const float* hw2   = (const float*)d_in[17];
    const float* hb2   = (const float*)d_in[18];
    float* out = (float*)d_out;

    cudaFuncSetAttribute((const void*)expert_kernel,
                         cudaFuncAttributeMaxDynamicSharedMemorySize, SMEM_BYTES);
    cudaFuncSetAttribute((const void*)head1_kernel,
                         cudaFuncAttributeMaxDynamicSharedMemorySize, H1_SMEM);

    repack_kernel<<<4096, 256>>>(w_in, w_out, w1, w2, hw1);
    gating_kernel<<<NB, 256>>>(z, a, w_gate, out + 4096);
    sched_kernel<<<1, 256>>>();
    loss_kernel<<<1, 256>>>(out + 4096, out);
    expert_kernel<<<MAXG, NT, SMEM_BYTES>>>(z, a, b_in, b_out, ln1g, ln1b,
                                            b1, b2, ln2g, ln2b);
    head1_kernel<<<dim3(32, 4), 256, H1_SMEM>>>(hb1);
    head2_kernel<<<NB, 128>>>(hw2, hb2, out);
}